// round 12
// baseline (speedup 1.0000x reference)
#include <cuda_runtime.h>
#include <cuda_bf16.h>
#include <math.h>
#include <stdint.h>

// ---------------- problem constants ----------------
#define Bdim 32
#define Sdim 512
#define Hdim 768
#define Ndim 4096
#define Edim 131072
#define Pdim 65536
#define ETOT (Edim + Ndim)
#define H1 4
#define C1 128
#define F1 (H1*C1)               // 512
#define C2 64
#define NREL 6
#define RHID 256
#define NERH 256
#define NERL 9
#define SLOPE 0.2f
#define LNEPS 1e-5f
#define NER_OUT_ELEMS (Bdim*Sdim*NERL)
#define NERROWS (Bdim*Sdim)      // 16384

// ---------------- device scratch ----------------
__device__ float g_h1[Ndim*F1];
__device__ float g_h2p[Ndim*128];
__device__ float g_es1[Ndim*H1], g_ed1[Ndim*H1];
__device__ float g_es2[Ndim],    g_ed2[Ndim];
__device__ int   g_deg[Ndim], g_cursor[Ndim], g_rowstart[Ndim+1];
__device__ int   g_csr[ETOT];
__device__ int   g_pdeg[Ndim], g_pcur[Ndim], g_prow[Ndim+1];
__device__ int   g_psorted[Pdim];
__device__ int   g_psortj[Pdim];
__device__ float g_tb[12*Ndim*RHID];
__device__ __nv_bfloat16 g_sqh[NERROWS*Hdim], g_sql[NERROWS*Hdim];
__device__ __nv_bfloat16 g_x0h[Ndim*Hdim],    g_x0l[Ndim*Hdim];
__device__ __nv_bfloat16 g_o1h[Ndim*F1],      g_o1l[Ndim*F1];
__device__ __nv_bfloat16 g_x2h[Ndim*C2],      g_x2l[Ndim*C2];
__device__ __nv_bfloat16 g_w1h[Hdim*F1],      g_w1l[Hdim*F1];
__device__ __nv_bfloat16 g_wnh[Hdim*NERH],    g_wnl[Hdim*NERH];
__device__ __nv_bfloat16 g_w2h[F1*128],       g_w2l[F1*128];
__device__ __nv_bfloat16 g_wrh[12*C2*RHID],   g_wrl[12*C2*RHID];

// ---------------- helpers ----------------
__device__ __forceinline__ float warpSum(float v){
    #pragma unroll
    for(int o=16;o;o>>=1) v += __shfl_xor_sync(0xffffffffu, v, o);
    return v;
}
__device__ __forceinline__ float quadSum(float v){
    v += __shfl_xor_sync(0xffffffffu, v, 1);
    v += __shfl_xor_sync(0xffffffffu, v, 2);
    return v;
}
__device__ __forceinline__ uint32_t smem_u32(const void* p){
    uint32_t a;
    asm("{ .reg .u64 t; cvta.to.shared.u64 t, %1; cvt.u32.u64 %0, t; }" : "=r"(a) : "l"(p));
    return a;
}
__device__ __forceinline__ unsigned pack_bf2(__nv_bfloat16 a, __nv_bfloat16 b){
    __nv_bfloat162 t; t.x = a; t.y = b;
    return *reinterpret_cast<unsigned*>(&t);
}
__device__ __forceinline__ void cp16(uint32_t dst, const void* src){
    asm volatile("cp.async.ca.shared.global [%0], [%1], 16;" :: "r"(dst), "l"(src) : "memory");
}
__device__ __forceinline__ void ldsm4(uint32_t* r, uint32_t addr){
    asm volatile("ldmatrix.sync.aligned.m8n8.x4.shared.b16 {%0,%1,%2,%3}, [%4];"
        : "=r"(r[0]), "=r"(r[1]), "=r"(r[2]), "=r"(r[3]) : "r"(addr));
}
__device__ __forceinline__ void ldsm4t(uint32_t* r, uint32_t addr){
    asm volatile("ldmatrix.sync.aligned.m8n8.x4.trans.shared.b16 {%0,%1,%2,%3}, [%4];"
        : "=r"(r[0]), "=r"(r[1]), "=r"(r[2]), "=r"(r[3]) : "r"(addr));
}
__device__ __forceinline__ void mma16816(float* d, const uint32_t* a, uint32_t b0, uint32_t b1){
    asm volatile(
        "mma.sync.aligned.m16n8k16.row.col.f32.bf16.bf16.f32 "
        "{%0,%1,%2,%3}, {%4,%5,%6,%7}, {%8,%9}, {%0,%1,%2,%3};"
        : "+f"(d[0]), "+f"(d[1]), "+f"(d[2]), "+f"(d[3])
        : "r"(a[0]), "r"(a[1]), "r"(a[2]), "r"(a[3]), "r"(b0), "r"(b1));
}

// ---------------- split fp32 -> bf16 hi/lo planes ----------------
__global__ void k_split(const float4* __restrict__ in, uint2* __restrict__ hi,
                        uint2* __restrict__ lo, int n4){
    int i = blockIdx.x*blockDim.x + threadIdx.x;
    if(i >= n4) return;
    float4 v = in[i];
    __nv_bfloat16 h0=__float2bfloat16(v.x), h1=__float2bfloat16(v.y);
    __nv_bfloat16 h2=__float2bfloat16(v.z), h3=__float2bfloat16(v.w);
    __nv_bfloat16 l0=__float2bfloat16(v.x-__bfloat162float(h0));
    __nv_bfloat16 l1=__float2bfloat16(v.y-__bfloat162float(h1));
    __nv_bfloat16 l2=__float2bfloat16(v.z-__bfloat162float(h2));
    __nv_bfloat16 l3=__float2bfloat16(v.w-__bfloat162float(h3));
    hi[i] = make_uint2(pack_bf2(h0,h1), pack_bf2(h2,h3));
    lo[i] = make_uint2(pack_bf2(l0,l1), pack_bf2(l2,l3));
}

__global__ void k_split_padW2(const float* __restrict__ W2,
                              __nv_bfloat16* __restrict__ hi, __nv_bfloat16* __restrict__ lo){
    int idx = blockIdx.x*256 + threadIdx.x;
    int k = idx >> 7, c = idx & 127;
    float v = (c < C2) ? W2[k*C2 + c] : 0.f;
    __nv_bfloat16 h = __float2bfloat16(v);
    __nv_bfloat16 l = __float2bfloat16(v - __bfloat162float(h));
    hi[idx] = h; lo[idx] = l;
}

// ---------------- split-bf16 HMMA GEMM with fused epilogues ----------------
// 256 threads, 8 warps, warp tile 64x32, CTA tile 128x128
// EPI: 0 = store only; 1 = store/atomic + attention coef atomics; 2 = NER stage2
#define SA 40
#define SB 136
#define A_PL (128*SA*2)
#define B_PL (32*SB*2)
#define BOFF (2*A_PL)
#define STAGE_SZ (BOFF + 2*B_PL)
#define PIPE_SZ (2*STAGE_SZ)
#define HMMA_SMEM (PIPE_SZ + 4608)
template<int EPI>
__global__ void __launch_bounds__(256) k_hmma(
        const __nv_bfloat16* __restrict__ aHi, const __nv_bfloat16* __restrict__ aLo,
        int lda, int K, long aStrideZ,
        const __nv_bfloat16* __restrict__ wHi, const __nv_bfloat16* __restrict__ wLo, int N,
        long wStrideZ, const float* __restrict__ bias, int reluFlag,
        float* __restrict__ C, int ldc, long cStrideZ, int atomicC,
        const float* __restrict__ p1, const float* __restrict__ p2,
        float* __restrict__ q1, float* __restrict__ q2,
        int headC, int nheads, int validN){
    extern __shared__ char sm_buf[];
    int tid = threadIdx.x, lane = tid & 31, warp = tid >> 5;
    int wm = warp & 1, wn = warp >> 1;
    int grp = lane >> 3, rr = lane & 7;
    int arow = rr + (grp & 1)*8;
    int acol = (grp >> 1)*8;

    int n0 = blockIdx.x*128, m0 = blockIdx.y*128, z = blockIdx.z;
    const __nv_bfloat16* azh = aHi + (size_t)z*aStrideZ;
    const __nv_bfloat16* azl = aLo + (size_t)z*aStrideZ;
    const __nv_bfloat16* wzh = wHi + (size_t)z*wStrideZ;
    const __nv_bfloat16* wzl = wLo + (size_t)z*wStrideZ;
    int nc = K >> 5;

    float* sx = (float*)(sm_buf + PIPE_SZ);
    if(EPI == 1){
        if(tid < 128){
            int n = n0 + tid;
            sx[tid]     = (n < validN) ? p1[n] : 0.f;
            sx[128+tid] = (n < validN) ? p2[n] : 0.f;
        }
    }else if(EPI == 2){
        for(int j=tid; j<128*NERL; j+=256)
            sx[j] = p1[(size_t)(n0 + j/NERL)*NERL + (j%NERL)];
    }

    float acc[4][4][4];
    #pragma unroll
    for(int a=0;a<4;a++)
        #pragma unroll
        for(int b=0;b<4;b++)
            #pragma unroll
            for(int c=0;c<4;c++) acc[a][b][c] = 0.f;

    uint32_t sb0 = smem_u32(sm_buf);

    #define ISSUE(kc, st) do{                                                        \
        uint32_t sb = sb0 + (st)*STAGE_SZ;                                           \
        _Pragma("unroll")                                                            \
        for(int i=0;i<2;i++){                                                        \
            int idx = tid + i*256; int row = idx >> 2, k8 = idx & 3;                 \
            size_t go = (size_t)(m0+row)*lda + (kc)*32 + k8*8;                       \
            uint32_t d = sb + row*80 + k8*16;                                        \
            cp16(d,        azh + go);                                                \
            cp16(d + A_PL, azl + go);                                                \
        }                                                                            \
        _Pragma("unroll")                                                            \
        for(int i=0;i<2;i++){                                                        \
            int idx = tid + i*256; int kr = idx >> 4, ncol = idx & 15;               \
            size_t go = (size_t)((kc)*32 + kr)*N + n0 + ncol*8;                      \
            uint32_t d = sb + BOFF + kr*272 + ncol*16;                               \
            cp16(d,        wzh + go);                                                \
            cp16(d + B_PL, wzl + go);                                                \
        }                                                                            \
        asm volatile("cp.async.commit_group;" ::: "memory");                         \
    }while(0)

    ISSUE(0, 0);
    for(int kc=0; kc<nc; kc++){
        if(kc+1 < nc){
            ISSUE(kc+1, (kc+1)&1);
            asm volatile("cp.async.wait_group 1;" ::: "memory");
        }else{
            asm volatile("cp.async.wait_group 0;" ::: "memory");
        }
        __syncthreads();
        uint32_t sb = sb0 + (kc&1)*STAGE_SZ;
        uint32_t aBase = sb + ((wm*64 + arow)*SA + acol)*2;
        uint32_t bBase = sb + BOFF + (arow*SB + wn*32 + acol)*2;
        #pragma unroll
        for(int kk=0; kk<2; kk++){
            uint32_t bfr[2][2][4];
            #pragma unroll
            for(int pr=0; pr<2; pr++){
                uint32_t bd = bBase + kk*(16*SB*2) + pr*32;
                ldsm4t(bfr[pr][0], bd);
                ldsm4t(bfr[pr][1], bd + B_PL);
            }
            #pragma unroll
            for(int mt=0; mt<4; mt++){
                uint32_t af[2][4];
                uint32_t ad = aBase + mt*(16*SA*2) + kk*32;
                ldsm4(af[0], ad);
                ldsm4(af[1], ad + A_PL);
                #pragma unroll
                for(int nt=0; nt<4; nt++){
                    int pr = nt >> 1, hf = (nt & 1)*2;
                    uint32_t bh0 = bfr[pr][0][hf], bh1 = bfr[pr][0][hf+1];
                    uint32_t bl0 = bfr[pr][1][hf], bl1 = bfr[pr][1][hf+1];
                    mma16816(acc[mt][nt], af[0], bh0, bh1);
                    mma16816(acc[mt][nt], af[0], bl0, bl1);
                    mma16816(acc[mt][nt], af[1], bh0, bh1);
                }
            }
        }
        __syncthreads();
    }
    #undef ISSUE

    // ---- epilogue ----
    float* Cz = C + (size_t)z*cStrideZ;
    int hh = (n0 + wn*32) / headC;
    bool hhok = hh < nheads;
    float bcol[8];
    #pragma unroll
    for(int nt=0; nt<4; nt++){
        int n = n0 + wn*32 + nt*8 + (lane & 3)*2;
        bcol[nt*2]   = bias ? bias[n]   : 0.f;
        bcol[nt*2+1] = bias ? bias[n+1] : 0.f;
    }
    #pragma unroll
    for(int mt=0; mt<4; mt++){
        int mb = m0 + wm*64 + mt*16 + (lane >> 2);
        #pragma unroll
        for(int half=0; half<2; half++){
            int m = mb + half*8;
            float v[8];
            #pragma unroll
            for(int nt=0; nt<4; nt++){
                float a0 = acc[mt][nt][half*2]   + bcol[nt*2];
                float a1 = acc[mt][nt][half*2+1] + bcol[nt*2+1];
                if(reluFlag){ a0 = fmaxf(a0,0.f); a1 = fmaxf(a1,0.f); }
                v[nt*2] = a0; v[nt*2+1] = a1;
                if(EPI != 2){
                    int n = n0 + wn*32 + nt*8 + (lane & 3)*2;
                    if(atomicC){
                        atomicAdd(&Cz[(size_t)m*ldc + n],   a0);
                        atomicAdd(&Cz[(size_t)m*ldc + n+1], a1);
                    }else{
                        *reinterpret_cast<float2*>(Cz + (size_t)m*ldc + n) = make_float2(a0, a1);
                    }
                }
            }
            if(EPI == 1){
                float ps = 0.f, pd = 0.f;
                #pragma unroll
                for(int t=0;t<8;t++){
                    int ln = wn*32 + (t>>1)*8 + (lane&3)*2 + (t&1);
                    ps += v[t]*sx[ln];
                    pd += v[t]*sx[128+ln];
                }
                ps = quadSum(ps); pd = quadSum(pd);
                if((lane&3)==0 && hhok){
                    atomicAdd(&q1[m*nheads + hh], ps);
                    atomicAdd(&q2[m*nheads + hh], pd);
                }
            }else if(EPI == 2){
                float pc[NERL];
                #pragma unroll
                for(int c=0;c<NERL;c++) pc[c] = 0.f;
                #pragma unroll
                for(int t=0;t<8;t++){
                    int ln = wn*32 + (t>>1)*8 + (lane&3)*2 + (t&1);
                    #pragma unroll
                    for(int c=0;c<NERL;c++) pc[c] += v[t]*sx[ln*NERL + c];
                }
                #pragma unroll
                for(int c=0;c<NERL;c++){
                    float s = quadSum(pc[c]);
                    if((lane&3)==0) atomicAdd(&q1[(size_t)m*NERL + c], s);
                }
            }
        }
    }
}

// ---------------- entity span mean pooling -> bf16 hi/lo planes ----------------
__global__ void k_span_pool(const float* __restrict__ seq,
                            const int* __restrict__ est, const int* __restrict__ elen,
                            const int* __restrict__ ebat,
                            __nv_bfloat16* __restrict__ xh, __nv_bfloat16* __restrict__ xl){
    int n = blockIdx.x;
    int b = ebat[n], st = est[n], len = elen[n];
    const float* base = seq + ((size_t)b*Sdim + st)*Hdim + threadIdx.x*4;
    float4 acc = make_float4(0.f,0.f,0.f,0.f);
    for(int r=0; r<=len; r++){
        float4 t = *reinterpret_cast<const float4*>(base + (size_t)r*Hdim);
        acc.x += t.x; acc.y += t.y; acc.z += t.z; acc.w += t.w;
    }
    float inv = 1.0f/(float)(len+1);
    acc.x*=inv; acc.y*=inv; acc.z*=inv; acc.w*=inv;
    __nv_bfloat16 h0=__float2bfloat16(acc.x), h1=__float2bfloat16(acc.y);
    __nv_bfloat16 h2=__float2bfloat16(acc.z), h3=__float2bfloat16(acc.w);
    __nv_bfloat16 l0=__float2bfloat16(acc.x-__bfloat162float(h0));
    __nv_bfloat16 l1=__float2bfloat16(acc.y-__bfloat162float(h1));
    __nv_bfloat16 l2=__float2bfloat16(acc.z-__bfloat162float(h2));
    __nv_bfloat16 l3=__float2bfloat16(acc.w-__bfloat162float(h3));
    size_t o = (size_t)n*Hdim + threadIdx.x*4;
    *reinterpret_cast<uint2*>(&xh[o]) = make_uint2(pack_bf2(h0,h1), pack_bf2(h2,h3));
    *reinterpret_cast<uint2*>(&xl[o]) = make_uint2(pack_bf2(l0,l1), pack_bf2(l2,l3));
}

// ---------------- init kernels ----------------
__global__ void k_init0(){
    int i = blockIdx.x*blockDim.x + threadIdx.x;
    if(i >= Ndim) return;
    g_deg[i]=0; g_cursor[i]=0; g_pdeg[i]=0; g_pcur[i]=0;
    g_es2[i]=0.f; g_ed2[i]=0.f;
    #pragma unroll
    for(int h=0;h<H1;h++){ g_es1[i*H1+h]=0.f; g_ed1[i*H1+h]=0.f; }
    float4 z4 = make_float4(0.f,0.f,0.f,0.f);
    float4* h2 = reinterpret_cast<float4*>(&g_h2p[(size_t)i*128]);
    #pragma unroll
    for(int j=0;j<32;j++) h2[j] = z4;
}
__global__ void k_out_init(const float* __restrict__ b2, float* __restrict__ out){
    int i = blockIdx.x*blockDim.x + threadIdx.x;
    if(i < NER_OUT_ELEMS) out[i] = b2[i % NERL];
}

// ---------------- merged CSR + pair-sort build ----------------
__global__ void k_count(const int* __restrict__ ei, const int* __restrict__ pidx){
    int idx = blockIdx.x*blockDim.x + threadIdx.x;
    if(idx < ETOT){
        int dst = (idx < Edim) ? ei[Edim + idx] : (idx - Edim);
        atomicAdd(&g_deg[dst], 1);
    }else if(idx < ETOT + Pdim){
        atomicAdd(&g_pdeg[pidx[(idx - ETOT)*2]], 1);
    }
}
__global__ void k_scan(){
    __shared__ int s[1024];
    const int* deg = (blockIdx.x == 0) ? g_deg : g_pdeg;
    int* rowstart  = (blockIdx.x == 0) ? g_rowstart : g_prow;
    int t = threadIdx.x;
    int v0 = deg[t*4+0], v1 = deg[t*4+1], v2 = deg[t*4+2], v3 = deg[t*4+3];
    int c0 = v0, c1 = c0+v1, c2 = c1+v2, c3 = c2+v3;
    s[t] = c3;
    __syncthreads();
    for(int off=1; off<1024; off<<=1){
        int x = (t >= off) ? s[t-off] : 0;
        __syncthreads();
        s[t] += x;
        __syncthreads();
    }
    int excl = s[t] - c3;
    rowstart[t*4+1] = excl + c0;
    rowstart[t*4+2] = excl + c1;
    rowstart[t*4+3] = excl + c2;
    rowstart[t*4+4] = excl + c3;
    if(t==0) rowstart[0] = 0;
}
__global__ void k_scatter(const int* __restrict__ ei, const int* __restrict__ pidx){
    int idx = blockIdx.x*blockDim.x + threadIdx.x;
    if(idx < ETOT){
        int src, dst;
        if(idx < Edim){ src = ei[idx]; dst = ei[Edim + idx]; }
        else          { src = idx - Edim; dst = src; }
        int pos = g_rowstart[dst] + atomicAdd(&g_cursor[dst], 1);
        g_csr[pos] = src;
    }else if(idx < ETOT + Pdim){
        int p = idx - ETOT;
        int i = pidx[p*2];
        int pos = g_prow[i] + atomicAdd(&g_pcur[i], 1);
        g_psorted[pos] = p;
        g_psortj[pos]  = pidx[p*2+1];
    }
}

// ---------------- GAT softmax + aggregation (2-pass; logits small) ----------------
template<int HEADS,int C,int LD,bool RELU,bool SPLIT>
__global__ void k_gat_agg(const float* __restrict__ h,
                          const float* __restrict__ es, const float* __restrict__ ed,
                          const float* __restrict__ bias, float* __restrict__ out,
                          __nv_bfloat16* __restrict__ outH, __nv_bfloat16* __restrict__ outL){
    const int F = HEADS*C;
    int d = blockIdx.x;
    int hh = threadIdx.x >> 5, lane = threadIdx.x & 31;
    int rs = g_rowstart[d], re = g_rowstart[d+1];
    float edv = ed[d*HEADS + hh];

    float den = 0.f;
    for(int e=rs+lane; e<re; e+=32){
        int s = g_csr[e];
        float t = es[s*HEADS+hh] + edv;
        t = (t > 0.f) ? t : SLOPE*t;
        den += __expf(t);
    }
    den = warpSum(den);
    float inv = 1.0f/den;

    float acc[C/32];
    #pragma unroll
    for(int i=0;i<C/32;i++) acc[i]=0.f;

    for(int e=rs; e<re; e++){
        int s = g_csr[e];
        float t = es[s*HEADS+hh] + edv;
        t = (t > 0.f) ? t : SLOPE*t;
        float w = __expf(t)*inv;
        const float* hp = h + (size_t)s*LD + hh*C + lane;
        #pragma unroll
        for(int i=0;i<C/32;i++) acc[i] += w*hp[32*i];
    }
    #pragma unroll
    for(int i=0;i<C/32;i++){
        float v = acc[i] + bias[hh*C + lane + 32*i];
        if(RELU) v = fmaxf(v, 0.f);
        size_t o = (size_t)d*F + hh*C + lane + 32*i;
        if(SPLIT){
            __nv_bfloat16 hb = __float2bfloat16(v);
            outH[o] = hb;
            outL[o] = __float2bfloat16(v - __bfloat162float(hb));
        }else{
            out[o] = v;
        }
    }
}

// ---------------- fused relation head: warp-per-left-entity, r = blockIdx.y ----------------
// element mapping k = lane*8 + t (LN permutation-invariant; params indexed consistently)
__global__ void k_rel_g(const int* __restrict__ psorted, const int* __restrict__ psortj,
                        const float* __restrict__ relb1, const float* __restrict__ lng,
                        const float* __restrict__ lnb, const float* __restrict__ relW2,
                        const float* __restrict__ relb2, float* __restrict__ out){
    __shared__ float sb1[256], sg[256], sbb[256], sw2[256];
    int r = blockIdx.y;
    int tid = threadIdx.x;
    sb1[tid] = relb1[r*256+tid];
    sg[tid]  = lng[r*256+tid];
    sbb[tid] = lnb[r*256+tid];
    sw2[tid] = relW2[r*256+tid];
    __syncthreads();

    int w = tid >> 5, lane = tid & 31;
    int i = blockIdx.x*8 + w;
    int rs = g_prow[i], re = g_prow[i+1];
    if(rs == re) return;
    float rb2 = relb2[r];

    float ti[8];
    {
        const float4* tip = reinterpret_cast<const float4*>(
            g_tb + ((size_t)(r*2)*Ndim + i)*RHID + lane*8);
        float4 t0 = tip[0], t1 = tip[1];
        ti[0]=t0.x; ti[1]=t0.y; ti[2]=t0.z; ti[3]=t0.w;
        ti[4]=t1.x; ti[5]=t1.y; ti[6]=t1.z; ti[7]=t1.w;
    }
    const float* tjbase = g_tb + (size_t)(r*2+1)*Ndim*RHID;

    for(int idx = rs; idx < re; idx++){
        int p = psorted[idx];
        int j = psortj[idx];
        const float4* tj = reinterpret_cast<const float4*>(tjbase + (size_t)j*RHID + lane*8);
        float4 u0 = tj[0], u1 = tj[1];
        float tjv[8] = {u0.x,u0.y,u0.z,u0.w,u1.x,u1.y,u1.z,u1.w};
        float v[8]; float s1 = 0.f, s2 = 0.f;
        #pragma unroll
        for(int t=0;t<8;t++){
            int k = lane*8 + t;
            float x = ti[t] + tjv[t] + sb1[k];
            v[t] = x; s1 += x; s2 += x*x;
        }
        #pragma unroll
        for(int o=16;o;o>>=1){
            s1 += __shfl_xor_sync(0xffffffffu, s1, o);
            s2 += __shfl_xor_sync(0xffffffffu, s2, o);
        }
        float mu  = s1 * (1.0f/256.0f);
        float var = s2 * (1.0f/256.0f) - mu*mu;
        float rinv = rsqrtf(var + LNEPS);
        float acc = 0.f;
        #pragma unroll
        for(int t=0;t<8;t++){
            int k = lane*8 + t;
            float x = (v[t]-mu)*rinv*sg[k] + sbb[k];
            x = fmaxf(x, 0.f);
            acc += x * sw2[k];
        }
        acc = warpSum(acc);
        if(lane==0) out[(size_t)r*Pdim + p] = acc + rb2;
    }
}

// ---------------- launch ----------------
extern "C" void kernel_launch(void* const* d_in, const int* in_sizes, int n_in,
                              void* d_out, int out_size){
    const float* seq     = (const float*)d_in[0];
    const int*   est     = (const int*)  d_in[1];
    const int*   elen    = (const int*)  d_in[2];
    const int*   ebat    = (const int*)  d_in[3];
    const int*   ei      = (const int*)  d_in[4];
    const int*   pidx    = (const int*)  d_in[5];
    const float* W1      = (const float*)d_in[6];
    const float* a_src1  = (const float*)d_in[7];
    const float* a_dst1  = (const float*)d_in[8];
    const float* b1      = (const float*)d_in[9];
    const float* W2      = (const float*)d_in[10];
    const float* a_src2  = (const float*)d_in[11];
    const float* a_dst2  = (const float*)d_in[12];
    const float* b2      = (const float*)d_in[13];
    const float* relW1   = (const float*)d_in[14];
    const float* relb1   = (const float*)d_in[15];
    const float* ln_g    = (const float*)d_in[16];
    const float* ln_b    = (const float*)d_in[17];
    const float* relW2   = (const float*)d_in[18];
    const float* relb2   = (const float*)d_in[19];
    const float* nerW1   = (const float*)d_in[20];
    const float* nerb1   = (const float*)d_in[21];
    const float* nerW2   = (const float*)d_in[22];
    const float* nerb2   = (const float*)d_in[23];
    float* out = (float*)d_out;

    float *h1p, *h2pp, *es1p, *ed1p, *es2p, *ed2p, *tbp;
    int *psortedp, *psortjp;
    cudaGetSymbolAddress((void**)&h1p,  g_h1);
    cudaGetSymbolAddress((void**)&h2pp, g_h2p);
    cudaGetSymbolAddress((void**)&es1p, g_es1);
    cudaGetSymbolAddress((void**)&ed1p, g_ed1);
    cudaGetSymbolAddress((void**)&es2p, g_es2);
    cudaGetSymbolAddress((void**)&ed2p, g_ed2);
    cudaGetSymbolAddress((void**)&tbp,  g_tb);
    cudaGetSymbolAddress((void**)&psortedp, g_psorted);
    cudaGetSymbolAddress((void**)&psortjp,  g_psortj);
    __nv_bfloat16 *sqh,*sql,*x0h,*x0l,*o1h,*o1l,*x2h,*x2l,*w1h,*w1l,*wnh,*wnl,*w2h,*w2l,*wrh,*wrl;
    cudaGetSymbolAddress((void**)&sqh, g_sqh); cudaGetSymbolAddress((void**)&sql, g_sql);
    cudaGetSymbolAddress((void**)&x0h, g_x0h); cudaGetSymbolAddress((void**)&x0l, g_x0l);
    cudaGetSymbolAddress((void**)&o1h, g_o1h); cudaGetSymbolAddress((void**)&o1l, g_o1l);
    cudaGetSymbolAddress((void**)&x2h, g_x2h); cudaGetSymbolAddress((void**)&x2l, g_x2l);
    cudaGetSymbolAddress((void**)&w1h, g_w1h); cudaGetSymbolAddress((void**)&w1l, g_w1l);
    cudaGetSymbolAddress((void**)&wnh, g_wnh); cudaGetSymbolAddress((void**)&wnl, g_wnl);
    cudaGetSymbolAddress((void**)&w2h, g_w2h); cudaGetSymbolAddress((void**)&w2l, g_w2l);
    cudaGetSymbolAddress((void**)&wrh, g_wrh); cudaGetSymbolAddress((void**)&wrl, g_wrl);

    static cudaStream_t sNER = nullptr, sIDX = nullptr, sWSP = nullptr;
    static cudaEvent_t evRoot, evNER, evIDX, evZERO, evW1, evW2, evREL;
    if(sNER == nullptr){
        cudaStreamCreateWithFlags(&sNER, cudaStreamNonBlocking);
        cudaStreamCreateWithFlags(&sIDX, cudaStreamNonBlocking);
        cudaStreamCreateWithFlags(&sWSP, cudaStreamNonBlocking);
        cudaEventCreateWithFlags(&evRoot, cudaEventDisableTiming);
        cudaEventCreateWithFlags(&evNER,  cudaEventDisableTiming);
        cudaEventCreateWithFlags(&evIDX,  cudaEventDisableTiming);
        cudaEventCreateWithFlags(&evZERO, cudaEventDisableTiming);
        cudaEventCreateWithFlags(&evW1,   cudaEventDisableTiming);
        cudaEventCreateWithFlags(&evW2,   cudaEventDisableTiming);
        cudaEventCreateWithFlags(&evREL,  cudaEventDisableTiming);
        cudaFuncSetAttribute(k_hmma<0>, cudaFuncAttributeMaxDynamicSharedMemorySize, HMMA_SMEM);
        cudaFuncSetAttribute(k_hmma<1>, cudaFuncAttributeMaxDynamicSharedMemorySize, HMMA_SMEM);
        cudaFuncSetAttribute(k_hmma<2>, cudaFuncAttributeMaxDynamicSharedMemorySize, HMMA_SMEM);
    }

    #define SPLIT(st, src, dh, dl, cnt) \
        k_split<<<((cnt)/4 + 255)/256, 256, 0, st>>>((const float4*)(src), (uint2*)(dh), (uint2*)(dl), (cnt)/4)

    // fork
    cudaEventRecord(evRoot, 0);
    cudaStreamWaitEvent(sNER, evRoot, 0);
    cudaStreamWaitEvent(sIDX, evRoot, 0);
    cudaStreamWaitEvent(sWSP, evRoot, 0);

    // --- NER chain ---
    k_out_init<<<(NER_OUT_ELEMS+255)/256, 256, 0, sNER>>>(nerb2, out);
    SPLIT(sNER, nerW1, wnh, wnl, Hdim*NERH);
    SPLIT(sNER, seq,   sqh, sql, NERROWS*Hdim);
    k_hmma<2><<<dim3(NERH/128, NERROWS/128, 1), 256, HMMA_SMEM, sNER>>>(
        sqh, sql, Hdim, Hdim, 0, wnh, wnl, NERH, 0, nerb1, 1, nullptr, 0, 0, 0,
        nerW2, nullptr, out, nullptr, 128, 1, NERH);
    cudaEventRecord(evNER, sNER);

    // --- index build chain ---
    k_init0<<<(Ndim+255)/256, 256, 0, sIDX>>>();
    cudaEventRecord(evZERO, sIDX);
    k_count<<<(ETOT+Pdim+255)/256, 256, 0, sIDX>>>(ei, pidx);
    k_scan<<<2, 1024, 0, sIDX>>>();
    k_scatter<<<(ETOT+Pdim+255)/256, 256, 0, sIDX>>>(ei, pidx);
    cudaEventRecord(evIDX, sIDX);

    // --- weight splits ---
    SPLIT(sWSP, W1, w1h, w1l, Hdim*F1);
    cudaEventRecord(evW1, sWSP);
    k_split_padW2<<<F1*128/256, 256, 0, sWSP>>>(W2, w2h, w2l);
    cudaEventRecord(evW2, sWSP);
    SPLIT(sWSP, relW1, wrh, wrl, 12*C2*RHID);
    cudaEventRecord(evREL, sWSP);

    // --- main GAT chain ---
    k_span_pool<<<Ndim, 192>>>(seq, est, elen, ebat, x0h, x0l);
    cudaStreamWaitEvent(0, evW1, 0);
    cudaStreamWaitEvent(0, evZERO, 0);
    k_hmma<1><<<dim3(F1/128, Ndim/128, 1), 256, HMMA_SMEM>>>(
        x0h, x0l, Hdim, Hdim, 0, w1h, w1l, F1, 0, nullptr, 0, h1p, F1, 0, 0,
        a_src1, a_dst1, es1p, ed1p, C1, H1, F1);
    cudaStreamWaitEvent(0, evIDX, 0);
    k_gat_agg<H1, C1, F1, true, true><<<Ndim, 128>>>(h1p, es1p, ed1p, b1, nullptr, o1h, o1l);
    cudaStreamWaitEvent(0, evW2, 0);
    k_hmma<1><<<dim3(1, Ndim/128, 2), 256, HMMA_SMEM>>>(
        o1h, o1l, F1, 256, 256, w2h, w2l, 128, (long)256*128, nullptr, 0,
        h2pp, 128, 0, 1,
        a_src2, a_dst2, es2p, ed2p, C2, 1, C2);
    k_gat_agg<1, C2, 128, false, true><<<Ndim, 32>>>(h2pp, es2p, ed2p, b2, nullptr, x2h, x2l);
    cudaStreamWaitEvent(0, evREL, 0);
    k_hmma<0><<<dim3(RHID/128, Ndim/128, 12), 256, HMMA_SMEM>>>(
        x2h, x2l, C2, C2, 0, wrh, wrl, RHID, (long)C2*RHID, nullptr, 0,
        tbp, RHID, (long)Ndim*RHID, 0,
        nullptr, nullptr, nullptr, nullptr, 128, 1, RHID);
    k_rel_g<<<dim3(Ndim/8, NREL), 256>>>(psortedp, psortjp,
        relb1, ln_g, ln_b, relW2, relb2, out + NER_OUT_ELEMS);

    // join
    cudaStreamWaitEvent(0, evNER, 0);
    #undef SPLIT
}

// round 13
// speedup vs baseline: 1.3908x; 1.3908x over previous
#include <cuda_runtime.h>
#include <cuda_bf16.h>
#include <math.h>
#include <stdint.h>

// ---------------- problem constants ----------------
#define Bdim 32
#define Sdim 512
#define Hdim 768
#define Ndim 4096
#define Edim 131072
#define Pdim 65536
#define ETOT (Edim + Ndim)
#define H1 4
#define C1 128
#define F1 (H1*C1)               // 512
#define C2 64
#define NREL 6
#define RHID 256
#define NERH 256
#define NERL 9
#define SLOPE 0.2f
#define LNEPS 1e-5f
#define NER_OUT_ELEMS (Bdim*Sdim*NERL)
#define NERROWS (Bdim*Sdim)      // 16384

// ---------------- device scratch ----------------
__device__ float g_h1[Ndim*F1];
__device__ float g_h2p[Ndim*128];
__device__ float g_es1[Ndim*H1], g_ed1[Ndim*H1];
__device__ float g_es2[Ndim],    g_ed2[Ndim];
__device__ int   g_deg[Ndim], g_cursor[Ndim], g_rowstart[Ndim+1];
__device__ int   g_csr[ETOT];
__device__ int   g_pdeg[Ndim], g_pcur[Ndim], g_prow[Ndim+1];
__device__ int   g_psorted[Pdim];
__device__ int   g_psortj[Pdim];
__device__ float g_tb[12*Ndim*RHID];
__device__ __nv_bfloat16 g_sqh[NERROWS*Hdim], g_sql[NERROWS*Hdim];
__device__ __nv_bfloat16 g_x0h[Ndim*Hdim],    g_x0l[Ndim*Hdim];
__device__ __nv_bfloat16 g_o1h[Ndim*F1],      g_o1l[Ndim*F1];
__device__ __nv_bfloat16 g_x2h[Ndim*C2],      g_x2l[Ndim*C2];
__device__ __nv_bfloat16 g_w1h[Hdim*F1],      g_w1l[Hdim*F1];
__device__ __nv_bfloat16 g_wnh[Hdim*NERH],    g_wnl[Hdim*NERH];
__device__ __nv_bfloat16 g_w2h[F1*128],       g_w2l[F1*128];
__device__ __nv_bfloat16 g_wrh[12*C2*RHID],   g_wrl[12*C2*RHID];

// ---------------- helpers ----------------
__device__ __forceinline__ float warpSum(float v){
    #pragma unroll
    for(int o=16;o;o>>=1) v += __shfl_xor_sync(0xffffffffu, v, o);
    return v;
}
__device__ __forceinline__ float quadSum(float v){
    v += __shfl_xor_sync(0xffffffffu, v, 1);
    v += __shfl_xor_sync(0xffffffffu, v, 2);
    return v;
}
__device__ __forceinline__ uint32_t smem_u32(const void* p){
    uint32_t a;
    asm("{ .reg .u64 t; cvta.to.shared.u64 t, %1; cvt.u32.u64 %0, t; }" : "=r"(a) : "l"(p));
    return a;
}
__device__ __forceinline__ unsigned pack_bf2(__nv_bfloat16 a, __nv_bfloat16 b){
    __nv_bfloat162 t; t.x = a; t.y = b;
    return *reinterpret_cast<unsigned*>(&t);
}
__device__ __forceinline__ void cp16(uint32_t dst, const void* src){
    asm volatile("cp.async.ca.shared.global [%0], [%1], 16;" :: "r"(dst), "l"(src) : "memory");
}
__device__ __forceinline__ void prefetchL2(const void* p){
    asm volatile("prefetch.global.L2 [%0];" :: "l"(p));
}
__device__ __forceinline__ void ldsm4(uint32_t* r, uint32_t addr){
    asm volatile("ldmatrix.sync.aligned.m8n8.x4.shared.b16 {%0,%1,%2,%3}, [%4];"
        : "=r"(r[0]), "=r"(r[1]), "=r"(r[2]), "=r"(r[3]) : "r"(addr));
}
__device__ __forceinline__ void ldsm4t(uint32_t* r, uint32_t addr){
    asm volatile("ldmatrix.sync.aligned.m8n8.x4.trans.shared.b16 {%0,%1,%2,%3}, [%4];"
        : "=r"(r[0]), "=r"(r[1]), "=r"(r[2]), "=r"(r[3]) : "r"(addr));
}
__device__ __forceinline__ void mma16816(float* d, const uint32_t* a, uint32_t b0, uint32_t b1){
    asm volatile(
        "mma.sync.aligned.m16n8k16.row.col.f32.bf16.bf16.f32 "
        "{%0,%1,%2,%3}, {%4,%5,%6,%7}, {%8,%9}, {%0,%1,%2,%3};"
        : "+f"(d[0]), "+f"(d[1]), "+f"(d[2]), "+f"(d[3])
        : "r"(a[0]), "r"(a[1]), "r"(a[2]), "r"(a[3]), "r"(b0), "r"(b1));
}

// ---------------- split fp32 -> bf16 hi/lo planes ----------------
__global__ void k_split(const float4* __restrict__ in, uint2* __restrict__ hi,
                        uint2* __restrict__ lo, int n4){
    int i = blockIdx.x*blockDim.x + threadIdx.x;
    if(i >= n4) return;
    float4 v = in[i];
    __nv_bfloat16 h0=__float2bfloat16(v.x), h1=__float2bfloat16(v.y);
    __nv_bfloat16 h2=__float2bfloat16(v.z), h3=__float2bfloat16(v.w);
    __nv_bfloat16 l0=__float2bfloat16(v.x-__bfloat162float(h0));
    __nv_bfloat16 l1=__float2bfloat16(v.y-__bfloat162float(h1));
    __nv_bfloat16 l2=__float2bfloat16(v.z-__bfloat162float(h2));
    __nv_bfloat16 l3=__float2bfloat16(v.w-__bfloat162float(h3));
    hi[i] = make_uint2(pack_bf2(h0,h1), pack_bf2(h2,h3));
    lo[i] = make_uint2(pack_bf2(l0,l1), pack_bf2(l2,l3));
}

__global__ void k_split_padW2(const float* __restrict__ W2,
                              __nv_bfloat16* __restrict__ hi, __nv_bfloat16* __restrict__ lo){
    int idx = blockIdx.x*256 + threadIdx.x;
    int k = idx >> 7, c = idx & 127;
    float v = (c < C2) ? W2[k*C2 + c] : 0.f;
    __nv_bfloat16 h = __float2bfloat16(v);
    __nv_bfloat16 l = __float2bfloat16(v - __bfloat162float(h));
    hi[idx] = h; lo[idx] = l;
}

// ---------------- split-bf16 HMMA GEMM with fused epilogues ----------------
// 256 threads, 8 warps, warp tile 64x32, CTA tile 128x128
// EPI: 0 = store only; 1 = store/atomic + attention coef atomics; 2 = NER stage2
#define SA 40
#define SB 136
#define A_PL (128*SA*2)
#define B_PL (32*SB*2)
#define BOFF (2*A_PL)
#define STAGE_SZ (BOFF + 2*B_PL)
#define PIPE_SZ (2*STAGE_SZ)
#define HMMA_SMEM (PIPE_SZ + 4608)
template<int EPI>
__global__ void __launch_bounds__(256) k_hmma(
        const __nv_bfloat16* __restrict__ aHi, const __nv_bfloat16* __restrict__ aLo,
        int lda, int K, long aStrideZ,
        const __nv_bfloat16* __restrict__ wHi, const __nv_bfloat16* __restrict__ wLo, int N,
        long wStrideZ, const float* __restrict__ bias, int reluFlag,
        float* __restrict__ C, int ldc, long cStrideZ, int atomicC,
        const float* __restrict__ p1, const float* __restrict__ p2,
        float* __restrict__ q1, float* __restrict__ q2,
        int headC, int nheads, int validN){
    extern __shared__ char sm_buf[];
    int tid = threadIdx.x, lane = tid & 31, warp = tid >> 5;
    int wm = warp & 1, wn = warp >> 1;
    int grp = lane >> 3, rr = lane & 7;
    int arow = rr + (grp & 1)*8;
    int acol = (grp >> 1)*8;

    int n0 = blockIdx.x*128, m0 = blockIdx.y*128, z = blockIdx.z;
    const __nv_bfloat16* azh = aHi + (size_t)z*aStrideZ;
    const __nv_bfloat16* azl = aLo + (size_t)z*aStrideZ;
    const __nv_bfloat16* wzh = wHi + (size_t)z*wStrideZ;
    const __nv_bfloat16* wzl = wLo + (size_t)z*wStrideZ;
    int nc = K >> 5;

    float* sx = (float*)(sm_buf + PIPE_SZ);
    if(EPI == 1){
        if(tid < 128){
            int n = n0 + tid;
            sx[tid]     = (n < validN) ? p1[n] : 0.f;
            sx[128+tid] = (n < validN) ? p2[n] : 0.f;
        }
    }else if(EPI == 2){
        for(int j=tid; j<128*NERL; j+=256)
            sx[j] = p1[(size_t)(n0 + j/NERL)*NERL + (j%NERL)];
    }

    float acc[4][4][4];
    #pragma unroll
    for(int a=0;a<4;a++)
        #pragma unroll
        for(int b=0;b<4;b++)
            #pragma unroll
            for(int c=0;c<4;c++) acc[a][b][c] = 0.f;

    uint32_t sb0 = smem_u32(sm_buf);

    #define ISSUE(kc, st) do{                                                        \
        uint32_t sb = sb0 + (st)*STAGE_SZ;                                           \
        _Pragma("unroll")                                                            \
        for(int i=0;i<2;i++){                                                        \
            int idx = tid + i*256; int row = idx >> 2, k8 = idx & 3;                 \
            size_t go = (size_t)(m0+row)*lda + (kc)*32 + k8*8;                       \
            uint32_t d = sb + row*80 + k8*16;                                        \
            cp16(d,        azh + go);                                                \
            cp16(d + A_PL, azl + go);                                                \
        }                                                                            \
        _Pragma("unroll")                                                            \
        for(int i=0;i<2;i++){                                                        \
            int idx = tid + i*256; int kr = idx >> 4, ncol = idx & 15;               \
            size_t go = (size_t)((kc)*32 + kr)*N + n0 + ncol*8;                      \
            uint32_t d = sb + BOFF + kr*272 + ncol*16;                               \
            cp16(d,        wzh + go);                                                \
            cp16(d + B_PL, wzl + go);                                                \
        }                                                                            \
        asm volatile("cp.async.commit_group;" ::: "memory");                         \
    }while(0)

    ISSUE(0, 0);
    for(int kc=0; kc<nc; kc++){
        if(kc+1 < nc){
            ISSUE(kc+1, (kc+1)&1);
            asm volatile("cp.async.wait_group 1;" ::: "memory");
        }else{
            asm volatile("cp.async.wait_group 0;" ::: "memory");
        }
        __syncthreads();
        uint32_t sb = sb0 + (kc&1)*STAGE_SZ;
        uint32_t aBase = sb + ((wm*64 + arow)*SA + acol)*2;
        uint32_t bBase = sb + BOFF + (arow*SB + wn*32 + acol)*2;
        #pragma unroll
        for(int kk=0; kk<2; kk++){
            uint32_t bfr[2][2][4];
            #pragma unroll
            for(int pr=0; pr<2; pr++){
                uint32_t bd = bBase + kk*(16*SB*2) + pr*32;
                ldsm4t(bfr[pr][0], bd);
                ldsm4t(bfr[pr][1], bd + B_PL);
            }
            #pragma unroll
            for(int mt=0; mt<4; mt++){
                uint32_t af[2][4];
                uint32_t ad = aBase + mt*(16*SA*2) + kk*32;
                ldsm4(af[0], ad);
                ldsm4(af[1], ad + A_PL);
                #pragma unroll
                for(int nt=0; nt<4; nt++){
                    int pr = nt >> 1, hf = (nt & 1)*2;
                    uint32_t bh0 = bfr[pr][0][hf], bh1 = bfr[pr][0][hf+1];
                    uint32_t bl0 = bfr[pr][1][hf], bl1 = bfr[pr][1][hf+1];
                    mma16816(acc[mt][nt], af[0], bh0, bh1);
                    mma16816(acc[mt][nt], af[0], bl0, bl1);
                    mma16816(acc[mt][nt], af[1], bh0, bh1);
                }
            }
        }
        __syncthreads();
    }
    #undef ISSUE

    // ---- epilogue ----
    float* Cz = C + (size_t)z*cStrideZ;
    int hh = (n0 + wn*32) / headC;
    bool hhok = hh < nheads;
    float bcol[8];
    #pragma unroll
    for(int nt=0; nt<4; nt++){
        int n = n0 + wn*32 + nt*8 + (lane & 3)*2;
        bcol[nt*2]   = bias ? bias[n]   : 0.f;
        bcol[nt*2+1] = bias ? bias[n+1] : 0.f;
    }
    #pragma unroll
    for(int mt=0; mt<4; mt++){
        int mb = m0 + wm*64 + mt*16 + (lane >> 2);
        #pragma unroll
        for(int half=0; half<2; half++){
            int m = mb + half*8;
            float v[8];
            #pragma unroll
            for(int nt=0; nt<4; nt++){
                float a0 = acc[mt][nt][half*2]   + bcol[nt*2];
                float a1 = acc[mt][nt][half*2+1] + bcol[nt*2+1];
                if(reluFlag){ a0 = fmaxf(a0,0.f); a1 = fmaxf(a1,0.f); }
                v[nt*2] = a0; v[nt*2+1] = a1;
                if(EPI != 2){
                    int n = n0 + wn*32 + nt*8 + (lane & 3)*2;
                    if(atomicC){
                        atomicAdd(&Cz[(size_t)m*ldc + n],   a0);
                        atomicAdd(&Cz[(size_t)m*ldc + n+1], a1);
                    }else{
                        *reinterpret_cast<float2*>(Cz + (size_t)m*ldc + n) = make_float2(a0, a1);
                    }
                }
            }
            if(EPI == 1){
                float ps = 0.f, pd = 0.f;
                #pragma unroll
                for(int t=0;t<8;t++){
                    int ln = wn*32 + (t>>1)*8 + (lane&3)*2 + (t&1);
                    ps += v[t]*sx[ln];
                    pd += v[t]*sx[128+ln];
                }
                ps = quadSum(ps); pd = quadSum(pd);
                if((lane&3)==0 && hhok){
                    atomicAdd(&q1[m*nheads + hh], ps);
                    atomicAdd(&q2[m*nheads + hh], pd);
                }
            }else if(EPI == 2){
                float pc[NERL];
                #pragma unroll
                for(int c=0;c<NERL;c++) pc[c] = 0.f;
                #pragma unroll
                for(int t=0;t<8;t++){
                    int ln = wn*32 + (t>>1)*8 + (lane&3)*2 + (t&1);
                    #pragma unroll
                    for(int c=0;c<NERL;c++) pc[c] += v[t]*sx[ln*NERL + c];
                }
                #pragma unroll
                for(int c=0;c<NERL;c++){
                    float s = quadSum(pc[c]);
                    if((lane&3)==0) atomicAdd(&q1[(size_t)m*NERL + c], s);
                }
            }
        }
    }
}

// ---------------- entity span mean pooling -> bf16 hi/lo planes ----------------
__global__ void k_span_pool(const float* __restrict__ seq,
                            const int* __restrict__ est, const int* __restrict__ elen,
                            const int* __restrict__ ebat,
                            __nv_bfloat16* __restrict__ xh, __nv_bfloat16* __restrict__ xl){
    int n = blockIdx.x;
    int b = ebat[n], st = est[n], len = elen[n];
    const float* base = seq + ((size_t)b*Sdim + st)*Hdim + threadIdx.x*4;
    float4 acc = make_float4(0.f,0.f,0.f,0.f);
    for(int r=0; r<=len; r++){
        float4 t = *reinterpret_cast<const float4*>(base + (size_t)r*Hdim);
        acc.x += t.x; acc.y += t.y; acc.z += t.z; acc.w += t.w;
    }
    float inv = 1.0f/(float)(len+1);
    acc.x*=inv; acc.y*=inv; acc.z*=inv; acc.w*=inv;
    __nv_bfloat16 h0=__float2bfloat16(acc.x), h1=__float2bfloat16(acc.y);
    __nv_bfloat16 h2=__float2bfloat16(acc.z), h3=__float2bfloat16(acc.w);
    __nv_bfloat16 l0=__float2bfloat16(acc.x-__bfloat162float(h0));
    __nv_bfloat16 l1=__float2bfloat16(acc.y-__bfloat162float(h1));
    __nv_bfloat16 l2=__float2bfloat16(acc.z-__bfloat162float(h2));
    __nv_bfloat16 l3=__float2bfloat16(acc.w-__bfloat162float(h3));
    size_t o = (size_t)n*Hdim + threadIdx.x*4;
    *reinterpret_cast<uint2*>(&xh[o]) = make_uint2(pack_bf2(h0,h1), pack_bf2(h2,h3));
    *reinterpret_cast<uint2*>(&xl[o]) = make_uint2(pack_bf2(l0,l1), pack_bf2(l2,l3));
}

// ---------------- init kernels ----------------
__global__ void k_init0(){
    int i = blockIdx.x*blockDim.x + threadIdx.x;
    if(i >= Ndim) return;
    g_deg[i]=0; g_cursor[i]=0; g_pdeg[i]=0; g_pcur[i]=0;
    g_es2[i]=0.f; g_ed2[i]=0.f;
    #pragma unroll
    for(int h=0;h<H1;h++){ g_es1[i*H1+h]=0.f; g_ed1[i*H1+h]=0.f; }
    float4 z4 = make_float4(0.f,0.f,0.f,0.f);
    float4* h2 = reinterpret_cast<float4*>(&g_h2p[(size_t)i*128]);
    #pragma unroll
    for(int j=0;j<32;j++) h2[j] = z4;
}
__global__ void k_out_init(const float* __restrict__ b2, float* __restrict__ out){
    int i = blockIdx.x*blockDim.x + threadIdx.x;
    if(i < NER_OUT_ELEMS) out[i] = b2[i % NERL];
}

// ---------------- merged CSR + pair-sort build ----------------
__global__ void k_count(const int* __restrict__ ei, const int* __restrict__ pidx){
    int idx = blockIdx.x*blockDim.x + threadIdx.x;
    if(idx < ETOT){
        int dst = (idx < Edim) ? ei[Edim + idx] : (idx - Edim);
        atomicAdd(&g_deg[dst], 1);
    }else if(idx < ETOT + Pdim){
        atomicAdd(&g_pdeg[pidx[(idx - ETOT)*2]], 1);
    }
}
__global__ void k_scan(){
    __shared__ int s[1024];
    const int* deg = (blockIdx.x == 0) ? g_deg : g_pdeg;
    int* rowstart  = (blockIdx.x == 0) ? g_rowstart : g_prow;
    int t = threadIdx.x;
    int v0 = deg[t*4+0], v1 = deg[t*4+1], v2 = deg[t*4+2], v3 = deg[t*4+3];
    int c0 = v0, c1 = c0+v1, c2 = c1+v2, c3 = c2+v3;
    s[t] = c3;
    __syncthreads();
    for(int off=1; off<1024; off<<=1){
        int x = (t >= off) ? s[t-off] : 0;
        __syncthreads();
        s[t] += x;
        __syncthreads();
    }
    int excl = s[t] - c3;
    rowstart[t*4+1] = excl + c0;
    rowstart[t*4+2] = excl + c1;
    rowstart[t*4+3] = excl + c2;
    rowstart[t*4+4] = excl + c3;
    if(t==0) rowstart[0] = 0;
}
__global__ void k_scatter(const int* __restrict__ ei, const int* __restrict__ pidx){
    int idx = blockIdx.x*blockDim.x + threadIdx.x;
    if(idx < ETOT){
        int src, dst;
        if(idx < Edim){ src = ei[idx]; dst = ei[Edim + idx]; }
        else          { src = idx - Edim; dst = src; }
        int pos = g_rowstart[dst] + atomicAdd(&g_cursor[dst], 1);
        g_csr[pos] = src;
    }else if(idx < ETOT + Pdim){
        int p = idx - ETOT;
        int i = pidx[p*2];
        int pos = g_prow[i] + atomicAdd(&g_pcur[i], 1);
        g_psorted[pos] = p;
        g_psortj[pos]  = pidx[p*2+1];
    }
}

// ---------------- GAT softmax + aggregation (2-pass; logits small) ----------------
template<int HEADS,int C,int LD,bool RELU,bool SPLIT>
__global__ void k_gat_agg(const float* __restrict__ h,
                          const float* __restrict__ es, const float* __restrict__ ed,
                          const float* __restrict__ bias, float* __restrict__ out,
                          __nv_bfloat16* __restrict__ outH, __nv_bfloat16* __restrict__ outL){
    const int F = HEADS*C;
    int d = blockIdx.x;
    int hh = threadIdx.x >> 5, lane = threadIdx.x & 31;
    int rs = g_rowstart[d], re = g_rowstart[d+1];
    float edv = ed[d*HEADS + hh];

    float den = 0.f;
    for(int e=rs+lane; e<re; e+=32){
        int s = g_csr[e];
        float t = es[s*HEADS+hh] + edv;
        t = (t > 0.f) ? t : SLOPE*t;
        den += __expf(t);
    }
    den = warpSum(den);
    float inv = 1.0f/den;

    float acc[C/32];
    #pragma unroll
    for(int i=0;i<C/32;i++) acc[i]=0.f;

    for(int e=rs; e<re; e++){
        // prefetch next source row into L2 while computing this one
        if(e+1 < re)
            prefetchL2(h + (size_t)g_csr[e+1]*LD + hh*C + lane);
        int s = g_csr[e];
        float t = es[s*HEADS+hh] + edv;
        t = (t > 0.f) ? t : SLOPE*t;
        float w = __expf(t)*inv;
        const float* hp = h + (size_t)s*LD + hh*C + lane;
        #pragma unroll
        for(int i=0;i<C/32;i++) acc[i] += w*hp[32*i];
    }
    #pragma unroll
    for(int i=0;i<C/32;i++){
        float v = acc[i] + bias[hh*C + lane + 32*i];
        if(RELU) v = fmaxf(v, 0.f);
        size_t o = (size_t)d*F + hh*C + lane + 32*i;
        if(SPLIT){
            __nv_bfloat16 hb = __float2bfloat16(v);
            outH[o] = hb;
            outL[o] = __float2bfloat16(v - __bfloat162float(hb));
        }else{
            out[o] = v;
        }
    }
}

// ---------------- fused relation head: warp-per-left-entity, r = blockIdx.y ----------------
// element mapping k = lane*8 + t (LN permutation-invariant; params indexed consistently)
__global__ void k_rel_g(const int* __restrict__ psorted, const int* __restrict__ psortj,
                        const float* __restrict__ relb1, const float* __restrict__ lng,
                        const float* __restrict__ lnb, const float* __restrict__ relW2,
                        const float* __restrict__ relb2, float* __restrict__ out){
    __shared__ float sb1[256], sg[256], sbb[256], sw2[256];
    int r = blockIdx.y;
    int tid = threadIdx.x;
    sb1[tid] = relb1[r*256+tid];
    sg[tid]  = lng[r*256+tid];
    sbb[tid] = lnb[r*256+tid];
    sw2[tid] = relW2[r*256+tid];
    __syncthreads();

    int w = tid >> 5, lane = tid & 31;
    int i = blockIdx.x*8 + w;
    int rs = g_prow[i], re = g_prow[i+1];
    if(rs == re) return;
    float rb2 = relb2[r];

    float ti[8];
    {
        const float4* tip = reinterpret_cast<const float4*>(
            g_tb + ((size_t)(r*2)*Ndim + i)*RHID + lane*8);
        float4 t0 = tip[0], t1 = tip[1];
        ti[0]=t0.x; ti[1]=t0.y; ti[2]=t0.z; ti[3]=t0.w;
        ti[4]=t1.x; ti[5]=t1.y; ti[6]=t1.z; ti[7]=t1.w;
    }
    const float* tjbase = g_tb + (size_t)(r*2+1)*Ndim*RHID;

    for(int idx = rs; idx < re; idx++){
        // prefetch next pair's tj row into L2 (zero register cost)
        if(idx+1 < re)
            prefetchL2(tjbase + (size_t)psortj[idx+1]*RHID + lane*8);
        int p = psorted[idx];
        int j = psortj[idx];
        const float4* tj = reinterpret_cast<const float4*>(tjbase + (size_t)j*RHID + lane*8);
        float4 u0 = tj[0], u1 = tj[1];
        float tjv[8] = {u0.x,u0.y,u0.z,u0.w,u1.x,u1.y,u1.z,u1.w};
        float v[8]; float s1 = 0.f, s2 = 0.f;
        #pragma unroll
        for(int t=0;t<8;t++){
            int k = lane*8 + t;
            float x = ti[t] + tjv[t] + sb1[k];
            v[t] = x; s1 += x; s2 += x*x;
        }
        #pragma unroll
        for(int o=16;o;o>>=1){
            s1 += __shfl_xor_sync(0xffffffffu, s1, o);
            s2 += __shfl_xor_sync(0xffffffffu, s2, o);
        }
        float mu  = s1 * (1.0f/256.0f);
        float var = s2 * (1.0f/256.0f) - mu*mu;
        float rinv = rsqrtf(var + LNEPS);
        float acc = 0.f;
        #pragma unroll
        for(int t=0;t<8;t++){
            int k = lane*8 + t;
            float x = (v[t]-mu)*rinv*sg[k] + sbb[k];
            x = fmaxf(x, 0.f);
            acc += x * sw2[k];
        }
        acc = warpSum(acc);
        if(lane==0) out[(size_t)r*Pdim + p] = acc + rb2;
    }
}

// ---------------- launch ----------------
extern "C" void kernel_launch(void* const* d_in, const int* in_sizes, int n_in,
                              void* d_out, int out_size){
    const float* seq     = (const float*)d_in[0];
    const int*   est     = (const int*)  d_in[1];
    const int*   elen    = (const int*)  d_in[2];
    const int*   ebat    = (const int*)  d_in[3];
    const int*   ei      = (const int*)  d_in[4];
    const int*   pidx    = (const int*)  d_in[5];
    const float* W1      = (const float*)d_in[6];
    const float* a_src1  = (const float*)d_in[7];
    const float* a_dst1  = (const float*)d_in[8];
    const float* b1      = (const float*)d_in[9];
    const float* W2      = (const float*)d_in[10];
    const float* a_src2  = (const float*)d_in[11];
    const float* a_dst2  = (const float*)d_in[12];
    const float* b2      = (const float*)d_in[13];
    const float* relW1   = (const float*)d_in[14];
    const float* relb1   = (const float*)d_in[15];
    const float* ln_g    = (const float*)d_in[16];
    const float* ln_b    = (const float*)d_in[17];
    const float* relW2   = (const float*)d_in[18];
    const float* relb2   = (const float*)d_in[19];
    const float* nerW1   = (const float*)d_in[20];
    const float* nerb1   = (const float*)d_in[21];
    const float* nerW2   = (const float*)d_in[22];
    const float* nerb2   = (const float*)d_in[23];
    float* out = (float*)d_out;

    float *h1p, *h2pp, *es1p, *ed1p, *es2p, *ed2p, *tbp;
    int *psortedp, *psortjp;
    cudaGetSymbolAddress((void**)&h1p,  g_h1);
    cudaGetSymbolAddress((void**)&h2pp, g_h2p);
    cudaGetSymbolAddress((void**)&es1p, g_es1);
    cudaGetSymbolAddress((void**)&ed1p, g_ed1);
    cudaGetSymbolAddress((void**)&es2p, g_es2);
    cudaGetSymbolAddress((void**)&ed2p, g_ed2);
    cudaGetSymbolAddress((void**)&tbp,  g_tb);
    cudaGetSymbolAddress((void**)&psortedp, g_psorted);
    cudaGetSymbolAddress((void**)&psortjp,  g_psortj);
    __nv_bfloat16 *sqh,*sql,*x0h,*x0l,*o1h,*o1l,*x2h,*x2l,*w1h,*w1l,*wnh,*wnl,*w2h,*w2l,*wrh,*wrl;
    cudaGetSymbolAddress((void**)&sqh, g_sqh); cudaGetSymbolAddress((void**)&sql, g_sql);
    cudaGetSymbolAddress((void**)&x0h, g_x0h); cudaGetSymbolAddress((void**)&x0l, g_x0l);
    cudaGetSymbolAddress((void**)&o1h, g_o1h); cudaGetSymbolAddress((void**)&o1l, g_o1l);
    cudaGetSymbolAddress((void**)&x2h, g_x2h); cudaGetSymbolAddress((void**)&x2l, g_x2l);
    cudaGetSymbolAddress((void**)&w1h, g_w1h); cudaGetSymbolAddress((void**)&w1l, g_w1l);
    cudaGetSymbolAddress((void**)&wnh, g_wnh); cudaGetSymbolAddress((void**)&wnl, g_wnl);
    cudaGetSymbolAddress((void**)&w2h, g_w2h); cudaGetSymbolAddress((void**)&w2l, g_w2l);
    cudaGetSymbolAddress((void**)&wrh, g_wrh); cudaGetSymbolAddress((void**)&wrl, g_wrl);

    static cudaStream_t sNER = nullptr, sIDX = nullptr, sWSP = nullptr;
    static cudaEvent_t evRoot, evNER, evIDX, evZERO, evW1, evW2, evREL;
    if(sNER == nullptr){
        cudaStreamCreateWithFlags(&sNER, cudaStreamNonBlocking);
        cudaStreamCreateWithFlags(&sIDX, cudaStreamNonBlocking);
        cudaStreamCreateWithFlags(&sWSP, cudaStreamNonBlocking);
        cudaEventCreateWithFlags(&evRoot, cudaEventDisableTiming);
        cudaEventCreateWithFlags(&evNER,  cudaEventDisableTiming);
        cudaEventCreateWithFlags(&evIDX,  cudaEventDisableTiming);
        cudaEventCreateWithFlags(&evZERO, cudaEventDisableTiming);
        cudaEventCreateWithFlags(&evW1,   cudaEventDisableTiming);
        cudaEventCreateWithFlags(&evW2,   cudaEventDisableTiming);
        cudaEventCreateWithFlags(&evREL,  cudaEventDisableTiming);
        cudaFuncSetAttribute(k_hmma<0>, cudaFuncAttributeMaxDynamicSharedMemorySize, HMMA_SMEM);
        cudaFuncSetAttribute(k_hmma<1>, cudaFuncAttributeMaxDynamicSharedMemorySize, HMMA_SMEM);
        cudaFuncSetAttribute(k_hmma<2>, cudaFuncAttributeMaxDynamicSharedMemorySize, HMMA_SMEM);
    }

    #define SPLIT(st, src, dh, dl, cnt) \
        k_split<<<((cnt)/4 + 255)/256, 256, 0, st>>>((const float4*)(src), (uint2*)(dh), (uint2*)(dl), (cnt)/4)

    // fork
    cudaEventRecord(evRoot, 0);
    cudaStreamWaitEvent(sNER, evRoot, 0);
    cudaStreamWaitEvent(sIDX, evRoot, 0);
    cudaStreamWaitEvent(sWSP, evRoot, 0);

    // --- NER chain ---
    k_out_init<<<(NER_OUT_ELEMS+255)/256, 256, 0, sNER>>>(nerb2, out);
    SPLIT(sNER, nerW1, wnh, wnl, Hdim*NERH);
    SPLIT(sNER, seq,   sqh, sql, NERROWS*Hdim);
    k_hmma<2><<<dim3(NERH/128, NERROWS/128, 1), 256, HMMA_SMEM, sNER>>>(
        sqh, sql, Hdim, Hdim, 0, wnh, wnl, NERH, 0, nerb1, 1, nullptr, 0, 0, 0,
        nerW2, nullptr, out, nullptr, 128, 1, NERH);
    cudaEventRecord(evNER, sNER);

    // --- index build chain ---
    k_init0<<<(Ndim+255)/256, 256, 0, sIDX>>>();
    cudaEventRecord(evZERO, sIDX);
    k_count<<<(ETOT+Pdim+255)/256, 256, 0, sIDX>>>(ei, pidx);
    k_scan<<<2, 1024, 0, sIDX>>>();
    k_scatter<<<(ETOT+Pdim+255)/256, 256, 0, sIDX>>>(ei, pidx);
    cudaEventRecord(evIDX, sIDX);

    // --- weight splits ---
    SPLIT(sWSP, W1, w1h, w1l, Hdim*F1);
    cudaEventRecord(evW1, sWSP);
    k_split_padW2<<<F1*128/256, 256, 0, sWSP>>>(W2, w2h, w2l);
    cudaEventRecord(evW2, sWSP);
    SPLIT(sWSP, relW1, wrh, wrl, 12*C2*RHID);
    cudaEventRecord(evREL, sWSP);

    // --- main GAT chain ---
    k_span_pool<<<Ndim, 192>>>(seq, est, elen, ebat, x0h, x0l);
    cudaStreamWaitEvent(0, evW1, 0);
    cudaStreamWaitEvent(0, evZERO, 0);
    k_hmma<1><<<dim3(F1/128, Ndim/128, 1), 256, HMMA_SMEM>>>(
        x0h, x0l, Hdim, Hdim, 0, w1h, w1l, F1, 0, nullptr, 0, h1p, F1, 0, 0,
        a_src1, a_dst1, es1p, ed1p, C1, H1, F1);
    cudaStreamWaitEvent(0, evIDX, 0);
    k_gat_agg<H1, C1, F1, true, true><<<Ndim, 128>>>(h1p, es1p, ed1p, b1, nullptr, o1h, o1l);
    cudaStreamWaitEvent(0, evW2, 0);
    k_hmma<1><<<dim3(1, Ndim/128, 2), 256, HMMA_SMEM>>>(
        o1h, o1l, F1, 256, 256, w2h, w2l, 128, (long)256*128, nullptr, 0,
        h2pp, 128, 0, 1,
        a_src2, a_dst2, es2p, ed2p, C2, 1, C2);
    k_gat_agg<1, C2, 128, false, true><<<Ndim, 32>>>(h2pp, es2p, ed2p, b2, nullptr, x2h, x2l);
    cudaStreamWaitEvent(0, evREL, 0);
    k_hmma<0><<<dim3(RHID/128, Ndim/128, 12), 256, HMMA_SMEM>>>(
        x2h, x2l, C2, C2, 0, wrh, wrl, RHID, (long)C2*RHID, nullptr, 0,
        tbp, RHID, (long)Ndim*RHID, 0,
        nullptr, nullptr, nullptr, nullptr, 128, 1, RHID);
    k_rel_g<<<dim3(Ndim/8, NREL), 256>>>(psortedp, psortjp,
        relb1, ln_g, ln_b, relW2, relb2, out + NER_OUT_ELEMS);

    // join
    cudaStreamWaitEvent(0, evNER, 0);
    #undef SPLIT
}

// round 14
// speedup vs baseline: 1.7058x; 1.2265x over previous
#include <cuda_runtime.h>
#include <cuda_bf16.h>
#include <math.h>
#include <stdint.h>

// ---------------- problem constants ----------------
#define Bdim 32
#define Sdim 512
#define Hdim 768
#define Ndim 4096
#define Edim 131072
#define Pdim 65536
#define ETOT (Edim + Ndim)
#define H1 4
#define C1 128
#define F1 (H1*C1)               // 512
#define C2 64
#define NREL 6
#define RHID 256
#define NERH 256
#define NERL 9
#define SLOPE 0.2f
#define LNEPS 1e-5f
#define NER_OUT_ELEMS (Bdim*Sdim*NERL)
#define NERROWS (Bdim*Sdim)      // 16384

// ---------------- device scratch ----------------
__device__ float g_h1[Ndim*F1];
__device__ float g_h2p[Ndim*128];
__device__ float g_es1[Ndim*H1], g_ed1[Ndim*H1];
__device__ float g_es2[Ndim],    g_ed2[Ndim];
__device__ int   g_deg[Ndim], g_cursor[Ndim], g_rowstart[Ndim+1];
__device__ int   g_csr[ETOT];
__device__ int   g_pdeg[Ndim], g_pcur[Ndim], g_prow[Ndim+1];
__device__ int   g_psorted[Pdim];
__device__ int   g_psortj[Pdim];
__device__ float g_tb[12*Ndim*RHID];
__device__ __nv_bfloat16 g_sqh[NERROWS*Hdim], g_sql[NERROWS*Hdim];
__device__ __nv_bfloat16 g_x0h[Ndim*Hdim],    g_x0l[Ndim*Hdim];
__device__ __nv_bfloat16 g_o1h[Ndim*F1],      g_o1l[Ndim*F1];
__device__ __nv_bfloat16 g_x2h[Ndim*C2],      g_x2l[Ndim*C2];
__device__ __nv_bfloat16 g_w1h[Hdim*F1],      g_w1l[Hdim*F1];
__device__ __nv_bfloat16 g_wnh[Hdim*NERH],    g_wnl[Hdim*NERH];
__device__ __nv_bfloat16 g_w2h[F1*128],       g_w2l[F1*128];
__device__ __nv_bfloat16 g_wrh[12*C2*RHID],   g_wrl[12*C2*RHID];

// ---------------- helpers ----------------
__device__ __forceinline__ float warpSum(float v){
    #pragma unroll
    for(int o=16;o;o>>=1) v += __shfl_xor_sync(0xffffffffu, v, o);
    return v;
}
__device__ __forceinline__ float quadSum(float v){
    v += __shfl_xor_sync(0xffffffffu, v, 1);
    v += __shfl_xor_sync(0xffffffffu, v, 2);
    return v;
}
__device__ __forceinline__ uint32_t smem_u32(const void* p){
    uint32_t a;
    asm("{ .reg .u64 t; cvta.to.shared.u64 t, %1; cvt.u32.u64 %0, t; }" : "=r"(a) : "l"(p));
    return a;
}
__device__ __forceinline__ unsigned pack_bf2(__nv_bfloat16 a, __nv_bfloat16 b){
    __nv_bfloat162 t; t.x = a; t.y = b;
    return *reinterpret_cast<unsigned*>(&t);
}
__device__ __forceinline__ void cp16(uint32_t dst, const void* src){
    asm volatile("cp.async.ca.shared.global [%0], [%1], 16;" :: "r"(dst), "l"(src) : "memory");
}
__device__ __forceinline__ void ldsm4(uint32_t* r, uint32_t addr){
    asm volatile("ldmatrix.sync.aligned.m8n8.x4.shared.b16 {%0,%1,%2,%3}, [%4];"
        : "=r"(r[0]), "=r"(r[1]), "=r"(r[2]), "=r"(r[3]) : "r"(addr));
}
__device__ __forceinline__ void ldsm4t(uint32_t* r, uint32_t addr){
    asm volatile("ldmatrix.sync.aligned.m8n8.x4.trans.shared.b16 {%0,%1,%2,%3}, [%4];"
        : "=r"(r[0]), "=r"(r[1]), "=r"(r[2]), "=r"(r[3]) : "r"(addr));
}
__device__ __forceinline__ void mma16816(float* d, const uint32_t* a, uint32_t b0, uint32_t b1){
    asm volatile(
        "mma.sync.aligned.m16n8k16.row.col.f32.bf16.bf16.f32 "
        "{%0,%1,%2,%3}, {%4,%5,%6,%7}, {%8,%9}, {%0,%1,%2,%3};"
        : "+f"(d[0]), "+f"(d[1]), "+f"(d[2]), "+f"(d[3])
        : "r"(a[0]), "r"(a[1]), "r"(a[2]), "r"(a[3]), "r"(b0), "r"(b1));
}

// ---------------- split fp32 -> bf16 hi/lo planes ----------------
__global__ void k_split(const float4* __restrict__ in, uint2* __restrict__ hi,
                        uint2* __restrict__ lo, int n4){
    int i = blockIdx.x*blockDim.x + threadIdx.x;
    if(i >= n4) return;
    float4 v = in[i];
    __nv_bfloat16 h0=__float2bfloat16(v.x), h1=__float2bfloat16(v.y);
    __nv_bfloat16 h2=__float2bfloat16(v.z), h3=__float2bfloat16(v.w);
    __nv_bfloat16 l0=__float2bfloat16(v.x-__bfloat162float(h0));
    __nv_bfloat16 l1=__float2bfloat16(v.y-__bfloat162float(h1));
    __nv_bfloat16 l2=__float2bfloat16(v.z-__bfloat162float(h2));
    __nv_bfloat16 l3=__float2bfloat16(v.w-__bfloat162float(h3));
    hi[i] = make_uint2(pack_bf2(h0,h1), pack_bf2(h2,h3));
    lo[i] = make_uint2(pack_bf2(l0,l1), pack_bf2(l2,l3));
}

__global__ void k_split_padW2(const float* __restrict__ W2,
                              __nv_bfloat16* __restrict__ hi, __nv_bfloat16* __restrict__ lo){
    int idx = blockIdx.x*256 + threadIdx.x;
    int k = idx >> 7, c = idx & 127;
    float v = (c < C2) ? W2[k*C2 + c] : 0.f;
    __nv_bfloat16 h = __float2bfloat16(v);
    __nv_bfloat16 l = __float2bfloat16(v - __bfloat162float(h));
    hi[idx] = h; lo[idx] = l;
}

// ---------------- split-bf16 HMMA GEMM with fused epilogues ----------------
// 256 threads, 8 warps, warp tile 64x32, CTA tile 128x128
// EPI: 0 = store only; 1 = store/atomic + attention coef atomics; 2 = NER stage2
#define SA 40
#define SB 136
#define A_PL (128*SA*2)
#define B_PL (32*SB*2)
#define BOFF (2*A_PL)
#define STAGE_SZ (BOFF + 2*B_PL)
#define PIPE_SZ (2*STAGE_SZ)
#define HMMA_SMEM (PIPE_SZ + 4608)
template<int EPI>
__global__ void __launch_bounds__(256) k_hmma(
        const __nv_bfloat16* __restrict__ aHi, const __nv_bfloat16* __restrict__ aLo,
        int lda, int K, long aStrideZ,
        const __nv_bfloat16* __restrict__ wHi, const __nv_bfloat16* __restrict__ wLo, int N,
        long wStrideZ, const float* __restrict__ bias, int reluFlag,
        float* __restrict__ C, int ldc, long cStrideZ, int atomicC,
        const float* __restrict__ p1, const float* __restrict__ p2,
        float* __restrict__ q1, float* __restrict__ q2,
        int headC, int nheads, int validN){
    extern __shared__ char sm_buf[];
    int tid = threadIdx.x, lane = tid & 31, warp = tid >> 5;
    int wm = warp & 1, wn = warp >> 1;
    int grp = lane >> 3, rr = lane & 7;
    int arow = rr + (grp & 1)*8;
    int acol = (grp >> 1)*8;

    int n0 = blockIdx.x*128, m0 = blockIdx.y*128, z = blockIdx.z;
    const __nv_bfloat16* azh = aHi + (size_t)z*aStrideZ;
    const __nv_bfloat16* azl = aLo + (size_t)z*aStrideZ;
    const __nv_bfloat16* wzh = wHi + (size_t)z*wStrideZ;
    const __nv_bfloat16* wzl = wLo + (size_t)z*wStrideZ;
    int nc = K >> 5;

    float* sx = (float*)(sm_buf + PIPE_SZ);
    if(EPI == 1){
        if(tid < 128){
            int n = n0 + tid;
            sx[tid]     = (n < validN) ? p1[n] : 0.f;
            sx[128+tid] = (n < validN) ? p2[n] : 0.f;
        }
    }else if(EPI == 2){
        for(int j=tid; j<128*NERL; j+=256)
            sx[j] = p1[(size_t)(n0 + j/NERL)*NERL + (j%NERL)];
    }

    float acc[4][4][4];
    #pragma unroll
    for(int a=0;a<4;a++)
        #pragma unroll
        for(int b=0;b<4;b++)
            #pragma unroll
            for(int c=0;c<4;c++) acc[a][b][c] = 0.f;

    uint32_t sb0 = smem_u32(sm_buf);

    #define ISSUE(kc, st) do{                                                        \
        uint32_t sb = sb0 + (st)*STAGE_SZ;                                           \
        _Pragma("unroll")                                                            \
        for(int i=0;i<2;i++){                                                        \
            int idx = tid + i*256; int row = idx >> 2, k8 = idx & 3;                 \
            size_t go = (size_t)(m0+row)*lda + (kc)*32 + k8*8;                       \
            uint32_t d = sb + row*80 + k8*16;                                        \
            cp16(d,        azh + go);                                                \
            cp16(d + A_PL, azl + go);                                                \
        }                                                                            \
        _Pragma("unroll")                                                            \
        for(int i=0;i<2;i++){                                                        \
            int idx = tid + i*256; int kr = idx >> 4, ncol = idx & 15;               \
            size_t go = (size_t)((kc)*32 + kr)*N + n0 + ncol*8;                      \
            uint32_t d = sb + BOFF + kr*272 + ncol*16;                               \
            cp16(d,        wzh + go);                                                \
            cp16(d + B_PL, wzl + go);                                                \
        }                                                                            \
        asm volatile("cp.async.commit_group;" ::: "memory");                         \
    }while(0)

    ISSUE(0, 0);
    for(int kc=0; kc<nc; kc++){
        if(kc+1 < nc){
            ISSUE(kc+1, (kc+1)&1);
            asm volatile("cp.async.wait_group 1;" ::: "memory");
        }else{
            asm volatile("cp.async.wait_group 0;" ::: "memory");
        }
        __syncthreads();
        uint32_t sb = sb0 + (kc&1)*STAGE_SZ;
        uint32_t aBase = sb + ((wm*64 + arow)*SA + acol)*2;
        uint32_t bBase = sb + BOFF + (arow*SB + wn*32 + acol)*2;
        #pragma unroll
        for(int kk=0; kk<2; kk++){
            uint32_t bfr[2][2][4];
            #pragma unroll
            for(int pr=0; pr<2; pr++){
                uint32_t bd = bBase + kk*(16*SB*2) + pr*32;
                ldsm4t(bfr[pr][0], bd);
                ldsm4t(bfr[pr][1], bd + B_PL);
            }
            #pragma unroll
            for(int mt=0; mt<4; mt++){
                uint32_t af[2][4];
                uint32_t ad = aBase + mt*(16*SA*2) + kk*32;
                ldsm4(af[0], ad);
                ldsm4(af[1], ad + A_PL);
                #pragma unroll
                for(int nt=0; nt<4; nt++){
                    int pr = nt >> 1, hf = (nt & 1)*2;
                    uint32_t bh0 = bfr[pr][0][hf], bh1 = bfr[pr][0][hf+1];
                    uint32_t bl0 = bfr[pr][1][hf], bl1 = bfr[pr][1][hf+1];
                    mma16816(acc[mt][nt], af[0], bh0, bh1);
                    mma16816(acc[mt][nt], af[0], bl0, bl1);
                    mma16816(acc[mt][nt], af[1], bh0, bh1);
                }
            }
        }
        __syncthreads();
    }
    #undef ISSUE

    // ---- epilogue ----
    float* Cz = C + (size_t)z*cStrideZ;
    int hh = (n0 + wn*32) / headC;
    bool hhok = hh < nheads;
    float bcol[8];
    #pragma unroll
    for(int nt=0; nt<4; nt++){
        int n = n0 + wn*32 + nt*8 + (lane & 3)*2;
        bcol[nt*2]   = bias ? bias[n]   : 0.f;
        bcol[nt*2+1] = bias ? bias[n+1] : 0.f;
    }
    #pragma unroll
    for(int mt=0; mt<4; mt++){
        int mb = m0 + wm*64 + mt*16 + (lane >> 2);
        #pragma unroll
        for(int half=0; half<2; half++){
            int m = mb + half*8;
            float v[8];
            #pragma unroll
            for(int nt=0; nt<4; nt++){
                float a0 = acc[mt][nt][half*2]   + bcol[nt*2];
                float a1 = acc[mt][nt][half*2+1] + bcol[nt*2+1];
                if(reluFlag){ a0 = fmaxf(a0,0.f); a1 = fmaxf(a1,0.f); }
                v[nt*2] = a0; v[nt*2+1] = a1;
                if(EPI != 2){
                    int n = n0 + wn*32 + nt*8 + (lane & 3)*2;
                    if(atomicC){
                        atomicAdd(&Cz[(size_t)m*ldc + n],   a0);
                        atomicAdd(&Cz[(size_t)m*ldc + n+1], a1);
                    }else{
                        *reinterpret_cast<float2*>(Cz + (size_t)m*ldc + n) = make_float2(a0, a1);
                    }
                }
            }
            if(EPI == 1){
                float ps = 0.f, pd = 0.f;
                #pragma unroll
                for(int t=0;t<8;t++){
                    int ln = wn*32 + (t>>1)*8 + (lane&3)*2 + (t&1);
                    ps += v[t]*sx[ln];
                    pd += v[t]*sx[128+ln];
                }
                ps = quadSum(ps); pd = quadSum(pd);
                if((lane&3)==0 && hhok){
                    atomicAdd(&q1[m*nheads + hh], ps);
                    atomicAdd(&q2[m*nheads + hh], pd);
                }
            }else if(EPI == 2){
                float pc[NERL];
                #pragma unroll
                for(int c=0;c<NERL;c++) pc[c] = 0.f;
                #pragma unroll
                for(int t=0;t<8;t++){
                    int ln = wn*32 + (t>>1)*8 + (lane&3)*2 + (t&1);
                    #pragma unroll
                    for(int c=0;c<NERL;c++) pc[c] += v[t]*sx[ln*NERL + c];
                }
                #pragma unroll
                for(int c=0;c<NERL;c++){
                    float s = quadSum(pc[c]);
                    if((lane&3)==0) atomicAdd(&q1[(size_t)m*NERL + c], s);
                }
            }
        }
    }
}

// ---------------- entity span mean pooling -> bf16 hi/lo planes ----------------
__global__ void k_span_pool(const float* __restrict__ seq,
                            const int* __restrict__ est, const int* __restrict__ elen,
                            const int* __restrict__ ebat,
                            __nv_bfloat16* __restrict__ xh, __nv_bfloat16* __restrict__ xl){
    int n = blockIdx.x;
    int b = ebat[n], st = est[n], len = elen[n];
    const float* base = seq + ((size_t)b*Sdim + st)*Hdim + threadIdx.x*4;
    float4 acc = make_float4(0.f,0.f,0.f,0.f);
    for(int r=0; r<=len; r++){
        float4 t = *reinterpret_cast<const float4*>(base + (size_t)r*Hdim);
        acc.x += t.x; acc.y += t.y; acc.z += t.z; acc.w += t.w;
    }
    float inv = 1.0f/(float)(len+1);
    acc.x*=inv; acc.y*=inv; acc.z*=inv; acc.w*=inv;
    __nv_bfloat16 h0=__float2bfloat16(acc.x), h1=__float2bfloat16(acc.y);
    __nv_bfloat16 h2=__float2bfloat16(acc.z), h3=__float2bfloat16(acc.w);
    __nv_bfloat16 l0=__float2bfloat16(acc.x-__bfloat162float(h0));
    __nv_bfloat16 l1=__float2bfloat16(acc.y-__bfloat162float(h1));
    __nv_bfloat16 l2=__float2bfloat16(acc.z-__bfloat162float(h2));
    __nv_bfloat16 l3=__float2bfloat16(acc.w-__bfloat162float(h3));
    size_t o = (size_t)n*Hdim + threadIdx.x*4;
    *reinterpret_cast<uint2*>(&xh[o]) = make_uint2(pack_bf2(h0,h1), pack_bf2(h2,h3));
    *reinterpret_cast<uint2*>(&xl[o]) = make_uint2(pack_bf2(l0,l1), pack_bf2(l2,l3));
}

// ---------------- init kernels ----------------
__global__ void k_init0(){
    int i = blockIdx.x*blockDim.x + threadIdx.x;
    if(i >= Ndim) return;
    g_deg[i]=0; g_cursor[i]=0; g_pdeg[i]=0; g_pcur[i]=0;
    g_es2[i]=0.f; g_ed2[i]=0.f;
    #pragma unroll
    for(int h=0;h<H1;h++){ g_es1[i*H1+h]=0.f; g_ed1[i*H1+h]=0.f; }
    float4 z4 = make_float4(0.f,0.f,0.f,0.f);
    float4* h2 = reinterpret_cast<float4*>(&g_h2p[(size_t)i*128]);
    #pragma unroll
    for(int j=0;j<32;j++) h2[j] = z4;
}
__global__ void k_out_init(const float* __restrict__ b2, float* __restrict__ out){
    int i = blockIdx.x*blockDim.x + threadIdx.x;
    if(i < NER_OUT_ELEMS) out[i] = b2[i % NERL];
}

// ---------------- merged CSR + pair-sort build ----------------
__global__ void k_count(const int* __restrict__ ei, const int* __restrict__ pidx){
    int idx = blockIdx.x*blockDim.x + threadIdx.x;
    if(idx < ETOT){
        int dst = (idx < Edim) ? ei[Edim + idx] : (idx - Edim);
        atomicAdd(&g_deg[dst], 1);
    }else if(idx < ETOT + Pdim){
        atomicAdd(&g_pdeg[pidx[(idx - ETOT)*2]], 1);
    }
}
__global__ void k_scan(){
    __shared__ int s[1024];
    const int* deg = (blockIdx.x == 0) ? g_deg : g_pdeg;
    int* rowstart  = (blockIdx.x == 0) ? g_rowstart : g_prow;
    int t = threadIdx.x;
    int v0 = deg[t*4+0], v1 = deg[t*4+1], v2 = deg[t*4+2], v3 = deg[t*4+3];
    int c0 = v0, c1 = c0+v1, c2 = c1+v2, c3 = c2+v3;
    s[t] = c3;
    __syncthreads();
    for(int off=1; off<1024; off<<=1){
        int x = (t >= off) ? s[t-off] : 0;
        __syncthreads();
        s[t] += x;
        __syncthreads();
    }
    int excl = s[t] - c3;
    rowstart[t*4+1] = excl + c0;
    rowstart[t*4+2] = excl + c1;
    rowstart[t*4+3] = excl + c2;
    rowstart[t*4+4] = excl + c3;
    if(t==0) rowstart[0] = 0;
}
__global__ void k_scatter(const int* __restrict__ ei, const int* __restrict__ pidx){
    int idx = blockIdx.x*blockDim.x + threadIdx.x;
    if(idx < ETOT){
        int src, dst;
        if(idx < Edim){ src = ei[idx]; dst = ei[Edim + idx]; }
        else          { src = idx - Edim; dst = src; }
        int pos = g_rowstart[dst] + atomicAdd(&g_cursor[dst], 1);
        g_csr[pos] = src;
    }else if(idx < ETOT + Pdim){
        int p = idx - ETOT;
        int i = pidx[p*2];
        int pos = g_prow[i] + atomicAdd(&g_pcur[i], 1);
        g_psorted[pos] = p;
        g_psortj[pos]  = pidx[p*2+1];
    }
}

// ---------------- GAT softmax + aggregation (2-pass; logits small) ----------------
template<int HEADS,int C,int LD,bool RELU,bool SPLIT>
__global__ void k_gat_agg(const float* __restrict__ h,
                          const float* __restrict__ es, const float* __restrict__ ed,
                          const float* __restrict__ bias, float* __restrict__ out,
                          __nv_bfloat16* __restrict__ outH, __nv_bfloat16* __restrict__ outL){
    const int F = HEADS*C;
    int d = blockIdx.x;
    int hh = threadIdx.x >> 5, lane = threadIdx.x & 31;
    int rs = g_rowstart[d], re = g_rowstart[d+1];
    float edv = ed[d*HEADS + hh];

    float den = 0.f;
    for(int e=rs+lane; e<re; e+=32){
        int s = g_csr[e];
        float t = es[s*HEADS+hh] + edv;
        t = (t > 0.f) ? t : SLOPE*t;
        den += __expf(t);
    }
    den = warpSum(den);
    float inv = 1.0f/den;

    float acc[C/32];
    #pragma unroll
    for(int i=0;i<C/32;i++) acc[i]=0.f;

    for(int e=rs; e<re; e++){
        int s = g_csr[e];
        float t = es[s*HEADS+hh] + edv;
        t = (t > 0.f) ? t : SLOPE*t;
        float w = __expf(t)*inv;
        const float* hp = h + (size_t)s*LD + hh*C + lane;
        #pragma unroll
        for(int i=0;i<C/32;i++) acc[i] += w*hp[32*i];
    }
    #pragma unroll
    for(int i=0;i<C/32;i++){
        float v = acc[i] + bias[hh*C + lane + 32*i];
        if(RELU) v = fmaxf(v, 0.f);
        size_t o = (size_t)d*F + hh*C + lane + 32*i;
        if(SPLIT){
            __nv_bfloat16 hb = __float2bfloat16(v);
            outH[o] = hb;
            outL[o] = __float2bfloat16(v - __bfloat162float(hb));
        }else{
            out[o] = v;
        }
    }
}

// ---------------- fused relation head: warp-per-left-entity, r = blockIdx.y ----------------
__global__ void k_rel_g(const int* __restrict__ psorted, const int* __restrict__ psortj,
                        const float* __restrict__ relb1, const float* __restrict__ lng,
                        const float* __restrict__ lnb, const float* __restrict__ relW2,
                        const float* __restrict__ relb2, float* __restrict__ out){
    __shared__ float sb1[256], sg[256], sbb[256], sw2[256];
    int r = blockIdx.y;
    int tid = threadIdx.x;
    sb1[tid] = relb1[r*256+tid];
    sg[tid]  = lng[r*256+tid];
    sbb[tid] = lnb[r*256+tid];
    sw2[tid] = relW2[r*256+tid];
    __syncthreads();

    int w = tid >> 5, lane = tid & 31;
    int i = blockIdx.x*8 + w;
    int rs = g_prow[i], re = g_prow[i+1];
    if(rs == re) return;
    float rb2 = relb2[r];

    float ti[8];
    const float* tip = g_tb + ((size_t)(r*2)*Ndim + i)*RHID;
    #pragma unroll
    for(int t=0;t<8;t++) ti[t] = tip[lane + 32*t];

    for(int idx = rs; idx < re; idx++){
        int p = psorted[idx];
        int j = psortj[idx];
        const float* tj = g_tb + ((size_t)(r*2+1)*Ndim + j)*RHID;
        float v[8]; float s1 = 0.f, s2 = 0.f;
        #pragma unroll
        for(int t=0;t<8;t++){
            int k = lane + 32*t;
            float x = ti[t] + tj[k] + sb1[k];
            v[t] = x; s1 += x; s2 += x*x;
        }
        // interleaved dual reduction (ILP-2)
        #pragma unroll
        for(int o=16;o;o>>=1){
            s1 += __shfl_xor_sync(0xffffffffu, s1, o);
            s2 += __shfl_xor_sync(0xffffffffu, s2, o);
        }
        float mu  = s1 * (1.0f/256.0f);
        float var = s2 * (1.0f/256.0f) - mu*mu;
        float rinv = rsqrtf(var + LNEPS);
        float acc = 0.f;
        #pragma unroll
        for(int t=0;t<8;t++){
            int k = lane + 32*t;
            float x = (v[t]-mu)*rinv*sg[k] + sbb[k];
            x = fmaxf(x, 0.f);
            acc += x * sw2[k];
        }
        acc = warpSum(acc);
        if(lane==0) out[(size_t)r*Pdim + p] = acc + rb2;
    }
}

// ---------------- launch ----------------
extern "C" void kernel_launch(void* const* d_in, const int* in_sizes, int n_in,
                              void* d_out, int out_size){
    const float* seq     = (const float*)d_in[0];
    const int*   est     = (const int*)  d_in[1];
    const int*   elen    = (const int*)  d_in[2];
    const int*   ebat    = (const int*)  d_in[3];
    const int*   ei      = (const int*)  d_in[4];
    const int*   pidx    = (const int*)  d_in[5];
    const float* W1      = (const float*)d_in[6];
    const float* a_src1  = (const float*)d_in[7];
    const float* a_dst1  = (const float*)d_in[8];
    const float* b1      = (const float*)d_in[9];
    const float* W2      = (const float*)d_in[10];
    const float* a_src2  = (const float*)d_in[11];
    const float* a_dst2  = (const float*)d_in[12];
    const float* b2      = (const float*)d_in[13];
    const float* relW1   = (const float*)d_in[14];
    const float* relb1   = (const float*)d_in[15];
    const float* ln_g    = (const float*)d_in[16];
    const float* ln_b    = (const float*)d_in[17];
    const float* relW2   = (const float*)d_in[18];
    const float* relb2   = (const float*)d_in[19];
    const float* nerW1   = (const float*)d_in[20];
    const float* nerb1   = (const float*)d_in[21];
    const float* nerW2   = (const float*)d_in[22];
    const float* nerb2   = (const float*)d_in[23];
    float* out = (float*)d_out;

    float *h1p, *h2pp, *es1p, *ed1p, *es2p, *ed2p, *tbp;
    int *psortedp, *psortjp;
    cudaGetSymbolAddress((void**)&h1p,  g_h1);
    cudaGetSymbolAddress((void**)&h2pp, g_h2p);
    cudaGetSymbolAddress((void**)&es1p, g_es1);
    cudaGetSymbolAddress((void**)&ed1p, g_ed1);
    cudaGetSymbolAddress((void**)&es2p, g_es2);
    cudaGetSymbolAddress((void**)&ed2p, g_ed2);
    cudaGetSymbolAddress((void**)&tbp,  g_tb);
    cudaGetSymbolAddress((void**)&psortedp, g_psorted);
    cudaGetSymbolAddress((void**)&psortjp,  g_psortj);
    __nv_bfloat16 *sqh,*sql,*x0h,*x0l,*o1h,*o1l,*x2h,*x2l,*w1h,*w1l,*wnh,*wnl,*w2h,*w2l,*wrh,*wrl;
    cudaGetSymbolAddress((void**)&sqh, g_sqh); cudaGetSymbolAddress((void**)&sql, g_sql);
    cudaGetSymbolAddress((void**)&x0h, g_x0h); cudaGetSymbolAddress((void**)&x0l, g_x0l);
    cudaGetSymbolAddress((void**)&o1h, g_o1h); cudaGetSymbolAddress((void**)&o1l, g_o1l);
    cudaGetSymbolAddress((void**)&x2h, g_x2h); cudaGetSymbolAddress((void**)&x2l, g_x2l);
    cudaGetSymbolAddress((void**)&w1h, g_w1h); cudaGetSymbolAddress((void**)&w1l, g_w1l);
    cudaGetSymbolAddress((void**)&wnh, g_wnh); cudaGetSymbolAddress((void**)&wnl, g_wnl);
    cudaGetSymbolAddress((void**)&w2h, g_w2h); cudaGetSymbolAddress((void**)&w2l, g_w2l);
    cudaGetSymbolAddress((void**)&wrh, g_wrh); cudaGetSymbolAddress((void**)&wrl, g_wrl);

    static cudaStream_t sNER = nullptr, sIDX = nullptr, sWSP = nullptr;
    static cudaEvent_t evRoot, evNER, evIDX, evZERO, evW1, evW2, evREL;
    if(sNER == nullptr){
        cudaStreamCreateWithFlags(&sNER, cudaStreamNonBlocking);
        cudaStreamCreateWithFlags(&sIDX, cudaStreamNonBlocking);
        cudaStreamCreateWithFlags(&sWSP, cudaStreamNonBlocking);
        cudaEventCreateWithFlags(&evRoot, cudaEventDisableTiming);
        cudaEventCreateWithFlags(&evNER,  cudaEventDisableTiming);
        cudaEventCreateWithFlags(&evIDX,  cudaEventDisableTiming);
        cudaEventCreateWithFlags(&evZERO, cudaEventDisableTiming);
        cudaEventCreateWithFlags(&evW1,   cudaEventDisableTiming);
        cudaEventCreateWithFlags(&evW2,   cudaEventDisableTiming);
        cudaEventCreateWithFlags(&evREL,  cudaEventDisableTiming);
        cudaFuncSetAttribute(k_hmma<0>, cudaFuncAttributeMaxDynamicSharedMemorySize, HMMA_SMEM);
        cudaFuncSetAttribute(k_hmma<1>, cudaFuncAttributeMaxDynamicSharedMemorySize, HMMA_SMEM);
        cudaFuncSetAttribute(k_hmma<2>, cudaFuncAttributeMaxDynamicSharedMemorySize, HMMA_SMEM);
    }

    #define SPLIT(st, src, dh, dl, cnt) \
        k_split<<<((cnt)/4 + 255)/256, 256, 0, st>>>((const float4*)(src), (uint2*)(dh), (uint2*)(dl), (cnt)/4)

    // fork
    cudaEventRecord(evRoot, 0);
    cudaStreamWaitEvent(sNER, evRoot, 0);
    cudaStreamWaitEvent(sIDX, evRoot, 0);
    cudaStreamWaitEvent(sWSP, evRoot, 0);

    // --- NER chain ---
    k_out_init<<<(NER_OUT_ELEMS+255)/256, 256, 0, sNER>>>(nerb2, out);
    SPLIT(sNER, nerW1, wnh, wnl, Hdim*NERH);
    SPLIT(sNER, seq,   sqh, sql, NERROWS*Hdim);
    k_hmma<2><<<dim3(NERH/128, NERROWS/128, 1), 256, HMMA_SMEM, sNER>>>(
        sqh, sql, Hdim, Hdim, 0, wnh, wnl, NERH, 0, nerb1, 1, nullptr, 0, 0, 0,
        nerW2, nullptr, out, nullptr, 128, 1, NERH);
    cudaEventRecord(evNER, sNER);

    // --- index build chain ---
    k_init0<<<(Ndim+255)/256, 256, 0, sIDX>>>();
    cudaEventRecord(evZERO, sIDX);
    k_count<<<(ETOT+Pdim+255)/256, 256, 0, sIDX>>>(ei, pidx);
    k_scan<<<2, 1024, 0, sIDX>>>();
    k_scatter<<<(ETOT+Pdim+255)/256, 256, 0, sIDX>>>(ei, pidx);
    cudaEventRecord(evIDX, sIDX);

    // --- weight splits ---
    SPLIT(sWSP, W1, w1h, w1l, Hdim*F1);
    cudaEventRecord(evW1, sWSP);
    k_split_padW2<<<F1*128/256, 256, 0, sWSP>>>(W2, w2h, w2l);
    cudaEventRecord(evW2, sWSP);
    SPLIT(sWSP, relW1, wrh, wrl, 12*C2*RHID);
    cudaEventRecord(evREL, sWSP);

    // --- main GAT chain ---
    k_span_pool<<<Ndim, 192>>>(seq, est, elen, ebat, x0h, x0l);
    cudaStreamWaitEvent(0, evW1, 0);
    cudaStreamWaitEvent(0, evZERO, 0);
    k_hmma<1><<<dim3(F1/128, Ndim/128, 1), 256, HMMA_SMEM>>>(
        x0h, x0l, Hdim, Hdim, 0, w1h, w1l, F1, 0, nullptr, 0, h1p, F1, 0, 0,
        a_src1, a_dst1, es1p, ed1p, C1, H1, F1);
    cudaStreamWaitEvent(0, evIDX, 0);
    k_gat_agg<H1, C1, F1, true, true><<<Ndim, 128>>>(h1p, es1p, ed1p, b1, nullptr, o1h, o1l);
    cudaStreamWaitEvent(0, evW2, 0);
    k_hmma<1><<<dim3(1, Ndim/128, 2), 256, HMMA_SMEM>>>(
        o1h, o1l, F1, 256, 256, w2h, w2l, 128, (long)256*128, nullptr, 0,
        h2pp, 128, 0, 1,
        a_src2, a_dst2, es2p, ed2p, C2, 1, C2);
    k_gat_agg<1, C2, 128, false, true><<<Ndim, 32>>>(h2pp, es2p, ed2p, b2, nullptr, x2h, x2l);
    cudaStreamWaitEvent(0, evREL, 0);
    k_hmma<0><<<dim3(RHID/128, Ndim/128, 12), 256, HMMA_SMEM>>>(
        x2h, x2l, C2, C2, 0, wrh, wrl, RHID, (long)C2*RHID, nullptr, 0,
        tbp, RHID, (long)Ndim*RHID, 0,
        nullptr, nullptr, nullptr, nullptr, 128, 1, RHID);
    k_rel_g<<<dim3(Ndim/8, NREL), 256>>>(psortedp, psortjp,
        relb1, ln_g, ln_b, relW2, relb2, out + NER_OUT_ELEMS);

    // join
    cudaStreamWaitEvent(0, evNER, 0);
    #undef SPLIT
}

// round 15
// speedup vs baseline: 1.8113x; 1.0619x over previous
#include <cuda_runtime.h>
#include <cuda_bf16.h>
#include <math.h>
#include <stdint.h>

// ---------------- problem constants ----------------
#define Bdim 32
#define Sdim 512
#define Hdim 768
#define Ndim 4096
#define Edim 131072
#define Pdim 65536
#define ETOT (Edim + Ndim)
#define H1 4
#define C1 128
#define F1 (H1*C1)               // 512
#define C2 64
#define NREL 6
#define RHID 256
#define NERH 256
#define NERL 9
#define SLOPE 0.2f
#define LNEPS 1e-5f
#define NER_OUT_ELEMS (Bdim*Sdim*NERL)
#define NERROWS (Bdim*Sdim)      // 16384

// ---------------- device scratch ----------------
__device__ float g_h1[Ndim*F1];
__device__ float g_h2p[Ndim*128];
__device__ float g_es1[Ndim*H1], g_ed1[Ndim*H1];
__device__ float g_es2[Ndim],    g_ed2[Ndim];
__device__ int   g_deg[Ndim], g_cursor[Ndim], g_rowstart[Ndim+1];
__device__ int   g_csr[ETOT];
__device__ int   g_pdeg[Ndim], g_pcur[Ndim], g_prow[Ndim+1];
__device__ int   g_psorted[Pdim];
__device__ int   g_psortj[Pdim];
__device__ float g_tb[12*Ndim*RHID];
__device__ __nv_bfloat16 g_sqh[NERROWS*Hdim], g_sql[NERROWS*Hdim];
__device__ __nv_bfloat16 g_x0h[Ndim*Hdim],    g_x0l[Ndim*Hdim];
__device__ __nv_bfloat16 g_o1h[Ndim*F1],      g_o1l[Ndim*F1];
__device__ __nv_bfloat16 g_x2h[Ndim*C2],      g_x2l[Ndim*C2];
__device__ __nv_bfloat16 g_w1h[Hdim*F1],      g_w1l[Hdim*F1];
__device__ __nv_bfloat16 g_wnh[Hdim*NERH],    g_wnl[Hdim*NERH];
__device__ __nv_bfloat16 g_w2h[F1*128],       g_w2l[F1*128];
__device__ __nv_bfloat16 g_wrh[12*C2*RHID],   g_wrl[12*C2*RHID];

// ---------------- helpers ----------------
__device__ __forceinline__ float warpSum(float v){
    #pragma unroll
    for(int o=16;o;o>>=1) v += __shfl_xor_sync(0xffffffffu, v, o);
    return v;
}
__device__ __forceinline__ float quadSum(float v){
    v += __shfl_xor_sync(0xffffffffu, v, 1);
    v += __shfl_xor_sync(0xffffffffu, v, 2);
    return v;
}
__device__ __forceinline__ uint32_t smem_u32(const void* p){
    uint32_t a;
    asm("{ .reg .u64 t; cvta.to.shared.u64 t, %1; cvt.u32.u64 %0, t; }" : "=r"(a) : "l"(p));
    return a;
}
__device__ __forceinline__ unsigned pack_bf2(__nv_bfloat16 a, __nv_bfloat16 b){
    __nv_bfloat162 t; t.x = a; t.y = b;
    return *reinterpret_cast<unsigned*>(&t);
}
__device__ __forceinline__ void cp16(uint32_t dst, const void* src){
    asm volatile("cp.async.ca.shared.global [%0], [%1], 16;" :: "r"(dst), "l"(src) : "memory");
}
__device__ __forceinline__ void ldsm4(uint32_t* r, uint32_t addr){
    asm volatile("ldmatrix.sync.aligned.m8n8.x4.shared.b16 {%0,%1,%2,%3}, [%4];"
        : "=r"(r[0]), "=r"(r[1]), "=r"(r[2]), "=r"(r[3]) : "r"(addr));
}
__device__ __forceinline__ void ldsm4t(uint32_t* r, uint32_t addr){
    asm volatile("ldmatrix.sync.aligned.m8n8.x4.trans.shared.b16 {%0,%1,%2,%3}, [%4];"
        : "=r"(r[0]), "=r"(r[1]), "=r"(r[2]), "=r"(r[3]) : "r"(addr));
}
__device__ __forceinline__ void mma16816(float* d, const uint32_t* a, uint32_t b0, uint32_t b1){
    asm volatile(
        "mma.sync.aligned.m16n8k16.row.col.f32.bf16.bf16.f32 "
        "{%0,%1,%2,%3}, {%4,%5,%6,%7}, {%8,%9}, {%0,%1,%2,%3};"
        : "+f"(d[0]), "+f"(d[1]), "+f"(d[2]), "+f"(d[3])
        : "r"(a[0]), "r"(a[1]), "r"(a[2]), "r"(a[3]), "r"(b0), "r"(b1));
}

// ---------------- split fp32 -> bf16 hi/lo planes ----------------
__global__ void k_split(const float4* __restrict__ in, uint2* __restrict__ hi,
                        uint2* __restrict__ lo, int n4){
    int i = blockIdx.x*blockDim.x + threadIdx.x;
    if(i >= n4) return;
    float4 v = in[i];
    __nv_bfloat16 h0=__float2bfloat16(v.x), h1=__float2bfloat16(v.y);
    __nv_bfloat16 h2=__float2bfloat16(v.z), h3=__float2bfloat16(v.w);
    __nv_bfloat16 l0=__float2bfloat16(v.x-__bfloat162float(h0));
    __nv_bfloat16 l1=__float2bfloat16(v.y-__bfloat162float(h1));
    __nv_bfloat16 l2=__float2bfloat16(v.z-__bfloat162float(h2));
    __nv_bfloat16 l3=__float2bfloat16(v.w-__bfloat162float(h3));
    hi[i] = make_uint2(pack_bf2(h0,h1), pack_bf2(h2,h3));
    lo[i] = make_uint2(pack_bf2(l0,l1), pack_bf2(l2,l3));
}

__global__ void k_split_padW2(const float* __restrict__ W2,
                              __nv_bfloat16* __restrict__ hi, __nv_bfloat16* __restrict__ lo){
    int idx = blockIdx.x*256 + threadIdx.x;
    int k = idx >> 7, c = idx & 127;
    float v = (c < C2) ? W2[k*C2 + c] : 0.f;
    __nv_bfloat16 h = __float2bfloat16(v);
    __nv_bfloat16 l = __float2bfloat16(v - __bfloat162float(h));
    hi[idx] = h; lo[idx] = l;
}

// ---------------- split-bf16 HMMA GEMM with fused epilogues ----------------
// 256 threads, 8 warps, warp tile 64x32, CTA tile 128x128
// EPI: 0 = store only; 1 = store/atomic + attention coef atomics; 2 = NER stage2
#define SA 40
#define SB 136
#define A_PL (128*SA*2)
#define B_PL (32*SB*2)
#define BOFF (2*A_PL)
#define STAGE_SZ (BOFF + 2*B_PL)
#define PIPE_SZ (2*STAGE_SZ)
#define HMMA_SMEM (PIPE_SZ + 4608)
template<int EPI>
__global__ void __launch_bounds__(256) k_hmma(
        const __nv_bfloat16* __restrict__ aHi, const __nv_bfloat16* __restrict__ aLo,
        int lda, int K, long aStrideZ,
        const __nv_bfloat16* __restrict__ wHi, const __nv_bfloat16* __restrict__ wLo, int N,
        long wStrideZ, const float* __restrict__ bias, int reluFlag,
        float* __restrict__ C, int ldc, long cStrideZ, int atomicC,
        const float* __restrict__ p1, const float* __restrict__ p2,
        float* __restrict__ q1, float* __restrict__ q2,
        int headC, int nheads, int validN){
    extern __shared__ char sm_buf[];
    int tid = threadIdx.x, lane = tid & 31, warp = tid >> 5;
    int wm = warp & 1, wn = warp >> 1;
    int grp = lane >> 3, rr = lane & 7;
    int arow = rr + (grp & 1)*8;
    int acol = (grp >> 1)*8;

    int n0 = blockIdx.x*128, m0 = blockIdx.y*128, z = blockIdx.z;
    const __nv_bfloat16* azh = aHi + (size_t)z*aStrideZ;
    const __nv_bfloat16* azl = aLo + (size_t)z*aStrideZ;
    const __nv_bfloat16* wzh = wHi + (size_t)z*wStrideZ;
    const __nv_bfloat16* wzl = wLo + (size_t)z*wStrideZ;
    int nc = K >> 5;

    float* sx = (float*)(sm_buf + PIPE_SZ);
    if(EPI == 1){
        if(tid < 128){
            int n = n0 + tid;
            sx[tid]     = (n < validN) ? p1[n] : 0.f;
            sx[128+tid] = (n < validN) ? p2[n] : 0.f;
        }
    }else if(EPI == 2){
        for(int j=tid; j<128*NERL; j+=256)
            sx[j] = p1[(size_t)(n0 + j/NERL)*NERL + (j%NERL)];
    }

    float acc[4][4][4];
    #pragma unroll
    for(int a=0;a<4;a++)
        #pragma unroll
        for(int b=0;b<4;b++)
            #pragma unroll
            for(int c=0;c<4;c++) acc[a][b][c] = 0.f;

    uint32_t sb0 = smem_u32(sm_buf);

    #define ISSUE(kc, st) do{                                                        \
        uint32_t sb = sb0 + (st)*STAGE_SZ;                                           \
        _Pragma("unroll")                                                            \
        for(int i=0;i<2;i++){                                                        \
            int idx = tid + i*256; int row = idx >> 2, k8 = idx & 3;                 \
            size_t go = (size_t)(m0+row)*lda + (kc)*32 + k8*8;                       \
            uint32_t d = sb + row*80 + k8*16;                                        \
            cp16(d,        azh + go);                                                \
            cp16(d + A_PL, azl + go);                                                \
        }                                                                            \
        _Pragma("unroll")                                                            \
        for(int i=0;i<2;i++){                                                        \
            int idx = tid + i*256; int kr = idx >> 4, ncol = idx & 15;               \
            size_t go = (size_t)((kc)*32 + kr)*N + n0 + ncol*8;                      \
            uint32_t d = sb + BOFF + kr*272 + ncol*16;                               \
            cp16(d,        wzh + go);                                                \
            cp16(d + B_PL, wzl + go);                                                \
        }                                                                            \
        asm volatile("cp.async.commit_group;" ::: "memory");                         \
    }while(0)

    ISSUE(0, 0);
    for(int kc=0; kc<nc; kc++){
        if(kc+1 < nc){
            ISSUE(kc+1, (kc+1)&1);
            asm volatile("cp.async.wait_group 1;" ::: "memory");
        }else{
            asm volatile("cp.async.wait_group 0;" ::: "memory");
        }
        __syncthreads();
        uint32_t sb = sb0 + (kc&1)*STAGE_SZ;
        uint32_t aBase = sb + ((wm*64 + arow)*SA + acol)*2;
        uint32_t bBase = sb + BOFF + (arow*SB + wn*32 + acol)*2;
        #pragma unroll
        for(int kk=0; kk<2; kk++){
            uint32_t bfr[2][2][4];
            #pragma unroll
            for(int pr=0; pr<2; pr++){
                uint32_t bd = bBase + kk*(16*SB*2) + pr*32;
                ldsm4t(bfr[pr][0], bd);
                ldsm4t(bfr[pr][1], bd + B_PL);
            }
            #pragma unroll
            for(int mt=0; mt<4; mt++){
                uint32_t af[2][4];
                uint32_t ad = aBase + mt*(16*SA*2) + kk*32;
                ldsm4(af[0], ad);
                ldsm4(af[1], ad + A_PL);
                #pragma unroll
                for(int nt=0; nt<4; nt++){
                    int pr = nt >> 1, hf = (nt & 1)*2;
                    uint32_t bh0 = bfr[pr][0][hf], bh1 = bfr[pr][0][hf+1];
                    uint32_t bl0 = bfr[pr][1][hf], bl1 = bfr[pr][1][hf+1];
                    mma16816(acc[mt][nt], af[0], bh0, bh1);
                    mma16816(acc[mt][nt], af[0], bl0, bl1);
                    mma16816(acc[mt][nt], af[1], bh0, bh1);
                }
            }
        }
        __syncthreads();
    }
    #undef ISSUE

    // ---- epilogue ----
    float* Cz = C + (size_t)z*cStrideZ;
    int hh = (n0 + wn*32) / headC;
    bool hhok = hh < nheads;
    float bcol[8];
    #pragma unroll
    for(int nt=0; nt<4; nt++){
        int n = n0 + wn*32 + nt*8 + (lane & 3)*2;
        bcol[nt*2]   = bias ? bias[n]   : 0.f;
        bcol[nt*2+1] = bias ? bias[n+1] : 0.f;
    }
    #pragma unroll
    for(int mt=0; mt<4; mt++){
        int mb = m0 + wm*64 + mt*16 + (lane >> 2);
        #pragma unroll
        for(int half=0; half<2; half++){
            int m = mb + half*8;
            float v[8];
            #pragma unroll
            for(int nt=0; nt<4; nt++){
                float a0 = acc[mt][nt][half*2]   + bcol[nt*2];
                float a1 = acc[mt][nt][half*2+1] + bcol[nt*2+1];
                if(reluFlag){ a0 = fmaxf(a0,0.f); a1 = fmaxf(a1,0.f); }
                v[nt*2] = a0; v[nt*2+1] = a1;
                if(EPI != 2){
                    int n = n0 + wn*32 + nt*8 + (lane & 3)*2;
                    if(atomicC){
                        atomicAdd(&Cz[(size_t)m*ldc + n],   a0);
                        atomicAdd(&Cz[(size_t)m*ldc + n+1], a1);
                    }else{
                        *reinterpret_cast<float2*>(Cz + (size_t)m*ldc + n) = make_float2(a0, a1);
                    }
                }
            }
            if(EPI == 1){
                float ps = 0.f, pd = 0.f;
                #pragma unroll
                for(int t=0;t<8;t++){
                    int ln = wn*32 + (t>>1)*8 + (lane&3)*2 + (t&1);
                    ps += v[t]*sx[ln];
                    pd += v[t]*sx[128+ln];
                }
                ps = quadSum(ps); pd = quadSum(pd);
                if((lane&3)==0 && hhok){
                    atomicAdd(&q1[m*nheads + hh], ps);
                    atomicAdd(&q2[m*nheads + hh], pd);
                }
            }else if(EPI == 2){
                float pc[NERL];
                #pragma unroll
                for(int c=0;c<NERL;c++) pc[c] = 0.f;
                #pragma unroll
                for(int t=0;t<8;t++){
                    int ln = wn*32 + (t>>1)*8 + (lane&3)*2 + (t&1);
                    #pragma unroll
                    for(int c=0;c<NERL;c++) pc[c] += v[t]*sx[ln*NERL + c];
                }
                #pragma unroll
                for(int c=0;c<NERL;c++){
                    float s = quadSum(pc[c]);
                    if((lane&3)==0) atomicAdd(&q1[(size_t)m*NERL + c], s);
                }
            }
        }
    }
}

// ---------------- entity span mean pooling -> bf16 hi/lo planes ----------------
__global__ void k_span_pool(const float* __restrict__ seq,
                            const int* __restrict__ est, const int* __restrict__ elen,
                            const int* __restrict__ ebat,
                            __nv_bfloat16* __restrict__ xh, __nv_bfloat16* __restrict__ xl){
    int n = blockIdx.x;
    int b = ebat[n], st = est[n], len = elen[n];
    const float* base = seq + ((size_t)b*Sdim + st)*Hdim + threadIdx.x*4;
    float4 acc = make_float4(0.f,0.f,0.f,0.f);
    for(int r=0; r<=len; r++){
        float4 t = *reinterpret_cast<const float4*>(base + (size_t)r*Hdim);
        acc.x += t.x; acc.y += t.y; acc.z += t.z; acc.w += t.w;
    }
    float inv = 1.0f/(float)(len+1);
    acc.x*=inv; acc.y*=inv; acc.z*=inv; acc.w*=inv;
    __nv_bfloat16 h0=__float2bfloat16(acc.x), h1=__float2bfloat16(acc.y);
    __nv_bfloat16 h2=__float2bfloat16(acc.z), h3=__float2bfloat16(acc.w);
    __nv_bfloat16 l0=__float2bfloat16(acc.x-__bfloat162float(h0));
    __nv_bfloat16 l1=__float2bfloat16(acc.y-__bfloat162float(h1));
    __nv_bfloat16 l2=__float2bfloat16(acc.z-__bfloat162float(h2));
    __nv_bfloat16 l3=__float2bfloat16(acc.w-__bfloat162float(h3));
    size_t o = (size_t)n*Hdim + threadIdx.x*4;
    *reinterpret_cast<uint2*>(&xh[o]) = make_uint2(pack_bf2(h0,h1), pack_bf2(h2,h3));
    *reinterpret_cast<uint2*>(&xl[o]) = make_uint2(pack_bf2(l0,l1), pack_bf2(l2,l3));
}

// ---------------- init kernels ----------------
__global__ void k_init0(){
    int i = blockIdx.x*blockDim.x + threadIdx.x;
    if(i >= Ndim) return;
    g_deg[i]=0; g_cursor[i]=0; g_pdeg[i]=0; g_pcur[i]=0;
    g_es2[i]=0.f; g_ed2[i]=0.f;
    #pragma unroll
    for(int h=0;h<H1;h++){ g_es1[i*H1+h]=0.f; g_ed1[i*H1+h]=0.f; }
    float4 z4 = make_float4(0.f,0.f,0.f,0.f);
    float4* h2 = reinterpret_cast<float4*>(&g_h2p[(size_t)i*128]);
    #pragma unroll
    for(int j=0;j<32;j++) h2[j] = z4;
}
__global__ void k_out_init(const float* __restrict__ b2, float* __restrict__ out){
    int i = blockIdx.x*blockDim.x + threadIdx.x;
    if(i < NER_OUT_ELEMS) out[i] = b2[i % NERL];
}

// ---------------- merged CSR + pair-sort build ----------------
__global__ void k_count(const int* __restrict__ ei, const int* __restrict__ pidx){
    int idx = blockIdx.x*blockDim.x + threadIdx.x;
    if(idx < ETOT){
        int dst = (idx < Edim) ? ei[Edim + idx] : (idx - Edim);
        atomicAdd(&g_deg[dst], 1);
    }else if(idx < ETOT + Pdim){
        atomicAdd(&g_pdeg[pidx[(idx - ETOT)*2]], 1);
    }
}
__global__ void k_scan(){
    __shared__ int s[1024];
    const int* deg = (blockIdx.x == 0) ? g_deg : g_pdeg;
    int* rowstart  = (blockIdx.x == 0) ? g_rowstart : g_prow;
    int t = threadIdx.x;
    int v0 = deg[t*4+0], v1 = deg[t*4+1], v2 = deg[t*4+2], v3 = deg[t*4+3];
    int c0 = v0, c1 = c0+v1, c2 = c1+v2, c3 = c2+v3;
    s[t] = c3;
    __syncthreads();
    for(int off=1; off<1024; off<<=1){
        int x = (t >= off) ? s[t-off] : 0;
        __syncthreads();
        s[t] += x;
        __syncthreads();
    }
    int excl = s[t] - c3;
    rowstart[t*4+1] = excl + c0;
    rowstart[t*4+2] = excl + c1;
    rowstart[t*4+3] = excl + c2;
    rowstart[t*4+4] = excl + c3;
    if(t==0) rowstart[0] = 0;
}
__global__ void k_scatter(const int* __restrict__ ei, const int* __restrict__ pidx){
    int idx = blockIdx.x*blockDim.x + threadIdx.x;
    if(idx < ETOT){
        int src, dst;
        if(idx < Edim){ src = ei[idx]; dst = ei[Edim + idx]; }
        else          { src = idx - Edim; dst = src; }
        int pos = g_rowstart[dst] + atomicAdd(&g_cursor[dst], 1);
        g_csr[pos] = src;
    }else if(idx < ETOT + Pdim){
        int p = idx - ETOT;
        int i = pidx[p*2];
        int pos = g_prow[i] + atomicAdd(&g_pcur[i], 1);
        g_psorted[pos] = p;
        g_psortj[pos]  = pidx[p*2+1];
    }
}

// ---------------- GAT softmax + aggregation (2-pass; logits small) ----------------
template<int HEADS,int C,int LD,bool RELU,bool SPLIT>
__global__ void k_gat_agg(const float* __restrict__ h,
                          const float* __restrict__ es, const float* __restrict__ ed,
                          const float* __restrict__ bias, float* __restrict__ out,
                          __nv_bfloat16* __restrict__ outH, __nv_bfloat16* __restrict__ outL){
    const int F = HEADS*C;
    int d = blockIdx.x;
    int hh = threadIdx.x >> 5, lane = threadIdx.x & 31;
    int rs = g_rowstart[d], re = g_rowstart[d+1];
    float edv = ed[d*HEADS + hh];

    float den = 0.f;
    for(int e=rs+lane; e<re; e+=32){
        int s = g_csr[e];
        float t = es[s*HEADS+hh] + edv;
        t = (t > 0.f) ? t : SLOPE*t;
        den += __expf(t);
    }
    den = warpSum(den);
    float inv = 1.0f/den;

    float acc[C/32];
    #pragma unroll
    for(int i=0;i<C/32;i++) acc[i]=0.f;

    for(int e=rs; e<re; e++){
        int s = g_csr[e];
        float t = es[s*HEADS+hh] + edv;
        t = (t > 0.f) ? t : SLOPE*t;
        float w = __expf(t)*inv;
        const float* hp = h + (size_t)s*LD + hh*C + lane;
        #pragma unroll
        for(int i=0;i<C/32;i++) acc[i] += w*hp[32*i];
    }
    #pragma unroll
    for(int i=0;i<C/32;i++){
        float v = acc[i] + bias[hh*C + lane + 32*i];
        if(RELU) v = fmaxf(v, 0.f);
        size_t o = (size_t)d*F + hh*C + lane + 32*i;
        if(SPLIT){
            __nv_bfloat16 hb = __float2bfloat16(v);
            outH[o] = hb;
            outL[o] = __float2bfloat16(v - __bfloat162float(hb));
        }else{
            out[o] = v;
        }
    }
}

// ---------------- fused relation head: warp-per-left-entity, 2-way pair unroll ----------------
__global__ void k_rel_g(const int* __restrict__ psorted, const int* __restrict__ psortj,
                        const float* __restrict__ relb1, const float* __restrict__ lng,
                        const float* __restrict__ lnb, const float* __restrict__ relW2,
                        const float* __restrict__ relb2, float* __restrict__ out){
    __shared__ float sb1[256], sg[256], sbb[256], sw2[256];
    int r = blockIdx.y;
    int tid = threadIdx.x;
    sb1[tid] = relb1[r*256+tid];
    sg[tid]  = lng[r*256+tid];
    sbb[tid] = lnb[r*256+tid];
    sw2[tid] = relW2[r*256+tid];
    __syncthreads();

    int w = tid >> 5, lane = tid & 31;
    int i = blockIdx.x*8 + w;
    int rs = g_prow[i], re = g_prow[i+1];
    if(rs == re) return;
    float rb2 = relb2[r];
    float* outr = out + (size_t)r*Pdim;

    float ti[8];
    const float* tip = g_tb + ((size_t)(r*2)*Ndim + i)*RHID;
    #pragma unroll
    for(int t=0;t<8;t++) ti[t] = tip[lane + 32*t];
    const float* tjbase = g_tb + (size_t)(r*2+1)*Ndim*RHID;

    int idx = rs;
    // 2-way unrolled main loop: two independent pairs in flight per iteration
    for(; idx+1 < re; idx += 2){
        int p0 = psorted[idx],   j0 = psortj[idx];
        int p1 = psorted[idx+1], j1 = psortj[idx+1];
        const float* tj0 = tjbase + (size_t)j0*RHID;
        const float* tj1 = tjbase + (size_t)j1*RHID;
        float v0[8], v1[8];
        float s1a=0.f, s2a=0.f, s1b=0.f, s2b=0.f;
        #pragma unroll
        for(int t=0;t<8;t++){
            int k = lane + 32*t;
            float xa = ti[t] + tj0[k] + sb1[k];
            float xb = ti[t] + tj1[k] + sb1[k];
            v0[t] = xa; s1a += xa; s2a += xa*xa;
            v1[t] = xb; s1b += xb; s2b += xb*xb;
        }
        // 4-way interleaved shuffle reduction
        #pragma unroll
        for(int o=16;o;o>>=1){
            s1a += __shfl_xor_sync(0xffffffffu, s1a, o);
            s2a += __shfl_xor_sync(0xffffffffu, s2a, o);
            s1b += __shfl_xor_sync(0xffffffffu, s1b, o);
            s2b += __shfl_xor_sync(0xffffffffu, s2b, o);
        }
        float mua  = s1a*(1.0f/256.0f), mub  = s1b*(1.0f/256.0f);
        float vara = s2a*(1.0f/256.0f) - mua*mua;
        float varb = s2b*(1.0f/256.0f) - mub*mub;
        float ria = rsqrtf(vara + LNEPS), rib = rsqrtf(varb + LNEPS);
        float acca = 0.f, accb = 0.f;
        #pragma unroll
        for(int t=0;t<8;t++){
            int k = lane + 32*t;
            float xa = (v0[t]-mua)*ria*sg[k] + sbb[k];
            float xb = (v1[t]-mub)*rib*sg[k] + sbb[k];
            acca += fmaxf(xa, 0.f) * sw2[k];
            accb += fmaxf(xb, 0.f) * sw2[k];
        }
        #pragma unroll
        for(int o=16;o;o>>=1){
            acca += __shfl_xor_sync(0xffffffffu, acca, o);
            accb += __shfl_xor_sync(0xffffffffu, accb, o);
        }
        if(lane==0){
            outr[p0] = acca + rb2;
            outr[p1] = accb + rb2;
        }
    }
    // tail
    if(idx < re){
        int p = psorted[idx];
        int j = psortj[idx];
        const float* tj = tjbase + (size_t)j*RHID;
        float v[8]; float s1 = 0.f, s2 = 0.f;
        #pragma unroll
        for(int t=0;t<8;t++){
            int k = lane + 32*t;
            float x = ti[t] + tj[k] + sb1[k];
            v[t] = x; s1 += x; s2 += x*x;
        }
        #pragma unroll
        for(int o=16;o;o>>=1){
            s1 += __shfl_xor_sync(0xffffffffu, s1, o);
            s2 += __shfl_xor_sync(0xffffffffu, s2, o);
        }
        float mu  = s1 * (1.0f/256.0f);
        float var = s2 * (1.0f/256.0f) - mu*mu;
        float rinv = rsqrtf(var + LNEPS);
        float acc = 0.f;
        #pragma unroll
        for(int t=0;t<8;t++){
            int k = lane + 32*t;
            float x = (v[t]-mu)*rinv*sg[k] + sbb[k];
            acc += fmaxf(x, 0.f) * sw2[k];
        }
        acc = warpSum(acc);
        if(lane==0) outr[p] = acc + rb2;
    }
}

// ---------------- launch ----------------
extern "C" void kernel_launch(void* const* d_in, const int* in_sizes, int n_in,
                              void* d_out, int out_size){
    const float* seq     = (const float*)d_in[0];
    const int*   est     = (const int*)  d_in[1];
    const int*   elen    = (const int*)  d_in[2];
    const int*   ebat    = (const int*)  d_in[3];
    const int*   ei      = (const int*)  d_in[4];
    const int*   pidx    = (const int*)  d_in[5];
    const float* W1      = (const float*)d_in[6];
    const float* a_src1  = (const float*)d_in[7];
    const float* a_dst1  = (const float*)d_in[8];
    const float* b1      = (const float*)d_in[9];
    const float* W2      = (const float*)d_in[10];
    const float* a_src2  = (const float*)d_in[11];
    const float* a_dst2  = (const float*)d_in[12];
    const float* b2      = (const float*)d_in[13];
    const float* relW1   = (const float*)d_in[14];
    const float* relb1   = (const float*)d_in[15];
    const float* ln_g    = (const float*)d_in[16];
    const float* ln_b    = (const float*)d_in[17];
    const float* relW2   = (const float*)d_in[18];
    const float* relb2   = (const float*)d_in[19];
    const float* nerW1   = (const float*)d_in[20];
    const float* nerb1   = (const float*)d_in[21];
    const float* nerW2   = (const float*)d_in[22];
    const float* nerb2   = (const float*)d_in[23];
    float* out = (float*)d_out;

    float *h1p, *h2pp, *es1p, *ed1p, *es2p, *ed2p, *tbp;
    int *psortedp, *psortjp;
    cudaGetSymbolAddress((void**)&h1p,  g_h1);
    cudaGetSymbolAddress((void**)&h2pp, g_h2p);
    cudaGetSymbolAddress((void**)&es1p, g_es1);
    cudaGetSymbolAddress((void**)&ed1p, g_ed1);
    cudaGetSymbolAddress((void**)&es2p, g_es2);
    cudaGetSymbolAddress((void**)&ed2p, g_ed2);
    cudaGetSymbolAddress((void**)&tbp,  g_tb);
    cudaGetSymbolAddress((void**)&psortedp, g_psorted);
    cudaGetSymbolAddress((void**)&psortjp,  g_psortj);
    __nv_bfloat16 *sqh,*sql,*x0h,*x0l,*o1h,*o1l,*x2h,*x2l,*w1h,*w1l,*wnh,*wnl,*w2h,*w2l,*wrh,*wrl;
    cudaGetSymbolAddress((void**)&sqh, g_sqh); cudaGetSymbolAddress((void**)&sql, g_sql);
    cudaGetSymbolAddress((void**)&x0h, g_x0h); cudaGetSymbolAddress((void**)&x0l, g_x0l);
    cudaGetSymbolAddress((void**)&o1h, g_o1h); cudaGetSymbolAddress((void**)&o1l, g_o1l);
    cudaGetSymbolAddress((void**)&x2h, g_x2h); cudaGetSymbolAddress((void**)&x2l, g_x2l);
    cudaGetSymbolAddress((void**)&w1h, g_w1h); cudaGetSymbolAddress((void**)&w1l, g_w1l);
    cudaGetSymbolAddress((void**)&wnh, g_wnh); cudaGetSymbolAddress((void**)&wnl, g_wnl);
    cudaGetSymbolAddress((void**)&w2h, g_w2h); cudaGetSymbolAddress((void**)&w2l, g_w2l);
    cudaGetSymbolAddress((void**)&wrh, g_wrh); cudaGetSymbolAddress((void**)&wrl, g_wrl);

    static cudaStream_t sNER = nullptr, sIDX = nullptr, sWSP = nullptr;
    static cudaEvent_t evRoot, evNER, evIDX, evZERO, evW1, evW2, evREL;
    if(sNER == nullptr){
        cudaStreamCreateWithFlags(&sNER, cudaStreamNonBlocking);
        cudaStreamCreateWithFlags(&sIDX, cudaStreamNonBlocking);
        cudaStreamCreateWithFlags(&sWSP, cudaStreamNonBlocking);
        cudaEventCreateWithFlags(&evRoot, cudaEventDisableTiming);
        cudaEventCreateWithFlags(&evNER,  cudaEventDisableTiming);
        cudaEventCreateWithFlags(&evIDX,  cudaEventDisableTiming);
        cudaEventCreateWithFlags(&evZERO, cudaEventDisableTiming);
        cudaEventCreateWithFlags(&evW1,   cudaEventDisableTiming);
        cudaEventCreateWithFlags(&evW2,   cudaEventDisableTiming);
        cudaEventCreateWithFlags(&evREL,  cudaEventDisableTiming);
        cudaFuncSetAttribute(k_hmma<0>, cudaFuncAttributeMaxDynamicSharedMemorySize, HMMA_SMEM);
        cudaFuncSetAttribute(k_hmma<1>, cudaFuncAttributeMaxDynamicSharedMemorySize, HMMA_SMEM);
        cudaFuncSetAttribute(k_hmma<2>, cudaFuncAttributeMaxDynamicSharedMemorySize, HMMA_SMEM);
    }

    #define SPLIT(st, src, dh, dl, cnt) \
        k_split<<<((cnt)/4 + 255)/256, 256, 0, st>>>((const float4*)(src), (uint2*)(dh), (uint2*)(dl), (cnt)/4)

    // fork
    cudaEventRecord(evRoot, 0);
    cudaStreamWaitEvent(sNER, evRoot, 0);
    cudaStreamWaitEvent(sIDX, evRoot, 0);
    cudaStreamWaitEvent(sWSP, evRoot, 0);

    // --- NER chain ---
    k_out_init<<<(NER_OUT_ELEMS+255)/256, 256, 0, sNER>>>(nerb2, out);
    SPLIT(sNER, nerW1, wnh, wnl, Hdim*NERH);
    SPLIT(sNER, seq,   sqh, sql, NERROWS*Hdim);
    k_hmma<2><<<dim3(NERH/128, NERROWS/128, 1), 256, HMMA_SMEM, sNER>>>(
        sqh, sql, Hdim, Hdim, 0, wnh, wnl, NERH, 0, nerb1, 1, nullptr, 0, 0, 0,
        nerW2, nullptr, out, nullptr, 128, 1, NERH);
    cudaEventRecord(evNER, sNER);

    // --- index build chain ---
    k_init0<<<(Ndim+255)/256, 256, 0, sIDX>>>();
    cudaEventRecord(evZERO, sIDX);
    k_count<<<(ETOT+Pdim+255)/256, 256, 0, sIDX>>>(ei, pidx);
    k_scan<<<2, 1024, 0, sIDX>>>();
    k_scatter<<<(ETOT+Pdim+255)/256, 256, 0, sIDX>>>(ei, pidx);
    cudaEventRecord(evIDX, sIDX);

    // --- weight splits ---
    SPLIT(sWSP, W1, w1h, w1l, Hdim*F1);
    cudaEventRecord(evW1, sWSP);
    k_split_padW2<<<F1*128/256, 256, 0, sWSP>>>(W2, w2h, w2l);
    cudaEventRecord(evW2, sWSP);
    SPLIT(sWSP, relW1, wrh, wrl, 12*C2*RHID);
    cudaEventRecord(evREL, sWSP);

    // --- main GAT chain ---
    k_span_pool<<<Ndim, 192>>>(seq, est, elen, ebat, x0h, x0l);
    cudaStreamWaitEvent(0, evW1, 0);
    cudaStreamWaitEvent(0, evZERO, 0);
    k_hmma<1><<<dim3(F1/128, Ndim/128, 1), 256, HMMA_SMEM>>>(
        x0h, x0l, Hdim, Hdim, 0, w1h, w1l, F1, 0, nullptr, 0, h1p, F1, 0, 0,
        a_src1, a_dst1, es1p, ed1p, C1, H1, F1);
    cudaStreamWaitEvent(0, evIDX, 0);
    k_gat_agg<H1, C1, F1, true, true><<<Ndim, 128>>>(h1p, es1p, ed1p, b1, nullptr, o1h, o1l);
    cudaStreamWaitEvent(0, evW2, 0);
    k_hmma<1><<<dim3(1, Ndim/128, 2), 256, HMMA_SMEM>>>(
        o1h, o1l, F1, 256, 256, w2h, w2l, 128, (long)256*128, nullptr, 0,
        h2pp, 128, 0, 1,
        a_src2, a_dst2, es2p, ed2p, C2, 1, C2);
    k_gat_agg<1, C2, 128, false, true><<<Ndim, 32>>>(h2pp, es2p, ed2p, b2, nullptr, x2h, x2l);
    cudaStreamWaitEvent(0, evREL, 0);
    k_hmma<0><<<dim3(RHID/128, Ndim/128, 12), 256, HMMA_SMEM>>>(
        x2h, x2l, C2, C2, 0, wrh, wrl, RHID, (long)C2*RHID, nullptr, 0,
        tbp, RHID, (long)Ndim*RHID, 0,
        nullptr, nullptr, nullptr, nullptr, 128, 1, RHID);
    k_rel_g<<<dim3(Ndim/8, NREL), 256>>>(psortedp, psortjp,
        relb1, ln_g, ln_b, relW2, relb2, out + NER_OUT_ELEMS);

    // join
    cudaStreamWaitEvent(0, evNER, 0);
    #undef SPLIT
}

// round 16
// speedup vs baseline: 1.9235x; 1.0619x over previous
#include <cuda_runtime.h>
#include <cuda_bf16.h>
#include <math.h>
#include <stdint.h>

// ---------------- problem constants ----------------
#define Bdim 32
#define Sdim 512
#define Hdim 768
#define Ndim 4096
#define Edim 131072
#define Pdim 65536
#define ETOT (Edim + Ndim)
#define H1 4
#define C1 128
#define F1 (H1*C1)               // 512
#define C2 64
#define NREL 6
#define RHID 256
#define NERH 256
#define NERL 9
#define SLOPE 0.2f
#define LNEPS 1e-5f
#define NER_OUT_ELEMS (Bdim*Sdim*NERL)
#define NERROWS (Bdim*Sdim)      // 16384

// ---------------- device scratch ----------------
__device__ float g_h1[Ndim*F1];
__device__ float g_h2p[Ndim*128];
__device__ float g_es1[Ndim*H1], g_ed1[Ndim*H1];
__device__ float g_es2[Ndim],    g_ed2[Ndim];
__device__ int   g_deg[Ndim], g_cursor[Ndim], g_rowstart[Ndim+1];
__device__ int   g_csr[ETOT];
__device__ int   g_pdeg[Ndim], g_pcur[Ndim], g_prow[Ndim+1];
__device__ int   g_psorted[Pdim];
__device__ int   g_psortj[Pdim];
__device__ float g_tb[12*Ndim*RHID];
__device__ __nv_bfloat16 g_sqh[NERROWS*Hdim], g_sql[NERROWS*Hdim];
__device__ __nv_bfloat16 g_x0h[Ndim*Hdim],    g_x0l[Ndim*Hdim];
__device__ __nv_bfloat16 g_o1h[Ndim*F1],      g_o1l[Ndim*F1];
__device__ __nv_bfloat16 g_x2h[Ndim*C2],      g_x2l[Ndim*C2];
__device__ __nv_bfloat16 g_w1h[Hdim*F1],      g_w1l[Hdim*F1];
__device__ __nv_bfloat16 g_wnh[Hdim*NERH],    g_wnl[Hdim*NERH];
__device__ __nv_bfloat16 g_w2h[F1*128],       g_w2l[F1*128];
__device__ __nv_bfloat16 g_wrh[12*C2*RHID],   g_wrl[12*C2*RHID];

// ---------------- helpers ----------------
__device__ __forceinline__ float warpSum(float v){
    #pragma unroll
    for(int o=16;o;o>>=1) v += __shfl_xor_sync(0xffffffffu, v, o);
    return v;
}
__device__ __forceinline__ float quadSum(float v){
    v += __shfl_xor_sync(0xffffffffu, v, 1);
    v += __shfl_xor_sync(0xffffffffu, v, 2);
    return v;
}
__device__ __forceinline__ uint32_t smem_u32(const void* p){
    uint32_t a;
    asm("{ .reg .u64 t; cvta.to.shared.u64 t, %1; cvt.u32.u64 %0, t; }" : "=r"(a) : "l"(p));
    return a;
}
__device__ __forceinline__ unsigned pack_bf2(__nv_bfloat16 a, __nv_bfloat16 b){
    __nv_bfloat162 t; t.x = a; t.y = b;
    return *reinterpret_cast<unsigned*>(&t);
}
__device__ __forceinline__ void cp16(uint32_t dst, const void* src){
    asm volatile("cp.async.ca.shared.global [%0], [%1], 16;" :: "r"(dst), "l"(src) : "memory");
}
__device__ __forceinline__ void ldsm4(uint32_t* r, uint32_t addr){
    asm volatile("ldmatrix.sync.aligned.m8n8.x4.shared.b16 {%0,%1,%2,%3}, [%4];"
        : "=r"(r[0]), "=r"(r[1]), "=r"(r[2]), "=r"(r[3]) : "r"(addr));
}
__device__ __forceinline__ void ldsm4t(uint32_t* r, uint32_t addr){
    asm volatile("ldmatrix.sync.aligned.m8n8.x4.trans.shared.b16 {%0,%1,%2,%3}, [%4];"
        : "=r"(r[0]), "=r"(r[1]), "=r"(r[2]), "=r"(r[3]) : "r"(addr));
}
__device__ __forceinline__ void mma16816(float* d, const uint32_t* a, uint32_t b0, uint32_t b1){
    asm volatile(
        "mma.sync.aligned.m16n8k16.row.col.f32.bf16.bf16.f32 "
        "{%0,%1,%2,%3}, {%4,%5,%6,%7}, {%8,%9}, {%0,%1,%2,%3};"
        : "+f"(d[0]), "+f"(d[1]), "+f"(d[2]), "+f"(d[3])
        : "r"(a[0]), "r"(a[1]), "r"(a[2]), "r"(a[3]), "r"(b0), "r"(b1));
}

// ---------------- split fp32 -> bf16 hi/lo planes ----------------
__global__ void k_split(const float4* __restrict__ in, uint2* __restrict__ hi,
                        uint2* __restrict__ lo, int n4){
    int i = blockIdx.x*blockDim.x + threadIdx.x;
    if(i >= n4) return;
    float4 v = in[i];
    __nv_bfloat16 h0=__float2bfloat16(v.x), h1=__float2bfloat16(v.y);
    __nv_bfloat16 h2=__float2bfloat16(v.z), h3=__float2bfloat16(v.w);
    __nv_bfloat16 l0=__float2bfloat16(v.x-__bfloat162float(h0));
    __nv_bfloat16 l1=__float2bfloat16(v.y-__bfloat162float(h1));
    __nv_bfloat16 l2=__float2bfloat16(v.z-__bfloat162float(h2));
    __nv_bfloat16 l3=__float2bfloat16(v.w-__bfloat162float(h3));
    hi[i] = make_uint2(pack_bf2(h0,h1), pack_bf2(h2,h3));
    lo[i] = make_uint2(pack_bf2(l0,l1), pack_bf2(l2,l3));
}

__global__ void k_split_padW2(const float* __restrict__ W2,
                              __nv_bfloat16* __restrict__ hi, __nv_bfloat16* __restrict__ lo){
    int idx = blockIdx.x*256 + threadIdx.x;
    int k = idx >> 7, c = idx & 127;
    float v = (c < C2) ? W2[k*C2 + c] : 0.f;
    __nv_bfloat16 h = __float2bfloat16(v);
    __nv_bfloat16 l = __float2bfloat16(v - __bfloat162float(h));
    hi[idx] = h; lo[idx] = l;
}

// ---------------- split-bf16 HMMA GEMM with fused epilogues ----------------
// 256 threads, 8 warps, warp tile 64x32, CTA tile 128x128
// EPI: 0 = store only; 1 = store/atomic + attention coef atomics; 2 = NER stage2
#define SA 40
#define SB 136
#define A_PL (128*SA*2)
#define B_PL (32*SB*2)
#define BOFF (2*A_PL)
#define STAGE_SZ (BOFF + 2*B_PL)
#define PIPE_SZ (2*STAGE_SZ)
#define HMMA_SMEM (PIPE_SZ + 4608)
template<int EPI>
__global__ void __launch_bounds__(256) k_hmma(
        const __nv_bfloat16* __restrict__ aHi, const __nv_bfloat16* __restrict__ aLo,
        int lda, int K, long aStrideZ,
        const __nv_bfloat16* __restrict__ wHi, const __nv_bfloat16* __restrict__ wLo, int N,
        long wStrideZ, const float* __restrict__ bias, int reluFlag,
        float* __restrict__ C, int ldc, long cStrideZ, int atomicC,
        const float* __restrict__ p1, const float* __restrict__ p2,
        float* __restrict__ q1, float* __restrict__ q2,
        int headC, int nheads, int validN){
    extern __shared__ char sm_buf[];
    int tid = threadIdx.x, lane = tid & 31, warp = tid >> 5;
    int wm = warp & 1, wn = warp >> 1;
    int grp = lane >> 3, rr = lane & 7;
    int arow = rr + (grp & 1)*8;
    int acol = (grp >> 1)*8;

    int n0 = blockIdx.x*128, m0 = blockIdx.y*128, z = blockIdx.z;
    const __nv_bfloat16* azh = aHi + (size_t)z*aStrideZ;
    const __nv_bfloat16* azl = aLo + (size_t)z*aStrideZ;
    const __nv_bfloat16* wzh = wHi + (size_t)z*wStrideZ;
    const __nv_bfloat16* wzl = wLo + (size_t)z*wStrideZ;
    int nc = K >> 5;

    float* sx = (float*)(sm_buf + PIPE_SZ);
    if(EPI == 1){
        if(tid < 128){
            int n = n0 + tid;
            sx[tid]     = (n < validN) ? p1[n] : 0.f;
            sx[128+tid] = (n < validN) ? p2[n] : 0.f;
        }
    }else if(EPI == 2){
        for(int j=tid; j<128*NERL; j+=256)
            sx[j] = p1[(size_t)(n0 + j/NERL)*NERL + (j%NERL)];
    }

    float acc[4][4][4];
    #pragma unroll
    for(int a=0;a<4;a++)
        #pragma unroll
        for(int b=0;b<4;b++)
            #pragma unroll
            for(int c=0;c<4;c++) acc[a][b][c] = 0.f;

    uint32_t sb0 = smem_u32(sm_buf);

    #define ISSUE(kc, st) do{                                                        \
        uint32_t sb = sb0 + (st)*STAGE_SZ;                                           \
        _Pragma("unroll")                                                            \
        for(int i=0;i<2;i++){                                                        \
            int idx = tid + i*256; int row = idx >> 2, k8 = idx & 3;                 \
            size_t go = (size_t)(m0+row)*lda + (kc)*32 + k8*8;                       \
            uint32_t d = sb + row*80 + k8*16;                                        \
            cp16(d,        azh + go);                                                \
            cp16(d + A_PL, azl + go);                                                \
        }                                                                            \
        _Pragma("unroll")                                                            \
        for(int i=0;i<2;i++){                                                        \
            int idx = tid + i*256; int kr = idx >> 4, ncol = idx & 15;               \
            size_t go = (size_t)((kc)*32 + kr)*N + n0 + ncol*8;                      \
            uint32_t d = sb + BOFF + kr*272 + ncol*16;                               \
            cp16(d,        wzh + go);                                                \
            cp16(d + B_PL, wzl + go);                                                \
        }                                                                            \
        asm volatile("cp.async.commit_group;" ::: "memory");                         \
    }while(0)

    ISSUE(0, 0);
    for(int kc=0; kc<nc; kc++){
        if(kc+1 < nc){
            ISSUE(kc+1, (kc+1)&1);
            asm volatile("cp.async.wait_group 1;" ::: "memory");
        }else{
            asm volatile("cp.async.wait_group 0;" ::: "memory");
        }
        __syncthreads();
        uint32_t sb = sb0 + (kc&1)*STAGE_SZ;
        uint32_t aBase = sb + ((wm*64 + arow)*SA + acol)*2;
        uint32_t bBase = sb + BOFF + (arow*SB + wn*32 + acol)*2;
        #pragma unroll
        for(int kk=0; kk<2; kk++){
            uint32_t bfr[2][2][4];
            #pragma unroll
            for(int pr=0; pr<2; pr++){
                uint32_t bd = bBase + kk*(16*SB*2) + pr*32;
                ldsm4t(bfr[pr][0], bd);
                ldsm4t(bfr[pr][1], bd + B_PL);
            }
            #pragma unroll
            for(int mt=0; mt<4; mt++){
                uint32_t af[2][4];
                uint32_t ad = aBase + mt*(16*SA*2) + kk*32;
                ldsm4(af[0], ad);
                ldsm4(af[1], ad + A_PL);
                #pragma unroll
                for(int nt=0; nt<4; nt++){
                    int pr = nt >> 1, hf = (nt & 1)*2;
                    uint32_t bh0 = bfr[pr][0][hf], bh1 = bfr[pr][0][hf+1];
                    uint32_t bl0 = bfr[pr][1][hf], bl1 = bfr[pr][1][hf+1];
                    mma16816(acc[mt][nt], af[0], bh0, bh1);
                    mma16816(acc[mt][nt], af[0], bl0, bl1);
                    mma16816(acc[mt][nt], af[1], bh0, bh1);
                }
            }
        }
        __syncthreads();
    }
    #undef ISSUE

    // ---- epilogue ----
    float* Cz = C + (size_t)z*cStrideZ;
    int hh = (n0 + wn*32) / headC;
    bool hhok = hh < nheads;
    float bcol[8];
    #pragma unroll
    for(int nt=0; nt<4; nt++){
        int n = n0 + wn*32 + nt*8 + (lane & 3)*2;
        bcol[nt*2]   = bias ? bias[n]   : 0.f;
        bcol[nt*2+1] = bias ? bias[n+1] : 0.f;
    }
    #pragma unroll
    for(int mt=0; mt<4; mt++){
        int mb = m0 + wm*64 + mt*16 + (lane >> 2);
        #pragma unroll
        for(int half=0; half<2; half++){
            int m = mb + half*8;
            float v[8];
            #pragma unroll
            for(int nt=0; nt<4; nt++){
                float a0 = acc[mt][nt][half*2]   + bcol[nt*2];
                float a1 = acc[mt][nt][half*2+1] + bcol[nt*2+1];
                if(reluFlag){ a0 = fmaxf(a0,0.f); a1 = fmaxf(a1,0.f); }
                v[nt*2] = a0; v[nt*2+1] = a1;
                if(EPI != 2){
                    int n = n0 + wn*32 + nt*8 + (lane & 3)*2;
                    if(atomicC){
                        atomicAdd(&Cz[(size_t)m*ldc + n],   a0);
                        atomicAdd(&Cz[(size_t)m*ldc + n+1], a1);
                    }else{
                        *reinterpret_cast<float2*>(Cz + (size_t)m*ldc + n) = make_float2(a0, a1);
                    }
                }
            }
            if(EPI == 1){
                float ps = 0.f, pd = 0.f;
                #pragma unroll
                for(int t=0;t<8;t++){
                    int ln = wn*32 + (t>>1)*8 + (lane&3)*2 + (t&1);
                    ps += v[t]*sx[ln];
                    pd += v[t]*sx[128+ln];
                }
                ps = quadSum(ps); pd = quadSum(pd);
                if((lane&3)==0 && hhok){
                    atomicAdd(&q1[m*nheads + hh], ps);
                    atomicAdd(&q2[m*nheads + hh], pd);
                }
            }else if(EPI == 2){
                float pc[NERL];
                #pragma unroll
                for(int c=0;c<NERL;c++) pc[c] = 0.f;
                #pragma unroll
                for(int t=0;t<8;t++){
                    int ln = wn*32 + (t>>1)*8 + (lane&3)*2 + (t&1);
                    #pragma unroll
                    for(int c=0;c<NERL;c++) pc[c] += v[t]*sx[ln*NERL + c];
                }
                #pragma unroll
                for(int c=0;c<NERL;c++){
                    float s = quadSum(pc[c]);
                    if((lane&3)==0) atomicAdd(&q1[(size_t)m*NERL + c], s);
                }
            }
        }
    }
}

// ---------------- entity span mean pooling -> bf16 hi/lo planes ----------------
__global__ void k_span_pool(const float* __restrict__ seq,
                            const int* __restrict__ est, const int* __restrict__ elen,
                            const int* __restrict__ ebat,
                            __nv_bfloat16* __restrict__ xh, __nv_bfloat16* __restrict__ xl){
    int n = blockIdx.x;
    int b = ebat[n], st = est[n], len = elen[n];
    const float* base = seq + ((size_t)b*Sdim + st)*Hdim + threadIdx.x*4;
    float4 acc = make_float4(0.f,0.f,0.f,0.f);
    for(int r=0; r<=len; r++){
        float4 t = *reinterpret_cast<const float4*>(base + (size_t)r*Hdim);
        acc.x += t.x; acc.y += t.y; acc.z += t.z; acc.w += t.w;
    }
    float inv = 1.0f/(float)(len+1);
    acc.x*=inv; acc.y*=inv; acc.z*=inv; acc.w*=inv;
    __nv_bfloat16 h0=__float2bfloat16(acc.x), h1=__float2bfloat16(acc.y);
    __nv_bfloat16 h2=__float2bfloat16(acc.z), h3=__float2bfloat16(acc.w);
    __nv_bfloat16 l0=__float2bfloat16(acc.x-__bfloat162float(h0));
    __nv_bfloat16 l1=__float2bfloat16(acc.y-__bfloat162float(h1));
    __nv_bfloat16 l2=__float2bfloat16(acc.z-__bfloat162float(h2));
    __nv_bfloat16 l3=__float2bfloat16(acc.w-__bfloat162float(h3));
    size_t o = (size_t)n*Hdim + threadIdx.x*4;
    *reinterpret_cast<uint2*>(&xh[o]) = make_uint2(pack_bf2(h0,h1), pack_bf2(h2,h3));
    *reinterpret_cast<uint2*>(&xl[o]) = make_uint2(pack_bf2(l0,l1), pack_bf2(l2,l3));
}

// ---------------- init kernels ----------------
__global__ void k_init0(){
    int i = blockIdx.x*blockDim.x + threadIdx.x;
    if(i >= Ndim) return;
    g_deg[i]=0; g_cursor[i]=0; g_pdeg[i]=0; g_pcur[i]=0;
    g_es2[i]=0.f; g_ed2[i]=0.f;
    #pragma unroll
    for(int h=0;h<H1;h++){ g_es1[i*H1+h]=0.f; g_ed1[i*H1+h]=0.f; }
    float4 z4 = make_float4(0.f,0.f,0.f,0.f);
    float4* h2 = reinterpret_cast<float4*>(&g_h2p[(size_t)i*128]);
    #pragma unroll
    for(int j=0;j<32;j++) h2[j] = z4;
}
__global__ void k_out_init(const float* __restrict__ b2, float* __restrict__ out){
    int i = blockIdx.x*blockDim.x + threadIdx.x;
    if(i < NER_OUT_ELEMS) out[i] = b2[i % NERL];
}

// ---------------- merged CSR + pair-sort build ----------------
__global__ void k_count(const int* __restrict__ ei, const int* __restrict__ pidx){
    int idx = blockIdx.x*blockDim.x + threadIdx.x;
    if(idx < ETOT){
        int dst = (idx < Edim) ? ei[Edim + idx] : (idx - Edim);
        atomicAdd(&g_deg[dst], 1);
    }else if(idx < ETOT + Pdim){
        atomicAdd(&g_pdeg[pidx[(idx - ETOT)*2]], 1);
    }
}
__global__ void k_scan(){
    __shared__ int s[1024];
    const int* deg = (blockIdx.x == 0) ? g_deg : g_pdeg;
    int* rowstart  = (blockIdx.x == 0) ? g_rowstart : g_prow;
    int t = threadIdx.x;
    int v0 = deg[t*4+0], v1 = deg[t*4+1], v2 = deg[t*4+2], v3 = deg[t*4+3];
    int c0 = v0, c1 = c0+v1, c2 = c1+v2, c3 = c2+v3;
    s[t] = c3;
    __syncthreads();
    for(int off=1; off<1024; off<<=1){
        int x = (t >= off) ? s[t-off] : 0;
        __syncthreads();
        s[t] += x;
        __syncthreads();
    }
    int excl = s[t] - c3;
    rowstart[t*4+1] = excl + c0;
    rowstart[t*4+2] = excl + c1;
    rowstart[t*4+3] = excl + c2;
    rowstart[t*4+4] = excl + c3;
    if(t==0) rowstart[0] = 0;
}
__global__ void k_scatter(const int* __restrict__ ei, const int* __restrict__ pidx){
    int idx = blockIdx.x*blockDim.x + threadIdx.x;
    if(idx < ETOT){
        int src, dst;
        if(idx < Edim){ src = ei[idx]; dst = ei[Edim + idx]; }
        else          { src = idx - Edim; dst = src; }
        int pos = g_rowstart[dst] + atomicAdd(&g_cursor[dst], 1);
        g_csr[pos] = src;
    }else if(idx < ETOT + Pdim){
        int p = idx - ETOT;
        int i = pidx[p*2];
        int pos = g_prow[i] + atomicAdd(&g_pcur[i], 1);
        g_psorted[pos] = p;
        g_psortj[pos]  = pidx[p*2+1];
    }
}

// ---------------- GAT softmax + aggregation (2-pass; pass 2 unrolled 2-way) ----------------
template<int HEADS,int C,int LD,bool RELU,bool SPLIT>
__global__ void k_gat_agg(const float* __restrict__ h,
                          const float* __restrict__ es, const float* __restrict__ ed,
                          const float* __restrict__ bias, float* __restrict__ out,
                          __nv_bfloat16* __restrict__ outH, __nv_bfloat16* __restrict__ outL){
    const int F = HEADS*C;
    int d = blockIdx.x;
    int hh = threadIdx.x >> 5, lane = threadIdx.x & 31;
    int rs = g_rowstart[d], re = g_rowstart[d+1];
    float edv = ed[d*HEADS + hh];

    float den = 0.f;
    for(int e=rs+lane; e<re; e+=32){
        int s = g_csr[e];
        float t = es[s*HEADS+hh] + edv;
        t = (t > 0.f) ? t : SLOPE*t;
        den += __expf(t);
    }
    den = warpSum(den);
    float inv = 1.0f/den;

    float acc[C/32];
    #pragma unroll
    for(int i=0;i<C/32;i++) acc[i]=0.f;

    int e = rs;
    for(; e+1 < re; e += 2){
        int s0 = g_csr[e], s1 = g_csr[e+1];
        float t0 = es[s0*HEADS+hh] + edv;
        float t1 = es[s1*HEADS+hh] + edv;
        t0 = (t0 > 0.f) ? t0 : SLOPE*t0;
        t1 = (t1 > 0.f) ? t1 : SLOPE*t1;
        float w0 = __expf(t0)*inv;
        float w1 = __expf(t1)*inv;
        const float* hp0 = h + (size_t)s0*LD + hh*C + lane;
        const float* hp1 = h + (size_t)s1*LD + hh*C + lane;
        #pragma unroll
        for(int i=0;i<C/32;i++) acc[i] += w0*hp0[32*i] + w1*hp1[32*i];
    }
    if(e < re){
        int s = g_csr[e];
        float t = es[s*HEADS+hh] + edv;
        t = (t > 0.f) ? t : SLOPE*t;
        float w = __expf(t)*inv;
        const float* hp = h + (size_t)s*LD + hh*C + lane;
        #pragma unroll
        for(int i=0;i<C/32;i++) acc[i] += w*hp[32*i];
    }
    #pragma unroll
    for(int i=0;i<C/32;i++){
        float v = acc[i] + bias[hh*C + lane + 32*i];
        if(RELU) v = fmaxf(v, 0.f);
        size_t o = (size_t)d*F + hh*C + lane + 32*i;
        if(SPLIT){
            __nv_bfloat16 hb = __float2bfloat16(v);
            outH[o] = hb;
            outL[o] = __float2bfloat16(v - __bfloat162float(hb));
        }else{
            out[o] = v;
        }
    }
}

// ---------------- fused relation head: warp-per-left-entity, 4/2/1-way unroll ----------------
__global__ void k_rel_g(const int* __restrict__ psorted, const int* __restrict__ psortj,
                        const float* __restrict__ relb1, const float* __restrict__ lng,
                        const float* __restrict__ lnb, const float* __restrict__ relW2,
                        const float* __restrict__ relb2, float* __restrict__ out){
    __shared__ float sb1[256], sg[256], sbb[256], sw2[256];
    int r = blockIdx.y;
    int tid = threadIdx.x;
    sb1[tid] = relb1[r*256+tid];
    sg[tid]  = lng[r*256+tid];
    sbb[tid] = lnb[r*256+tid];
    sw2[tid] = relW2[r*256+tid];
    __syncthreads();

    int w = tid >> 5, lane = tid & 31;
    int i = blockIdx.x*8 + w;
    int rs = g_prow[i], re = g_prow[i+1];
    if(rs == re) return;
    float rb2 = relb2[r];
    float* outr = out + (size_t)r*Pdim;

    float ti[8];
    const float* tip = g_tb + ((size_t)(r*2)*Ndim + i)*RHID;
    #pragma unroll
    for(int t=0;t<8;t++) ti[t] = tip[lane + 32*t];
    const float* tjbase = g_tb + (size_t)(r*2+1)*Ndim*RHID;

    int idx = rs;
    // 4-way unrolled main loop
    for(; idx+3 < re; idx += 4){
        int p0 = psorted[idx],   j0 = psortj[idx];
        int p1 = psorted[idx+1], j1 = psortj[idx+1];
        int p2 = psorted[idx+2], j2 = psortj[idx+2];
        int p3 = psorted[idx+3], j3 = psortj[idx+3];
        const float* tj0 = tjbase + (size_t)j0*RHID;
        const float* tj1 = tjbase + (size_t)j1*RHID;
        const float* tj2 = tjbase + (size_t)j2*RHID;
        const float* tj3 = tjbase + (size_t)j3*RHID;
        float v0[8], v1[8], v2[8], v3[8];
        float s1a=0.f,s2a=0.f,s1b=0.f,s2b=0.f,s1c=0.f,s2c=0.f,s1d=0.f,s2d=0.f;
        #pragma unroll
        for(int t=0;t<8;t++){
            int k = lane + 32*t;
            float base = ti[t] + sb1[k];
            float xa = base + tj0[k];
            float xb = base + tj1[k];
            float xc = base + tj2[k];
            float xd = base + tj3[k];
            v0[t]=xa; s1a+=xa; s2a+=xa*xa;
            v1[t]=xb; s1b+=xb; s2b+=xb*xb;
            v2[t]=xc; s1c+=xc; s2c+=xc*xc;
            v3[t]=xd; s1d+=xd; s2d+=xd*xd;
        }
        #pragma unroll
        for(int o=16;o;o>>=1){
            s1a += __shfl_xor_sync(0xffffffffu, s1a, o);
            s2a += __shfl_xor_sync(0xffffffffu, s2a, o);
            s1b += __shfl_xor_sync(0xffffffffu, s1b, o);
            s2b += __shfl_xor_sync(0xffffffffu, s2b, o);
            s1c += __shfl_xor_sync(0xffffffffu, s1c, o);
            s2c += __shfl_xor_sync(0xffffffffu, s2c, o);
            s1d += __shfl_xor_sync(0xffffffffu, s1d, o);
            s2d += __shfl_xor_sync(0xffffffffu, s2d, o);
        }
        float mua = s1a*(1.0f/256.0f), mub = s1b*(1.0f/256.0f);
        float muc = s1c*(1.0f/256.0f), mud = s1d*(1.0f/256.0f);
        float ria = rsqrtf(s2a*(1.0f/256.0f) - mua*mua + LNEPS);
        float rib = rsqrtf(s2b*(1.0f/256.0f) - mub*mub + LNEPS);
        float ric = rsqrtf(s2c*(1.0f/256.0f) - muc*muc + LNEPS);
        float rid = rsqrtf(s2d*(1.0f/256.0f) - mud*mud + LNEPS);
        float acca=0.f, accb=0.f, accc=0.f, accd=0.f;
        #pragma unroll
        for(int t=0;t<8;t++){
            int k = lane + 32*t;
            float gk = sg[k], bk = sbb[k], wk = sw2[k];
            acca += fmaxf((v0[t]-mua)*ria*gk + bk, 0.f) * wk;
            accb += fmaxf((v1[t]-mub)*rib*gk + bk, 0.f) * wk;
            accc += fmaxf((v2[t]-muc)*ric*gk + bk, 0.f) * wk;
            accd += fmaxf((v3[t]-mud)*rid*gk + bk, 0.f) * wk;
        }
        #pragma unroll
        for(int o=16;o;o>>=1){
            acca += __shfl_xor_sync(0xffffffffu, acca, o);
            accb += __shfl_xor_sync(0xffffffffu, accb, o);
            accc += __shfl_xor_sync(0xffffffffu, accc, o);
            accd += __shfl_xor_sync(0xffffffffu, accd, o);
        }
        if(lane==0){
            outr[p0] = acca + rb2;
            outr[p1] = accb + rb2;
            outr[p2] = accc + rb2;
            outr[p3] = accd + rb2;
        }
    }
    // 2-way
    for(; idx+1 < re; idx += 2){
        int p0 = psorted[idx],   j0 = psortj[idx];
        int p1 = psorted[idx+1], j1 = psortj[idx+1];
        const float* tj0 = tjbase + (size_t)j0*RHID;
        const float* tj1 = tjbase + (size_t)j1*RHID;
        float v0[8], v1[8];
        float s1a=0.f, s2a=0.f, s1b=0.f, s2b=0.f;
        #pragma unroll
        for(int t=0;t<8;t++){
            int k = lane + 32*t;
            float base = ti[t] + sb1[k];
            float xa = base + tj0[k];
            float xb = base + tj1[k];
            v0[t] = xa; s1a += xa; s2a += xa*xa;
            v1[t] = xb; s1b += xb; s2b += xb*xb;
        }
        #pragma unroll
        for(int o=16;o;o>>=1){
            s1a += __shfl_xor_sync(0xffffffffu, s1a, o);
            s2a += __shfl_xor_sync(0xffffffffu, s2a, o);
            s1b += __shfl_xor_sync(0xffffffffu, s1b, o);
            s2b += __shfl_xor_sync(0xffffffffu, s2b, o);
        }
        float mua  = s1a*(1.0f/256.0f), mub  = s1b*(1.0f/256.0f);
        float ria = rsqrtf(s2a*(1.0f/256.0f) - mua*mua + LNEPS);
        float rib = rsqrtf(s2b*(1.0f/256.0f) - mub*mub + LNEPS);
        float acca = 0.f, accb = 0.f;
        #pragma unroll
        for(int t=0;t<8;t++){
            int k = lane + 32*t;
            float gk = sg[k], bk = sbb[k], wk = sw2[k];
            acca += fmaxf((v0[t]-mua)*ria*gk + bk, 0.f) * wk;
            accb += fmaxf((v1[t]-mub)*rib*gk + bk, 0.f) * wk;
        }
        #pragma unroll
        for(int o=16;o;o>>=1){
            acca += __shfl_xor_sync(0xffffffffu, acca, o);
            accb += __shfl_xor_sync(0xffffffffu, accb, o);
        }
        if(lane==0){
            outr[p0] = acca + rb2;
            outr[p1] = accb + rb2;
        }
    }
    // tail
    if(idx < re){
        int p = psorted[idx];
        int j = psortj[idx];
        const float* tj = tjbase + (size_t)j*RHID;
        float v[8]; float s1 = 0.f, s2 = 0.f;
        #pragma unroll
        for(int t=0;t<8;t++){
            int k = lane + 32*t;
            float x = ti[t] + tj[k] + sb1[k];
            v[t] = x; s1 += x; s2 += x*x;
        }
        #pragma unroll
        for(int o=16;o;o>>=1){
            s1 += __shfl_xor_sync(0xffffffffu, s1, o);
            s2 += __shfl_xor_sync(0xffffffffu, s2, o);
        }
        float mu  = s1 * (1.0f/256.0f);
        float rinv = rsqrtf(s2*(1.0f/256.0f) - mu*mu + LNEPS);
        float acc = 0.f;
        #pragma unroll
        for(int t=0;t<8;t++){
            int k = lane + 32*t;
            float x = (v[t]-mu)*rinv*sg[k] + sbb[k];
            acc += fmaxf(x, 0.f) * sw2[k];
        }
        acc = warpSum(acc);
        if(lane==0) outr[p] = acc + rb2;
    }
}

// ---------------- launch ----------------
extern "C" void kernel_launch(void* const* d_in, const int* in_sizes, int n_in,
                              void* d_out, int out_size){
    const float* seq     = (const float*)d_in[0];
    const int*   est     = (const int*)  d_in[1];
    const int*   elen    = (const int*)  d_in[2];
    const int*   ebat    = (const int*)  d_in[3];
    const int*   ei      = (const int*)  d_in[4];
    const int*   pidx    = (const int*)  d_in[5];
    const float* W1      = (const float*)d_in[6];
    const float* a_src1  = (const float*)d_in[7];
    const float* a_dst1  = (const float*)d_in[8];
    const float* b1      = (const float*)d_in[9];
    const float* W2      = (const float*)d_in[10];
    const float* a_src2  = (const float*)d_in[11];
    const float* a_dst2  = (const float*)d_in[12];
    const float* b2      = (const float*)d_in[13];
    const float* relW1   = (const float*)d_in[14];
    const float* relb1   = (const float*)d_in[15];
    const float* ln_g    = (const float*)d_in[16];
    const float* ln_b    = (const float*)d_in[17];
    const float* relW2   = (const float*)d_in[18];
    const float* relb2   = (const float*)d_in[19];
    const float* nerW1   = (const float*)d_in[20];
    const float* nerb1   = (const float*)d_in[21];
    const float* nerW2   = (const float*)d_in[22];
    const float* nerb2   = (const float*)d_in[23];
    float* out = (float*)d_out;

    float *h1p, *h2pp, *es1p, *ed1p, *es2p, *ed2p, *tbp;
    int *psortedp, *psortjp;
    cudaGetSymbolAddress((void**)&h1p,  g_h1);
    cudaGetSymbolAddress((void**)&h2pp, g_h2p);
    cudaGetSymbolAddress((void**)&es1p, g_es1);
    cudaGetSymbolAddress((void**)&ed1p, g_ed1);
    cudaGetSymbolAddress((void**)&es2p, g_es2);
    cudaGetSymbolAddress((void**)&ed2p, g_ed2);
    cudaGetSymbolAddress((void**)&tbp,  g_tb);
    cudaGetSymbolAddress((void**)&psortedp, g_psorted);
    cudaGetSymbolAddress((void**)&psortjp,  g_psortj);
    __nv_bfloat16 *sqh,*sql,*x0h,*x0l,*o1h,*o1l,*x2h,*x2l,*w1h,*w1l,*wnh,*wnl,*w2h,*w2l,*wrh,*wrl;
    cudaGetSymbolAddress((void**)&sqh, g_sqh); cudaGetSymbolAddress((void**)&sql, g_sql);
    cudaGetSymbolAddress((void**)&x0h, g_x0h); cudaGetSymbolAddress((void**)&x0l, g_x0l);
    cudaGetSymbolAddress((void**)&o1h, g_o1h); cudaGetSymbolAddress((void**)&o1l, g_o1l);
    cudaGetSymbolAddress((void**)&x2h, g_x2h); cudaGetSymbolAddress((void**)&x2l, g_x2l);
    cudaGetSymbolAddress((void**)&w1h, g_w1h); cudaGetSymbolAddress((void**)&w1l, g_w1l);
    cudaGetSymbolAddress((void**)&wnh, g_wnh); cudaGetSymbolAddress((void**)&wnl, g_wnl);
    cudaGetSymbolAddress((void**)&w2h, g_w2h); cudaGetSymbolAddress((void**)&w2l, g_w2l);
    cudaGetSymbolAddress((void**)&wrh, g_wrh); cudaGetSymbolAddress((void**)&wrl, g_wrl);

    static cudaStream_t sNER = nullptr, sIDX = nullptr, sWSP = nullptr;
    static cudaEvent_t evRoot, evNER, evIDX, evZERO, evW1, evW2, evREL;
    if(sNER == nullptr){
        cudaStreamCreateWithFlags(&sNER, cudaStreamNonBlocking);
        cudaStreamCreateWithFlags(&sIDX, cudaStreamNonBlocking);
        cudaStreamCreateWithFlags(&sWSP, cudaStreamNonBlocking);
        cudaEventCreateWithFlags(&evRoot, cudaEventDisableTiming);
        cudaEventCreateWithFlags(&evNER,  cudaEventDisableTiming);
        cudaEventCreateWithFlags(&evIDX,  cudaEventDisableTiming);
        cudaEventCreateWithFlags(&evZERO, cudaEventDisableTiming);
        cudaEventCreateWithFlags(&evW1,   cudaEventDisableTiming);
        cudaEventCreateWithFlags(&evW2,   cudaEventDisableTiming);
        cudaEventCreateWithFlags(&evREL,  cudaEventDisableTiming);
        cudaFuncSetAttribute(k_hmma<0>, cudaFuncAttributeMaxDynamicSharedMemorySize, HMMA_SMEM);
        cudaFuncSetAttribute(k_hmma<1>, cudaFuncAttributeMaxDynamicSharedMemorySize, HMMA_SMEM);
        cudaFuncSetAttribute(k_hmma<2>, cudaFuncAttributeMaxDynamicSharedMemorySize, HMMA_SMEM);
    }

    #define SPLIT(st, src, dh, dl, cnt) \
        k_split<<<((cnt)/4 + 255)/256, 256, 0, st>>>((const float4*)(src), (uint2*)(dh), (uint2*)(dl), (cnt)/4)

    // fork
    cudaEventRecord(evRoot, 0);
    cudaStreamWaitEvent(sNER, evRoot, 0);
    cudaStreamWaitEvent(sIDX, evRoot, 0);
    cudaStreamWaitEvent(sWSP, evRoot, 0);

    // --- NER chain ---
    k_out_init<<<(NER_OUT_ELEMS+255)/256, 256, 0, sNER>>>(nerb2, out);
    SPLIT(sNER, nerW1, wnh, wnl, Hdim*NERH);
    SPLIT(sNER, seq,   sqh, sql, NERROWS*Hdim);
    k_hmma<2><<<dim3(NERH/128, NERROWS/128, 1), 256, HMMA_SMEM, sNER>>>(
        sqh, sql, Hdim, Hdim, 0, wnh, wnl, NERH, 0, nerb1, 1, nullptr, 0, 0, 0,
        nerW2, nullptr, out, nullptr, 128, 1, NERH);
    cudaEventRecord(evNER, sNER);

    // --- index build chain ---
    k_init0<<<(Ndim+255)/256, 256, 0, sIDX>>>();
    cudaEventRecord(evZERO, sIDX);
    k_count<<<(ETOT+Pdim+255)/256, 256, 0, sIDX>>>(ei, pidx);
    k_scan<<<2, 1024, 0, sIDX>>>();
    k_scatter<<<(ETOT+Pdim+255)/256, 256, 0, sIDX>>>(ei, pidx);
    cudaEventRecord(evIDX, sIDX);

    // --- weight splits ---
    SPLIT(sWSP, W1, w1h, w1l, Hdim*F1);
    cudaEventRecord(evW1, sWSP);
    k_split_padW2<<<F1*128/256, 256, 0, sWSP>>>(W2, w2h, w2l);
    cudaEventRecord(evW2, sWSP);
    SPLIT(sWSP, relW1, wrh, wrl, 12*C2*RHID);
    cudaEventRecord(evREL, sWSP);

    // --- main GAT chain ---
    k_span_pool<<<Ndim, 192>>>(seq, est, elen, ebat, x0h, x0l);
    cudaStreamWaitEvent(0, evW1, 0);
    cudaStreamWaitEvent(0, evZERO, 0);
    k_hmma<1><<<dim3(F1/128, Ndim/128, 1), 256, HMMA_SMEM>>>(
        x0h, x0l, Hdim, Hdim, 0, w1h, w1l, F1, 0, nullptr, 0, h1p, F1, 0, 0,
        a_src1, a_dst1, es1p, ed1p, C1, H1, F1);
    cudaStreamWaitEvent(0, evIDX, 0);
    k_gat_agg<H1, C1, F1, true, true><<<Ndim, 128>>>(h1p, es1p, ed1p, b1, nullptr, o1h, o1l);
    cudaStreamWaitEvent(0, evW2, 0);
    k_hmma<1><<<dim3(1, Ndim/128, 2), 256, HMMA_SMEM>>>(
        o1h, o1l, F1, 256, 256, w2h, w2l, 128, (long)256*128, nullptr, 0,
        h2pp, 128, 0, 1,
        a_src2, a_dst2, es2p, ed2p, C2, 1, C2);
    k_gat_agg<1, C2, 128, false, true><<<Ndim, 32>>>(h2pp, es2p, ed2p, b2, nullptr, x2h, x2l);
    cudaStreamWaitEvent(0, evREL, 0);
    k_hmma<0><<<dim3(RHID/128, Ndim/128, 12), 256, HMMA_SMEM>>>(
        x2h, x2l, C2, C2, 0, wrh, wrl, RHID, (long)C2*RHID, nullptr, 0,
        tbp, RHID, (long)Ndim*RHID, 0,
        nullptr, nullptr, nullptr, nullptr, 128, 1, RHID);
    k_rel_g<<<dim3(Ndim/8, NREL), 256>>>(psortedp, psortjp,
        relb1, ln_g, ln_b, relW2, relb2, out + NER_OUT_ELEMS);

    // join
    cudaStreamWaitEvent(0, evNER, 0);
    #undef SPLIT
}

// round 17
// speedup vs baseline: 1.9408x; 1.0090x over previous
#include <cuda_runtime.h>
#include <cuda_bf16.h>
#include <math.h>
#include <stdint.h>

// ---------------- problem constants ----------------
#define Bdim 32
#define Sdim 512
#define Hdim 768
#define Ndim 4096
#define Edim 131072
#define Pdim 65536
#define ETOT (Edim + Ndim)
#define H1 4
#define C1 128
#define F1 (H1*C1)               // 512
#define C2 64
#define NREL 6
#define RHID 256
#define NERH 256
#define NERL 9
#define SLOPE 0.2f
#define LNEPS 1e-5f
#define NER_OUT_ELEMS (Bdim*Sdim*NERL)
#define NERROWS (Bdim*Sdim)      // 16384

// ---------------- device scratch ----------------
__device__ float g_h1[Ndim*F1];
__device__ float g_h2p[Ndim*128];
__device__ float g_es1[Ndim*H1], g_ed1[Ndim*H1];
__device__ float g_es2[Ndim],    g_ed2[Ndim];
__device__ int   g_deg[Ndim], g_cursor[Ndim], g_rowstart[Ndim+1];
__device__ int   g_csr[ETOT];
__device__ int   g_pdeg[Ndim], g_pcur[Ndim], g_prow[Ndim+1];
__device__ int   g_psorted[Pdim];
__device__ int   g_psortj[Pdim];
__device__ float g_tb[12*Ndim*RHID];
__device__ __nv_bfloat16 g_sqh[NERROWS*Hdim], g_sql[NERROWS*Hdim];
__device__ __nv_bfloat16 g_x0h[Ndim*Hdim],    g_x0l[Ndim*Hdim];
__device__ __nv_bfloat16 g_o1h[Ndim*F1],      g_o1l[Ndim*F1];
__device__ __nv_bfloat16 g_x2h[Ndim*C2],      g_x2l[Ndim*C2];
__device__ __nv_bfloat16 g_w1h[Hdim*F1],      g_w1l[Hdim*F1];
__device__ __nv_bfloat16 g_wnh[Hdim*NERH],    g_wnl[Hdim*NERH];
__device__ __nv_bfloat16 g_w2h[F1*128],       g_w2l[F1*128];
__device__ __nv_bfloat16 g_wrh[12*C2*RHID],   g_wrl[12*C2*RHID];

// ---------------- helpers ----------------
__device__ __forceinline__ float warpSum(float v){
    #pragma unroll
    for(int o=16;o;o>>=1) v += __shfl_xor_sync(0xffffffffu, v, o);
    return v;
}
__device__ __forceinline__ float quadSum(float v){
    v += __shfl_xor_sync(0xffffffffu, v, 1);
    v += __shfl_xor_sync(0xffffffffu, v, 2);
    return v;
}
__device__ __forceinline__ uint32_t smem_u32(const void* p){
    uint32_t a;
    asm("{ .reg .u64 t; cvta.to.shared.u64 t, %1; cvt.u32.u64 %0, t; }" : "=r"(a) : "l"(p));
    return a;
}
__device__ __forceinline__ unsigned pack_bf2(__nv_bfloat16 a, __nv_bfloat16 b){
    __nv_bfloat162 t; t.x = a; t.y = b;
    return *reinterpret_cast<unsigned*>(&t);
}
__device__ __forceinline__ void cp16(uint32_t dst, const void* src){
    asm volatile("cp.async.ca.shared.global [%0], [%1], 16;" :: "r"(dst), "l"(src) : "memory");
}
__device__ __forceinline__ void ldsm4(uint32_t* r, uint32_t addr){
    asm volatile("ldmatrix.sync.aligned.m8n8.x4.shared.b16 {%0,%1,%2,%3}, [%4];"
        : "=r"(r[0]), "=r"(r[1]), "=r"(r[2]), "=r"(r[3]) : "r"(addr));
}
__device__ __forceinline__ void ldsm4t(uint32_t* r, uint32_t addr){
    asm volatile("ldmatrix.sync.aligned.m8n8.x4.trans.shared.b16 {%0,%1,%2,%3}, [%4];"
        : "=r"(r[0]), "=r"(r[1]), "=r"(r[2]), "=r"(r[3]) : "r"(addr));
}
__device__ __forceinline__ void mma16816(float* d, const uint32_t* a, uint32_t b0, uint32_t b1){
    asm volatile(
        "mma.sync.aligned.m16n8k16.row.col.f32.bf16.bf16.f32 "
        "{%0,%1,%2,%3}, {%4,%5,%6,%7}, {%8,%9}, {%0,%1,%2,%3};"
        : "+f"(d[0]), "+f"(d[1]), "+f"(d[2]), "+f"(d[3])
        : "r"(a[0]), "r"(a[1]), "r"(a[2]), "r"(a[3]), "r"(b0), "r"(b1));
}

// ---------------- split fp32 -> bf16 hi/lo planes ----------------
__global__ void k_split(const float4* __restrict__ in, uint2* __restrict__ hi,
                        uint2* __restrict__ lo, int n4){
    int i = blockIdx.x*blockDim.x + threadIdx.x;
    if(i >= n4) return;
    float4 v = in[i];
    __nv_bfloat16 h0=__float2bfloat16(v.x), h1=__float2bfloat16(v.y);
    __nv_bfloat16 h2=__float2bfloat16(v.z), h3=__float2bfloat16(v.w);
    __nv_bfloat16 l0=__float2bfloat16(v.x-__bfloat162float(h0));
    __nv_bfloat16 l1=__float2bfloat16(v.y-__bfloat162float(h1));
    __nv_bfloat16 l2=__float2bfloat16(v.z-__bfloat162float(h2));
    __nv_bfloat16 l3=__float2bfloat16(v.w-__bfloat162float(h3));
    hi[i] = make_uint2(pack_bf2(h0,h1), pack_bf2(h2,h3));
    lo[i] = make_uint2(pack_bf2(l0,l1), pack_bf2(l2,l3));
}

__global__ void k_split_padW2(const float* __restrict__ W2,
                              __nv_bfloat16* __restrict__ hi, __nv_bfloat16* __restrict__ lo){
    int idx = blockIdx.x*256 + threadIdx.x;
    int k = idx >> 7, c = idx & 127;
    float v = (c < C2) ? W2[k*C2 + c] : 0.f;
    __nv_bfloat16 h = __float2bfloat16(v);
    __nv_bfloat16 l = __float2bfloat16(v - __bfloat162float(h));
    hi[idx] = h; lo[idx] = l;
}

// ---------------- split-bf16 HMMA GEMM with fused epilogues ----------------
// 256 threads, 8 warps, warp tile 64x32, CTA tile 128x128
// EPI: 0 = store only; 1 = store/atomic + attention coef atomics; 2 = NER stage2
#define SA 40
#define SB 136
#define A_PL (128*SA*2)
#define B_PL (32*SB*2)
#define BOFF (2*A_PL)
#define STAGE_SZ (BOFF + 2*B_PL)
#define PIPE_SZ (2*STAGE_SZ)
#define HMMA_SMEM (PIPE_SZ + 4608)
template<int EPI>
__global__ void __launch_bounds__(256) k_hmma(
        const __nv_bfloat16* __restrict__ aHi, const __nv_bfloat16* __restrict__ aLo,
        int lda, int K, long aStrideZ,
        const __nv_bfloat16* __restrict__ wHi, const __nv_bfloat16* __restrict__ wLo, int N,
        long wStrideZ, const float* __restrict__ bias, int reluFlag,
        float* __restrict__ C, int ldc, long cStrideZ, int atomicC,
        const float* __restrict__ p1, const float* __restrict__ p2,
        float* __restrict__ q1, float* __restrict__ q2,
        int headC, int nheads, int validN){
    extern __shared__ char sm_buf[];
    int tid = threadIdx.x, lane = tid & 31, warp = tid >> 5;
    int wm = warp & 1, wn = warp >> 1;
    int grp = lane >> 3, rr = lane & 7;
    int arow = rr + (grp & 1)*8;
    int acol = (grp >> 1)*8;

    int n0 = blockIdx.x*128, m0 = blockIdx.y*128, z = blockIdx.z;
    const __nv_bfloat16* azh = aHi + (size_t)z*aStrideZ;
    const __nv_bfloat16* azl = aLo + (size_t)z*aStrideZ;
    const __nv_bfloat16* wzh = wHi + (size_t)z*wStrideZ;
    const __nv_bfloat16* wzl = wLo + (size_t)z*wStrideZ;
    int nc = K >> 5;

    float* sx = (float*)(sm_buf + PIPE_SZ);
    if(EPI == 1){
        if(tid < 128){
            int n = n0 + tid;
            sx[tid]     = (n < validN) ? p1[n] : 0.f;
            sx[128+tid] = (n < validN) ? p2[n] : 0.f;
        }
    }else if(EPI == 2){
        for(int j=tid; j<128*NERL; j+=256)
            sx[j] = p1[(size_t)(n0 + j/NERL)*NERL + (j%NERL)];
    }

    float acc[4][4][4];
    #pragma unroll
    for(int a=0;a<4;a++)
        #pragma unroll
        for(int b=0;b<4;b++)
            #pragma unroll
            for(int c=0;c<4;c++) acc[a][b][c] = 0.f;

    uint32_t sb0 = smem_u32(sm_buf);

    #define ISSUE(kc, st) do{                                                        \
        uint32_t sb = sb0 + (st)*STAGE_SZ;                                           \
        _Pragma("unroll")                                                            \
        for(int i=0;i<2;i++){                                                        \
            int idx = tid + i*256; int row = idx >> 2, k8 = idx & 3;                 \
            size_t go = (size_t)(m0+row)*lda + (kc)*32 + k8*8;                       \
            uint32_t d = sb + row*80 + k8*16;                                        \
            cp16(d,        azh + go);                                                \
            cp16(d + A_PL, azl + go);                                                \
        }                                                                            \
        _Pragma("unroll")                                                            \
        for(int i=0;i<2;i++){                                                        \
            int idx = tid + i*256; int kr = idx >> 4, ncol = idx & 15;               \
            size_t go = (size_t)((kc)*32 + kr)*N + n0 + ncol*8;                      \
            uint32_t d = sb + BOFF + kr*272 + ncol*16;                               \
            cp16(d,        wzh + go);                                                \
            cp16(d + B_PL, wzl + go);                                                \
        }                                                                            \
        asm volatile("cp.async.commit_group;" ::: "memory");                         \
    }while(0)

    ISSUE(0, 0);
    for(int kc=0; kc<nc; kc++){
        if(kc+1 < nc){
            ISSUE(kc+1, (kc+1)&1);
            asm volatile("cp.async.wait_group 1;" ::: "memory");
        }else{
            asm volatile("cp.async.wait_group 0;" ::: "memory");
        }
        __syncthreads();
        uint32_t sb = sb0 + (kc&1)*STAGE_SZ;
        uint32_t aBase = sb + ((wm*64 + arow)*SA + acol)*2;
        uint32_t bBase = sb + BOFF + (arow*SB + wn*32 + acol)*2;
        #pragma unroll
        for(int kk=0; kk<2; kk++){
            uint32_t bfr[2][2][4];
            #pragma unroll
            for(int pr=0; pr<2; pr++){
                uint32_t bd = bBase + kk*(16*SB*2) + pr*32;
                ldsm4t(bfr[pr][0], bd);
                ldsm4t(bfr[pr][1], bd + B_PL);
            }
            #pragma unroll
            for(int mt=0; mt<4; mt++){
                uint32_t af[2][4];
                uint32_t ad = aBase + mt*(16*SA*2) + kk*32;
                ldsm4(af[0], ad);
                ldsm4(af[1], ad + A_PL);
                #pragma unroll
                for(int nt=0; nt<4; nt++){
                    int pr = nt >> 1, hf = (nt & 1)*2;
                    uint32_t bh0 = bfr[pr][0][hf], bh1 = bfr[pr][0][hf+1];
                    uint32_t bl0 = bfr[pr][1][hf], bl1 = bfr[pr][1][hf+1];
                    mma16816(acc[mt][nt], af[0], bh0, bh1);
                    mma16816(acc[mt][nt], af[0], bl0, bl1);
                    mma16816(acc[mt][nt], af[1], bh0, bh1);
                }
            }
        }
        __syncthreads();
    }
    #undef ISSUE

    // ---- epilogue ----
    float* Cz = C + (size_t)z*cStrideZ;
    int hh = (n0 + wn*32) / headC;
    bool hhok = hh < nheads;
    float bcol[8];
    #pragma unroll
    for(int nt=0; nt<4; nt++){
        int n = n0 + wn*32 + nt*8 + (lane & 3)*2;
        bcol[nt*2]   = bias ? bias[n]   : 0.f;
        bcol[nt*2+1] = bias ? bias[n+1] : 0.f;
    }
    #pragma unroll
    for(int mt=0; mt<4; mt++){
        int mb = m0 + wm*64 + mt*16 + (lane >> 2);
        #pragma unroll
        for(int half=0; half<2; half++){
            int m = mb + half*8;
            float v[8];
            #pragma unroll
            for(int nt=0; nt<4; nt++){
                float a0 = acc[mt][nt][half*2]   + bcol[nt*2];
                float a1 = acc[mt][nt][half*2+1] + bcol[nt*2+1];
                if(reluFlag){ a0 = fmaxf(a0,0.f); a1 = fmaxf(a1,0.f); }
                v[nt*2] = a0; v[nt*2+1] = a1;
                if(EPI != 2){
                    int n = n0 + wn*32 + nt*8 + (lane & 3)*2;
                    if(atomicC){
                        atomicAdd(&Cz[(size_t)m*ldc + n],   a0);
                        atomicAdd(&Cz[(size_t)m*ldc + n+1], a1);
                    }else{
                        *reinterpret_cast<float2*>(Cz + (size_t)m*ldc + n) = make_float2(a0, a1);
                    }
                }
            }
            if(EPI == 1){
                float ps = 0.f, pd = 0.f;
                #pragma unroll
                for(int t=0;t<8;t++){
                    int ln = wn*32 + (t>>1)*8 + (lane&3)*2 + (t&1);
                    ps += v[t]*sx[ln];
                    pd += v[t]*sx[128+ln];
                }
                ps = quadSum(ps); pd = quadSum(pd);
                if((lane&3)==0 && hhok){
                    atomicAdd(&q1[m*nheads + hh], ps);
                    atomicAdd(&q2[m*nheads + hh], pd);
                }
            }else if(EPI == 2){
                float pc[NERL];
                #pragma unroll
                for(int c=0;c<NERL;c++) pc[c] = 0.f;
                #pragma unroll
                for(int t=0;t<8;t++){
                    int ln = wn*32 + (t>>1)*8 + (lane&3)*2 + (t&1);
                    #pragma unroll
                    for(int c=0;c<NERL;c++) pc[c] += v[t]*sx[ln*NERL + c];
                }
                #pragma unroll
                for(int c=0;c<NERL;c++){
                    float s = quadSum(pc[c]);
                    if((lane&3)==0) atomicAdd(&q1[(size_t)m*NERL + c], s);
                }
            }
        }
    }
}

// ---------------- entity span mean pooling -> bf16 hi/lo planes ----------------
__global__ void k_span_pool(const float* __restrict__ seq,
                            const int* __restrict__ est, const int* __restrict__ elen,
                            const int* __restrict__ ebat,
                            __nv_bfloat16* __restrict__ xh, __nv_bfloat16* __restrict__ xl){
    int n = blockIdx.x;
    int b = ebat[n], st = est[n], len = elen[n];
    const float* base = seq + ((size_t)b*Sdim + st)*Hdim + threadIdx.x*4;
    float4 acc = make_float4(0.f,0.f,0.f,0.f);
    for(int r=0; r<=len; r++){
        float4 t = *reinterpret_cast<const float4*>(base + (size_t)r*Hdim);
        acc.x += t.x; acc.y += t.y; acc.z += t.z; acc.w += t.w;
    }
    float inv = 1.0f/(float)(len+1);
    acc.x*=inv; acc.y*=inv; acc.z*=inv; acc.w*=inv;
    __nv_bfloat16 h0=__float2bfloat16(acc.x), h1=__float2bfloat16(acc.y);
    __nv_bfloat16 h2=__float2bfloat16(acc.z), h3=__float2bfloat16(acc.w);
    __nv_bfloat16 l0=__float2bfloat16(acc.x-__bfloat162float(h0));
    __nv_bfloat16 l1=__float2bfloat16(acc.y-__bfloat162float(h1));
    __nv_bfloat16 l2=__float2bfloat16(acc.z-__bfloat162float(h2));
    __nv_bfloat16 l3=__float2bfloat16(acc.w-__bfloat162float(h3));
    size_t o = (size_t)n*Hdim + threadIdx.x*4;
    *reinterpret_cast<uint2*>(&xh[o]) = make_uint2(pack_bf2(h0,h1), pack_bf2(h2,h3));
    *reinterpret_cast<uint2*>(&xl[o]) = make_uint2(pack_bf2(l0,l1), pack_bf2(l2,l3));
}

// ---------------- init kernels ----------------
__global__ void k_init0(){
    int i = blockIdx.x*blockDim.x + threadIdx.x;
    if(i >= Ndim) return;
    g_deg[i]=0; g_cursor[i]=0; g_pdeg[i]=0; g_pcur[i]=0;
    g_es2[i]=0.f; g_ed2[i]=0.f;
    #pragma unroll
    for(int h=0;h<H1;h++){ g_es1[i*H1+h]=0.f; g_ed1[i*H1+h]=0.f; }
    float4 z4 = make_float4(0.f,0.f,0.f,0.f);
    float4* h2 = reinterpret_cast<float4*>(&g_h2p[(size_t)i*128]);
    #pragma unroll
    for(int j=0;j<32;j++) h2[j] = z4;
}
__global__ void k_out_init(const float* __restrict__ b2, float* __restrict__ out){
    int i = blockIdx.x*blockDim.x + threadIdx.x;
    if(i < NER_OUT_ELEMS) out[i] = b2[i % NERL];
}

// ---------------- merged CSR + pair-sort build ----------------
__global__ void k_count(const int* __restrict__ ei, const int* __restrict__ pidx){
    int idx = blockIdx.x*blockDim.x + threadIdx.x;
    if(idx < ETOT){
        int dst = (idx < Edim) ? ei[Edim + idx] : (idx - Edim);
        atomicAdd(&g_deg[dst], 1);
    }else if(idx < ETOT + Pdim){
        atomicAdd(&g_pdeg[pidx[(idx - ETOT)*2]], 1);
    }
}
__global__ void k_scan(){
    __shared__ int s[1024];
    const int* deg = (blockIdx.x == 0) ? g_deg : g_pdeg;
    int* rowstart  = (blockIdx.x == 0) ? g_rowstart : g_prow;
    int t = threadIdx.x;
    int v0 = deg[t*4+0], v1 = deg[t*4+1], v2 = deg[t*4+2], v3 = deg[t*4+3];
    int c0 = v0, c1 = c0+v1, c2 = c1+v2, c3 = c2+v3;
    s[t] = c3;
    __syncthreads();
    for(int off=1; off<1024; off<<=1){
        int x = (t >= off) ? s[t-off] : 0;
        __syncthreads();
        s[t] += x;
        __syncthreads();
    }
    int excl = s[t] - c3;
    rowstart[t*4+1] = excl + c0;
    rowstart[t*4+2] = excl + c1;
    rowstart[t*4+3] = excl + c2;
    rowstart[t*4+4] = excl + c3;
    if(t==0) rowstart[0] = 0;
}
__global__ void k_scatter(const int* __restrict__ ei, const int* __restrict__ pidx){
    int idx = blockIdx.x*blockDim.x + threadIdx.x;
    if(idx < ETOT){
        int src, dst;
        if(idx < Edim){ src = ei[idx]; dst = ei[Edim + idx]; }
        else          { src = idx - Edim; dst = src; }
        int pos = g_rowstart[dst] + atomicAdd(&g_cursor[dst], 1);
        g_csr[pos] = src;
    }else if(idx < ETOT + Pdim){
        int p = idx - ETOT;
        int i = pidx[p*2];
        int pos = g_prow[i] + atomicAdd(&g_pcur[i], 1);
        g_psorted[pos] = p;
        g_psortj[pos]  = pidx[p*2+1];
    }
}

// ---------------- GAT softmax + aggregation (pass 2 unrolled 4/2/1-way) ----------------
template<int HEADS,int C,int LD,bool RELU,bool SPLIT>
__global__ void k_gat_agg(const float* __restrict__ h,
                          const float* __restrict__ es, const float* __restrict__ ed,
                          const float* __restrict__ bias, float* __restrict__ out,
                          __nv_bfloat16* __restrict__ outH, __nv_bfloat16* __restrict__ outL){
    const int F = HEADS*C;
    int d = blockIdx.x;
    int hh = threadIdx.x >> 5, lane = threadIdx.x & 31;
    int rs = g_rowstart[d], re = g_rowstart[d+1];
    float edv = ed[d*HEADS + hh];

    float den = 0.f;
    for(int e=rs+lane; e<re; e+=32){
        int s = g_csr[e];
        float t = es[s*HEADS+hh] + edv;
        t = (t > 0.f) ? t : SLOPE*t;
        den += __expf(t);
    }
    den = warpSum(den);
    float inv = 1.0f/den;

    float acc[C/32];
    #pragma unroll
    for(int i=0;i<C/32;i++) acc[i]=0.f;

    int e = rs;
    for(; e+3 < re; e += 4){
        int s0 = g_csr[e],   s1 = g_csr[e+1];
        int s2 = g_csr[e+2], s3 = g_csr[e+3];
        float t0 = es[s0*HEADS+hh] + edv;
        float t1 = es[s1*HEADS+hh] + edv;
        float t2 = es[s2*HEADS+hh] + edv;
        float t3 = es[s3*HEADS+hh] + edv;
        t0 = (t0 > 0.f) ? t0 : SLOPE*t0;
        t1 = (t1 > 0.f) ? t1 : SLOPE*t1;
        t2 = (t2 > 0.f) ? t2 : SLOPE*t2;
        t3 = (t3 > 0.f) ? t3 : SLOPE*t3;
        float w0 = __expf(t0)*inv;
        float w1 = __expf(t1)*inv;
        float w2 = __expf(t2)*inv;
        float w3 = __expf(t3)*inv;
        const float* hp0 = h + (size_t)s0*LD + hh*C + lane;
        const float* hp1 = h + (size_t)s1*LD + hh*C + lane;
        const float* hp2 = h + (size_t)s2*LD + hh*C + lane;
        const float* hp3 = h + (size_t)s3*LD + hh*C + lane;
        #pragma unroll
        for(int i=0;i<C/32;i++)
            acc[i] += w0*hp0[32*i] + w1*hp1[32*i] + w2*hp2[32*i] + w3*hp3[32*i];
    }
    for(; e+1 < re; e += 2){
        int s0 = g_csr[e], s1 = g_csr[e+1];
        float t0 = es[s0*HEADS+hh] + edv;
        float t1 = es[s1*HEADS+hh] + edv;
        t0 = (t0 > 0.f) ? t0 : SLOPE*t0;
        t1 = (t1 > 0.f) ? t1 : SLOPE*t1;
        float w0 = __expf(t0)*inv;
        float w1 = __expf(t1)*inv;
        const float* hp0 = h + (size_t)s0*LD + hh*C + lane;
        const float* hp1 = h + (size_t)s1*LD + hh*C + lane;
        #pragma unroll
        for(int i=0;i<C/32;i++) acc[i] += w0*hp0[32*i] + w1*hp1[32*i];
    }
    if(e < re){
        int s = g_csr[e];
        float t = es[s*HEADS+hh] + edv;
        t = (t > 0.f) ? t : SLOPE*t;
        float w = __expf(t)*inv;
        const float* hp = h + (size_t)s*LD + hh*C + lane;
        #pragma unroll
        for(int i=0;i<C/32;i++) acc[i] += w*hp[32*i];
    }
    #pragma unroll
    for(int i=0;i<C/32;i++){
        float v = acc[i] + bias[hh*C + lane + 32*i];
        if(RELU) v = fmaxf(v, 0.f);
        size_t o = (size_t)d*F + hh*C + lane + 32*i;
        if(SPLIT){
            __nv_bfloat16 hb = __float2bfloat16(v);
            outH[o] = hb;
            outL[o] = __float2bfloat16(v - __bfloat162float(hb));
        }else{
            out[o] = v;
        }
    }
}

// ---------------- fused relation head: warp-per-left-entity, 4/2/1-way unroll ----------------
__global__ void k_rel_g(const int* __restrict__ psorted, const int* __restrict__ psortj,
                        const float* __restrict__ relb1, const float* __restrict__ lng,
                        const float* __restrict__ lnb, const float* __restrict__ relW2,
                        const float* __restrict__ relb2, float* __restrict__ out){
    __shared__ float sb1[256], sg[256], sbb[256], sw2[256];
    int r = blockIdx.y;
    int tid = threadIdx.x;
    sb1[tid] = relb1[r*256+tid];
    sg[tid]  = lng[r*256+tid];
    sbb[tid] = lnb[r*256+tid];
    sw2[tid] = relW2[r*256+tid];
    __syncthreads();

    int w = tid >> 5, lane = tid & 31;
    int i = blockIdx.x*8 + w;
    int rs = g_prow[i], re = g_prow[i+1];
    if(rs == re) return;
    float rb2 = relb2[r];
    float* outr = out + (size_t)r*Pdim;

    float ti[8];
    const float* tip = g_tb + ((size_t)(r*2)*Ndim + i)*RHID;
    #pragma unroll
    for(int t=0;t<8;t++) ti[t] = tip[lane + 32*t];
    const float* tjbase = g_tb + (size_t)(r*2+1)*Ndim*RHID;

    int idx = rs;
    // 4-way unrolled main loop
    for(; idx+3 < re; idx += 4){
        int p0 = psorted[idx],   j0 = psortj[idx];
        int p1 = psorted[idx+1], j1 = psortj[idx+1];
        int p2 = psorted[idx+2], j2 = psortj[idx+2];
        int p3 = psorted[idx+3], j3 = psortj[idx+3];
        const float* tj0 = tjbase + (size_t)j0*RHID;
        const float* tj1 = tjbase + (size_t)j1*RHID;
        const float* tj2 = tjbase + (size_t)j2*RHID;
        const float* tj3 = tjbase + (size_t)j3*RHID;
        float v0[8], v1[8], v2[8], v3[8];
        float s1a=0.f,s2a=0.f,s1b=0.f,s2b=0.f,s1c=0.f,s2c=0.f,s1d=0.f,s2d=0.f;
        #pragma unroll
        for(int t=0;t<8;t++){
            int k = lane + 32*t;
            float base = ti[t] + sb1[k];
            float xa = base + tj0[k];
            float xb = base + tj1[k];
            float xc = base + tj2[k];
            float xd = base + tj3[k];
            v0[t]=xa; s1a+=xa; s2a+=xa*xa;
            v1[t]=xb; s1b+=xb; s2b+=xb*xb;
            v2[t]=xc; s1c+=xc; s2c+=xc*xc;
            v3[t]=xd; s1d+=xd; s2d+=xd*xd;
        }
        #pragma unroll
        for(int o=16;o;o>>=1){
            s1a += __shfl_xor_sync(0xffffffffu, s1a, o);
            s2a += __shfl_xor_sync(0xffffffffu, s2a, o);
            s1b += __shfl_xor_sync(0xffffffffu, s1b, o);
            s2b += __shfl_xor_sync(0xffffffffu, s2b, o);
            s1c += __shfl_xor_sync(0xffffffffu, s1c, o);
            s2c += __shfl_xor_sync(0xffffffffu, s2c, o);
            s1d += __shfl_xor_sync(0xffffffffu, s1d, o);
            s2d += __shfl_xor_sync(0xffffffffu, s2d, o);
        }
        float mua = s1a*(1.0f/256.0f), mub = s1b*(1.0f/256.0f);
        float muc = s1c*(1.0f/256.0f), mud = s1d*(1.0f/256.0f);
        float ria = rsqrtf(s2a*(1.0f/256.0f) - mua*mua + LNEPS);
        float rib = rsqrtf(s2b*(1.0f/256.0f) - mub*mub + LNEPS);
        float ric = rsqrtf(s2c*(1.0f/256.0f) - muc*muc + LNEPS);
        float rid = rsqrtf(s2d*(1.0f/256.0f) - mud*mud + LNEPS);
        float acca=0.f, accb=0.f, accc=0.f, accd=0.f;
        #pragma unroll
        for(int t=0;t<8;t++){
            int k = lane + 32*t;
            float gk = sg[k], bk = sbb[k], wk = sw2[k];
            acca += fmaxf((v0[t]-mua)*ria*gk + bk, 0.f) * wk;
            accb += fmaxf((v1[t]-mub)*rib*gk + bk, 0.f) * wk;
            accc += fmaxf((v2[t]-muc)*ric*gk + bk, 0.f) * wk;
            accd += fmaxf((v3[t]-mud)*rid*gk + bk, 0.f) * wk;
        }
        #pragma unroll
        for(int o=16;o;o>>=1){
            acca += __shfl_xor_sync(0xffffffffu, acca, o);
            accb += __shfl_xor_sync(0xffffffffu, accb, o);
            accc += __shfl_xor_sync(0xffffffffu, accc, o);
            accd += __shfl_xor_sync(0xffffffffu, accd, o);
        }
        if(lane==0){
            outr[p0] = acca + rb2;
            outr[p1] = accb + rb2;
            outr[p2] = accc + rb2;
            outr[p3] = accd + rb2;
        }
    }
    // 2-way
    for(; idx+1 < re; idx += 2){
        int p0 = psorted[idx],   j0 = psortj[idx];
        int p1 = psorted[idx+1], j1 = psortj[idx+1];
        const float* tj0 = tjbase + (size_t)j0*RHID;
        const float* tj1 = tjbase + (size_t)j1*RHID;
        float v0[8], v1[8];
        float s1a=0.f, s2a=0.f, s1b=0.f, s2b=0.f;
        #pragma unroll
        for(int t=0;t<8;t++){
            int k = lane + 32*t;
            float base = ti[t] + sb1[k];
            float xa = base + tj0[k];
            float xb = base + tj1[k];
            v0[t] = xa; s1a += xa; s2a += xa*xa;
            v1[t] = xb; s1b += xb; s2b += xb*xb;
        }
        #pragma unroll
        for(int o=16;o;o>>=1){
            s1a += __shfl_xor_sync(0xffffffffu, s1a, o);
            s2a += __shfl_xor_sync(0xffffffffu, s2a, o);
            s1b += __shfl_xor_sync(0xffffffffu, s1b, o);
            s2b += __shfl_xor_sync(0xffffffffu, s2b, o);
        }
        float mua  = s1a*(1.0f/256.0f), mub  = s1b*(1.0f/256.0f);
        float ria = rsqrtf(s2a*(1.0f/256.0f) - mua*mua + LNEPS);
        float rib = rsqrtf(s2b*(1.0f/256.0f) - mub*mub + LNEPS);
        float acca = 0.f, accb = 0.f;
        #pragma unroll
        for(int t=0;t<8;t++){
            int k = lane + 32*t;
            float gk = sg[k], bk = sbb[k], wk = sw2[k];
            acca += fmaxf((v0[t]-mua)*ria*gk + bk, 0.f) * wk;
            accb += fmaxf((v1[t]-mub)*rib*gk + bk, 0.f) * wk;
        }
        #pragma unroll
        for(int o=16;o;o>>=1){
            acca += __shfl_xor_sync(0xffffffffu, acca, o);
            accb += __shfl_xor_sync(0xffffffffu, accb, o);
        }
        if(lane==0){
            outr[p0] = acca + rb2;
            outr[p1] = accb + rb2;
        }
    }
    // tail
    if(idx < re){
        int p = psorted[idx];
        int j = psortj[idx];
        const float* tj = tjbase + (size_t)j*RHID;
        float v[8]; float s1 = 0.f, s2 = 0.f;
        #pragma unroll
        for(int t=0;t<8;t++){
            int k = lane + 32*t;
            float x = ti[t] + tj[k] + sb1[k];
            v[t] = x; s1 += x; s2 += x*x;
        }
        #pragma unroll
        for(int o=16;o;o>>=1){
            s1 += __shfl_xor_sync(0xffffffffu, s1, o);
            s2 += __shfl_xor_sync(0xffffffffu, s2, o);
        }
        float mu  = s1 * (1.0f/256.0f);
        float rinv = rsqrtf(s2*(1.0f/256.0f) - mu*mu + LNEPS);
        float acc = 0.f;
        #pragma unroll
        for(int t=0;t<8;t++){
            int k = lane + 32*t;
            float x = (v[t]-mu)*rinv*sg[k] + sbb[k];
            acc += fmaxf(x, 0.f) * sw2[k];
        }
        acc = warpSum(acc);
        if(lane==0) outr[p] = acc + rb2;
    }
}

// ---------------- launch ----------------
extern "C" void kernel_launch(void* const* d_in, const int* in_sizes, int n_in,
                              void* d_out, int out_size){
    const float* seq     = (const float*)d_in[0];
    const int*   est     = (const int*)  d_in[1];
    const int*   elen    = (const int*)  d_in[2];
    const int*   ebat    = (const int*)  d_in[3];
    const int*   ei      = (const int*)  d_in[4];
    const int*   pidx    = (const int*)  d_in[5];
    const float* W1      = (const float*)d_in[6];
    const float* a_src1  = (const float*)d_in[7];
    const float* a_dst1  = (const float*)d_in[8];
    const float* b1      = (const float*)d_in[9];
    const float* W2      = (const float*)d_in[10];
    const float* a_src2  = (const float*)d_in[11];
    const float* a_dst2  = (const float*)d_in[12];
    const float* b2      = (const float*)d_in[13];
    const float* relW1   = (const float*)d_in[14];
    const float* relb1   = (const float*)d_in[15];
    const float* ln_g    = (const float*)d_in[16];
    const float* ln_b    = (const float*)d_in[17];
    const float* relW2   = (const float*)d_in[18];
    const float* relb2   = (const float*)d_in[19];
    const float* nerW1   = (const float*)d_in[20];
    const float* nerb1   = (const float*)d_in[21];
    const float* nerW2   = (const float*)d_in[22];
    const float* nerb2   = (const float*)d_in[23];
    float* out = (float*)d_out;

    float *h1p, *h2pp, *es1p, *ed1p, *es2p, *ed2p, *tbp;
    int *psortedp, *psortjp;
    cudaGetSymbolAddress((void**)&h1p,  g_h1);
    cudaGetSymbolAddress((void**)&h2pp, g_h2p);
    cudaGetSymbolAddress((void**)&es1p, g_es1);
    cudaGetSymbolAddress((void**)&ed1p, g_ed1);
    cudaGetSymbolAddress((void**)&es2p, g_es2);
    cudaGetSymbolAddress((void**)&ed2p, g_ed2);
    cudaGetSymbolAddress((void**)&tbp,  g_tb);
    cudaGetSymbolAddress((void**)&psortedp, g_psorted);
    cudaGetSymbolAddress((void**)&psortjp,  g_psortj);
    __nv_bfloat16 *sqh,*sql,*x0h,*x0l,*o1h,*o1l,*x2h,*x2l,*w1h,*w1l,*wnh,*wnl,*w2h,*w2l,*wrh,*wrl;
    cudaGetSymbolAddress((void**)&sqh, g_sqh); cudaGetSymbolAddress((void**)&sql, g_sql);
    cudaGetSymbolAddress((void**)&x0h, g_x0h); cudaGetSymbolAddress((void**)&x0l, g_x0l);
    cudaGetSymbolAddress((void**)&o1h, g_o1h); cudaGetSymbolAddress((void**)&o1l, g_o1l);
    cudaGetSymbolAddress((void**)&x2h, g_x2h); cudaGetSymbolAddress((void**)&x2l, g_x2l);
    cudaGetSymbolAddress((void**)&w1h, g_w1h); cudaGetSymbolAddress((void**)&w1l, g_w1l);
    cudaGetSymbolAddress((void**)&wnh, g_wnh); cudaGetSymbolAddress((void**)&wnl, g_wnl);
    cudaGetSymbolAddress((void**)&w2h, g_w2h); cudaGetSymbolAddress((void**)&w2l, g_w2l);
    cudaGetSymbolAddress((void**)&wrh, g_wrh); cudaGetSymbolAddress((void**)&wrl, g_wrl);

    static cudaStream_t sNER = nullptr, sIDX = nullptr, sWSP = nullptr;
    static cudaEvent_t evRoot, evNER, evIDX, evZERO, evW1, evW2, evREL;
    if(sNER == nullptr){
        cudaStreamCreateWithFlags(&sNER, cudaStreamNonBlocking);
        cudaStreamCreateWithFlags(&sIDX, cudaStreamNonBlocking);
        cudaStreamCreateWithFlags(&sWSP, cudaStreamNonBlocking);
        cudaEventCreateWithFlags(&evRoot, cudaEventDisableTiming);
        cudaEventCreateWithFlags(&evNER,  cudaEventDisableTiming);
        cudaEventCreateWithFlags(&evIDX,  cudaEventDisableTiming);
        cudaEventCreateWithFlags(&evZERO, cudaEventDisableTiming);
        cudaEventCreateWithFlags(&evW1,   cudaEventDisableTiming);
        cudaEventCreateWithFlags(&evW2,   cudaEventDisableTiming);
        cudaEventCreateWithFlags(&evREL,  cudaEventDisableTiming);
        cudaFuncSetAttribute(k_hmma<0>, cudaFuncAttributeMaxDynamicSharedMemorySize, HMMA_SMEM);
        cudaFuncSetAttribute(k_hmma<1>, cudaFuncAttributeMaxDynamicSharedMemorySize, HMMA_SMEM);
        cudaFuncSetAttribute(k_hmma<2>, cudaFuncAttributeMaxDynamicSharedMemorySize, HMMA_SMEM);
    }

    #define SPLIT(st, src, dh, dl, cnt) \
        k_split<<<((cnt)/4 + 255)/256, 256, 0, st>>>((const float4*)(src), (uint2*)(dh), (uint2*)(dl), (cnt)/4)

    // fork
    cudaEventRecord(evRoot, 0);
    cudaStreamWaitEvent(sNER, evRoot, 0);
    cudaStreamWaitEvent(sIDX, evRoot, 0);
    cudaStreamWaitEvent(sWSP, evRoot, 0);

    // --- NER chain ---
    k_out_init<<<(NER_OUT_ELEMS+255)/256, 256, 0, sNER>>>(nerb2, out);
    SPLIT(sNER, nerW1, wnh, wnl, Hdim*NERH);
    SPLIT(sNER, seq,   sqh, sql, NERROWS*Hdim);
    k_hmma<2><<<dim3(NERH/128, NERROWS/128, 1), 256, HMMA_SMEM, sNER>>>(
        sqh, sql, Hdim, Hdim, 0, wnh, wnl, NERH, 0, nerb1, 1, nullptr, 0, 0, 0,
        nerW2, nullptr, out, nullptr, 128, 1, NERH);
    cudaEventRecord(evNER, sNER);

    // --- index build chain ---
    k_init0<<<(Ndim+255)/256, 256, 0, sIDX>>>();
    cudaEventRecord(evZERO, sIDX);
    k_count<<<(ETOT+Pdim+255)/256, 256, 0, sIDX>>>(ei, pidx);
    k_scan<<<2, 1024, 0, sIDX>>>();
    k_scatter<<<(ETOT+Pdim+255)/256, 256, 0, sIDX>>>(ei, pidx);
    cudaEventRecord(evIDX, sIDX);

    // --- weight splits ---
    SPLIT(sWSP, W1, w1h, w1l, Hdim*F1);
    cudaEventRecord(evW1, sWSP);
    k_split_padW2<<<F1*128/256, 256, 0, sWSP>>>(W2, w2h, w2l);
    cudaEventRecord(evW2, sWSP);
    SPLIT(sWSP, relW1, wrh, wrl, 12*C2*RHID);
    cudaEventRecord(evREL, sWSP);

    // --- main GAT chain ---
    k_span_pool<<<Ndim, 192>>>(seq, est, elen, ebat, x0h, x0l);
    cudaStreamWaitEvent(0, evW1, 0);
    cudaStreamWaitEvent(0, evZERO, 0);
    k_hmma<1><<<dim3(F1/128, Ndim/128, 1), 256, HMMA_SMEM>>>(
        x0h, x0l, Hdim, Hdim, 0, w1h, w1l, F1, 0, nullptr, 0, h1p, F1, 0, 0,
        a_src1, a_dst1, es1p, ed1p, C1, H1, F1);
    cudaStreamWaitEvent(0, evIDX, 0);
    k_gat_agg<H1, C1, F1, true, true><<<Ndim, 128>>>(h1p, es1p, ed1p, b1, nullptr, o1h, o1l);
    cudaStreamWaitEvent(0, evW2, 0);
    k_hmma<1><<<dim3(1, Ndim/128, 2), 256, HMMA_SMEM>>>(
        o1h, o1l, F1, 256, 256, w2h, w2l, 128, (long)256*128, nullptr, 0,
        h2pp, 128, 0, 1,
        a_src2, a_dst2, es2p, ed2p, C2, 1, C2);
    k_gat_agg<1, C2, 128, false, true><<<Ndim, 32>>>(h2pp, es2p, ed2p, b2, nullptr, x2h, x2l);
    cudaStreamWaitEvent(0, evREL, 0);
    k_hmma<0><<<dim3(RHID/128, Ndim/128, 12), 256, HMMA_SMEM>>>(
        x2h, x2l, C2, C2, 0, wrh, wrl, RHID, (long)C2*RHID, nullptr, 0,
        tbp, RHID, (long)Ndim*RHID, 0,
        nullptr, nullptr, nullptr, nullptr, 128, 1, RHID);
    k_rel_g<<<dim3(Ndim/8, NREL), 256>>>(psortedp, psortjp,
        relb1, ln_g, ln_b, relW2, relb2, out + NER_OUT_ELEMS);

    // join
    cudaStreamWaitEvent(0, evNER, 0);
    #undef SPLIT
}